// round 1
// baseline (speedup 1.0000x reference)
#include <cuda_runtime.h>
#include <math.h>

// ---------------------------------------------------------------------------
// TCNAttentionBlock: ALiBi + persistent-memory + talking-heads MHA -> residual
// -> causal TCN (2x conv k=3) -> LayerNorm.
// N=8, T=1024, E=512, H=8, D=64, P=16. All fp32.
// ---------------------------------------------------------------------------

#define NB   8
#define TT   1024
#define EE   512
#define HH   8
#define DD   64
#define PP   16
#define LP   1040            // TT + PP
#define NT   8192            // NB*TT
#define SOFTMAX_SCALE 0.044194173824159216f   // 1/sqrt(512)

// ------------------------------ scratch -----------------------------------
__device__ float g_q  [NB * TT * HH * DD];        // (n,t,h,d) = (8192,512)
__device__ float g_k  [NB * LP * HH * DD];        // (n,l,h,d)
__device__ float g_v  [NB * LP * HH * DD];
__device__ float g_att[(size_t)NB * HH * TT * LP]; // (n,h,q,k)  272MB
__device__ float g_ctx[NB * TT * EE];             // (n,q,h,d) flat (8192,512)
__device__ float g_h  [NB * TT * EE];             // x + attention
__device__ float g_t1 [NB * TT * EE];             // conv1 out
__device__ float g_t2 [NB * TT * EE];             // conv2 out (+res)

// ------------------------------ QKV projection -----------------------------
// rows = (n,t,h) : 65536 rows of dim 64.  q/k/v[row,i] = sum_j x[row,j]*W[i,j]
__global__ void qkv_kernel(const float* __restrict__ x,
                           const float* __restrict__ Wq,
                           const float* __restrict__ Wk,
                           const float* __restrict__ Wv) {
    __shared__ float xs[32][65];
    __shared__ float Wt[64][65];
    const int rbase = blockIdx.x * 32;
    const int tid = threadIdx.x;

    #pragma unroll
    for (int l = 0; l < 8; l++) {
        int idx = tid + l * 256;            // 32*64 = 2048
        int r = idx >> 6, c = idx & 63;
        xs[r][c] = x[(size_t)(rbase + r) * 64 + c];
    }

    const int i  = tid & 63;                // output col
    const int rg = tid >> 6;                // row group 0..3

    for (int m = 0; m < 3; m++) {
        const float* Wm = (m == 0) ? Wq : (m == 1) ? Wk : Wv;
        #pragma unroll
        for (int l = 0; l < 16; l++) {
            int idx = tid + l * 256;        // 64*64 = 4096
            int wi = idx >> 6, wj = idx & 63;
            Wt[wj][wi] = Wm[idx];
        }
        __syncthreads();

        float acc[8];
        #pragma unroll
        for (int rr = 0; rr < 8; rr++) acc[rr] = 0.f;
        #pragma unroll
        for (int j = 0; j < 64; j++) {
            float w = Wt[j][i];
            #pragma unroll
            for (int rr = 0; rr < 8; rr++)
                acc[rr] += xs[rg * 8 + rr][j] * w;
        }
        #pragma unroll
        for (int rr = 0; rr < 8; rr++) {
            int row = rbase + rg * 8 + rr;
            if (m == 0) {
                g_q[(size_t)row * 64 + i] = acc[rr];
            } else {
                int n = row >> 13;
                int t = (row >> 3) & 1023;
                int h = row & 7;
                size_t o = (((size_t)(n * LP + t) * HH + h) << 6) + i;
                if (m == 1) g_k[o] = acc[rr]; else g_v[o] = acc[rr];
            }
        }
        __syncthreads();
    }
}

// -------------------- persistent kv slots ----------------------------------
__global__ void persist_kernel(const float* __restrict__ pk,
                               const float* __restrict__ pv) {
    int idx = blockIdx.x * 256 + threadIdx.x;       // NB*PP*HH*DD = 65536
    if (idx >= NB * PP * HH * DD) return;
    int d = idx & 63, h = (idx >> 6) & 7, p = (idx >> 9) & 15, n = idx >> 13;
    size_t o = (((size_t)(n * LP + TT + p) * HH + h) << 6) + d;
    int src = ((p * HH + h) << 6) + d;
    g_k[o] = pk[src];
    g_v[o] = pv[src];
}

// -------------------- per-head energy + ALiBi bias -------------------------
// block: z = n*8+h, y = q-tile (16), x = k-tile (17). 64x64 tile, K=64.
__global__ void energy_kernel() {
    const int kt = blockIdx.x;
    const int qt = blockIdx.y;
    const int ng = blockIdx.z;
    const int n = ng >> 3, h = ng & 7;
    __shared__ __align__(16) float As[32][68];
    __shared__ __align__(16) float Bs[32][68];
    const int tid = threadIdx.x;
    const int tx = tid & 15, ty = tid >> 4;

    float acc[4][4];
    #pragma unroll
    for (int i = 0; i < 4; i++)
        #pragma unroll
        for (int j = 0; j < 4; j++) acc[i][j] = 0.f;

    const float* qbase = g_q + ((size_t)n * TT + qt * 64) * EE + h * 64;
    const float* kbase = g_k + ((size_t)n * LP + kt * 64) * EE + h * 64;
    int krows = LP - kt * 64; if (krows > 64) krows = 64;

    for (int cc = 0; cc < 64; cc += 32) {
        #pragma unroll
        for (int l = 0; l < 8; l++) {
            int idx = tid + l * 256;            // 2048
            int row = idx >> 5, c = idx & 31;
            As[c][row] = qbase[(size_t)row * EE + cc + c];
            Bs[c][row] = (row < krows) ? kbase[(size_t)row * EE + cc + c] : 0.f;
        }
        __syncthreads();
        #pragma unroll
        for (int k2 = 0; k2 < 32; k2++) {
            float4 a4 = *(const float4*)(&As[k2][ty * 4]);
            float4 b4 = *(const float4*)(&Bs[k2][tx * 4]);
            float a[4] = {a4.x, a4.y, a4.z, a4.w};
            float b[4] = {b4.x, b4.y, b4.z, b4.w};
            #pragma unroll
            for (int i = 0; i < 4; i++)
                #pragma unroll
                for (int j = 0; j < 4; j++)
                    acc[i][j] += a[i] * b[j];
        }
        __syncthreads();
    }

    const float slope = exp2f(-(float)(h + 1));     // ALiBi slope for head h
    const int q0 = qt * 64 + ty * 4;
    const int k0 = kt * 64 + tx * 4;
    #pragma unroll
    for (int i = 0; i < 4; i++) {
        int Q = q0 + i;
        #pragma unroll
        for (int j = 0; j < 4; j++) {
            int Kk = k0 + j;
            if (Kk < LP) {
                float e = acc[i][j];
                if (Kk < TT) e -= fabsf((float)(Q - Kk)) * slope;
                g_att[((size_t)(ng * TT + Q)) * LP + Kk] = e;
            }
        }
    }
}

// ------------- pre-mix -> mask -> softmax -> post-mix (fused) ---------------
// one block per (n,q). 8 rows of 1040 held in shared.
__global__ void softmax_kernel(const float* __restrict__ pre,
                               const float* __restrict__ post,
                               const int* __restrict__ seq_mask) {
    __shared__ float sm[8][LP];
    __shared__ float ps_pre[64];
    __shared__ float ps_post[64];
    const int nq = blockIdx.x;
    const int n = nq >> 10, q = nq & 1023;
    const int tid = threadIdx.x;

    if (tid < 64) { ps_pre[tid] = pre[tid]; ps_post[tid] = post[tid]; }

    // load 8 head-rows
    for (int idx = tid; idx < 8 * LP; idx += 256) {
        int h = idx / LP, kk = idx - h * LP;
        sm[h][kk] = g_att[((size_t)((n * 8 + h) * TT + q)) * LP + kk];
    }
    __syncthreads();

    // pre-softmax talking heads + mask (column-exclusive, in place)
    for (int kk = tid; kk < LP; kk += 256) {
        float a[8];
        #pragma unroll
        for (int h = 0; h < 8; h++) a[h] = sm[h][kk];
        bool masked = (kk < TT) && (seq_mask[n * TT + kk] == 0);
        #pragma unroll
        for (int g = 0; g < 8; g++) {
            float o = 0.f;
            #pragma unroll
            for (int h = 0; h < 8; h++) o += ps_pre[g * 8 + h] * a[h];
            sm[g][kk] = masked ? -1e4f : o;
        }
    }
    __syncthreads();

    // row-wise softmax of (energy * scale): warp w owns row w
    const int w = tid >> 5, lane = tid & 31;
    float mx = -1e30f;
    for (int kk = lane; kk < LP; kk += 32) {
        float v = sm[w][kk] * SOFTMAX_SCALE;
        sm[w][kk] = v;
        mx = fmaxf(mx, v);
    }
    #pragma unroll
    for (int o = 16; o; o >>= 1) mx = fmaxf(mx, __shfl_xor_sync(0xffffffffu, mx, o));
    float s = 0.f;
    for (int kk = lane; kk < LP; kk += 32) {
        float p = __expf(sm[w][kk] - mx);
        sm[w][kk] = p;
        s += p;
    }
    #pragma unroll
    for (int o = 16; o; o >>= 1) s += __shfl_xor_sync(0xffffffffu, s, o);
    float inv = 1.f / s;
    for (int kk = lane; kk < LP; kk += 32) sm[w][kk] *= inv;
    __syncthreads();

    // post-softmax talking heads, write back to global
    for (int kk = tid; kk < LP; kk += 256) {
        float a[8];
        #pragma unroll
        for (int h = 0; h < 8; h++) a[h] = sm[h][kk];
        #pragma unroll
        for (int g = 0; g < 8; g++) {
            float o = 0.f;
            #pragma unroll
            for (int h = 0; h < 8; h++) o += ps_post[g * 8 + h] * a[h];
            g_att[((size_t)((n * 8 + g) * TT + q)) * LP + kk] = o;
        }
    }
}

// ------------------------- attn @ V ----------------------------------------
// block: y = n*8+h, x = q-tile (16). out 64q x 64d, K = 1040
__global__ void av_kernel() {
    const int qt = blockIdx.x;
    const int ng = blockIdx.y;
    const int n = ng >> 3, h = ng & 7;
    __shared__ __align__(16) float As[32][68];
    __shared__ __align__(16) float Bs[32][68];
    const int tid = threadIdx.x;
    const int tx = tid & 15, ty = tid >> 4;

    float acc[4][4];
    #pragma unroll
    for (int i = 0; i < 4; i++)
        #pragma unroll
        for (int j = 0; j < 4; j++) acc[i][j] = 0.f;

    const float* abase = g_att + ((size_t)(ng * TT + qt * 64)) * LP;
    for (int ll = 0; ll < LP; ll += 32) {
        #pragma unroll
        for (int l = 0; l < 8; l++) {
            int idx = tid + l * 256;
            int row = idx >> 5, c = idx & 31;                // attn: [q row][l]
            As[c][row] = (ll + c < LP) ? abase[(size_t)row * LP + ll + c] : 0.f;
            int vl = idx >> 6, d = idx & 63;                 // v: [l][d]
            Bs[vl][d] = (ll + vl < LP)
                ? g_v[(((size_t)(n * LP + ll + vl)) * HH + h) * 64 + d] : 0.f;
        }
        __syncthreads();
        #pragma unroll
        for (int k2 = 0; k2 < 32; k2++) {
            float4 a4 = *(const float4*)(&As[k2][ty * 4]);
            float4 b4 = *(const float4*)(&Bs[k2][tx * 4]);
            float a[4] = {a4.x, a4.y, a4.z, a4.w};
            float b[4] = {b4.x, b4.y, b4.z, b4.w};
            #pragma unroll
            for (int i = 0; i < 4; i++)
                #pragma unroll
                for (int j = 0; j < 4; j++)
                    acc[i][j] += a[i] * b[j];
        }
        __syncthreads();
    }

    const int q0 = qt * 64 + ty * 4;
    const int d0 = tx * 4;
    #pragma unroll
    for (int i = 0; i < 4; i++)
        #pragma unroll
        for (int j = 0; j < 4; j++)
            g_ctx[(((size_t)(n * TT + q0 + i)) * HH + h) * 64 + d0 + j] = acc[i][j];
}

// -------------------- output projection + residual -------------------------
// C(8192,512) = ctx @ Wo^T + bo + x   -> g_h
__global__ void outproj_kernel(const float* __restrict__ Wo,
                               const float* __restrict__ bo,
                               const float* __restrict__ x) {
    const int ct = blockIdx.x;          // 0..7
    const int rt = blockIdx.y;          // 0..127
    __shared__ __align__(16) float As[32][68];
    __shared__ __align__(16) float Bs[32][68];
    const int tid = threadIdx.x;
    const int tx = tid & 15, ty = tid >> 4;

    float acc[4][4];
    #pragma unroll
    for (int i = 0; i < 4; i++)
        #pragma unroll
        for (int j = 0; j < 4; j++) acc[i][j] = 0.f;

    for (int cc = 0; cc < EE; cc += 32) {
        #pragma unroll
        for (int l = 0; l < 8; l++) {
            int idx = tid + l * 256;
            int row = idx >> 5, c = idx & 31;
            As[c][row] = g_ctx[(size_t)(rt * 64 + row) * EE + cc + c];
            Bs[c][row] = Wo[(size_t)(ct * 64 + row) * EE + cc + c];
        }
        __syncthreads();
        #pragma unroll
        for (int k2 = 0; k2 < 32; k2++) {
            float4 a4 = *(const float4*)(&As[k2][ty * 4]);
            float4 b4 = *(const float4*)(&Bs[k2][tx * 4]);
            float a[4] = {a4.x, a4.y, a4.z, a4.w};
            float b[4] = {b4.x, b4.y, b4.z, b4.w};
            #pragma unroll
            for (int i = 0; i < 4; i++)
                #pragma unroll
                for (int j = 0; j < 4; j++)
                    acc[i][j] += a[i] * b[j];
        }
        __syncthreads();
    }

    const int r0 = rt * 64 + ty * 4;
    const int c0 = ct * 64 + tx * 4;
    #pragma unroll
    for (int i = 0; i < 4; i++)
        #pragma unroll
        for (int j = 0; j < 4; j++) {
            size_t o = (size_t)(r0 + i) * EE + c0 + j;
            g_h[o] = acc[i][j] + bo[c0 + j] + x[o];
        }
}

// ------------------------- causal conv (k=3) --------------------------------
// stage 0: g_h -> relu((conv+b)*valid) -> g_t1
// stage 1: g_t1 -> relu(relu((conv+b)*valid) + g_h) -> g_t2
__global__ void conv_kernel(int stage,
                            const float* __restrict__ W,
                            const float* __restrict__ b,
                            const int* __restrict__ seq_mask) {
    const float* in  = stage ? g_t1 : g_h;
    float*       out = stage ? g_t2 : g_t1;
    const int ct = blockIdx.x;          // 0..7
    const int rt = blockIdx.y;          // 0..127
    __shared__ float Is[32][67];                     // [ci][row 0..65]
    __shared__ __align__(16) float Ws[3][32][68];    // [k][ci][co]
    const int tid = threadIdx.x;
    const int tx = tid & 15, ty = tid >> 4;

    const int r0 = rt * 64;
    const int nBase = r0 & ~1023;

    float acc[4][4];
    #pragma unroll
    for (int i = 0; i < 4; i++)
        #pragma unroll
        for (int j = 0; j < 4; j++) acc[i][j] = 0.f;

    for (int cc = 0; cc < EE; cc += 32) {
        for (int idx = tid; idx < 66 * 32; idx += 256) {
            int s = idx >> 5, c = idx & 31;
            int gr = r0 - 2 + s;
            Is[c][s] = (gr >= nBase) ? in[(size_t)gr * EE + cc + c] : 0.f;
        }
        for (int idx = tid; idx < 64 * 96; idx += 256) {
            int co = idx / 96;
            int rem = idx - co * 96;
            int ci = rem / 3;
            int k  = rem - ci * 3;
            Ws[k][ci][co] = W[((size_t)(ct * 64 + co) * EE + cc + ci) * 3 + k];
        }
        __syncthreads();
        #pragma unroll
        for (int c2 = 0; c2 < 32; c2++) {
            float4 w0 = *(const float4*)(&Ws[0][c2][tx * 4]);
            float4 w1 = *(const float4*)(&Ws[1][c2][tx * 4]);
            float4 w2 = *(const float4*)(&Ws[2][c2][tx * 4]);
            float xv[6];
            #pragma unroll
            for (int s = 0; s < 6; s++) xv[s] = Is[c2][ty * 4 + s];
            float wj0[4] = {w0.x, w0.y, w0.z, w0.w};
            float wj1[4] = {w1.x, w1.y, w1.z, w1.w};
            float wj2[4] = {w2.x, w2.y, w2.z, w2.w};
            #pragma unroll
            for (int i = 0; i < 4; i++)
                #pragma unroll
                for (int j = 0; j < 4; j++)
                    acc[i][j] += wj0[j] * xv[i] + wj1[j] * xv[i + 1] + wj2[j] * xv[i + 2];
        }
        __syncthreads();
    }

    #pragma unroll
    for (int i = 0; i < 4; i++) {
        int r = r0 + ty * 4 + i;
        float valid = (float)seq_mask[r];
        #pragma unroll
        for (int j = 0; j < 4; j++) {
            int co = ct * 64 + tx * 4 + j;
            float y = (acc[i][j] + b[co]) * valid;
            y = fmaxf(y, 0.f);
            if (stage) y = fmaxf(y + g_h[(size_t)r * EE + co], 0.f);
            out[(size_t)r * EE + co] = y;
        }
    }
}

// ------------------------------ LayerNorm ----------------------------------
__global__ void ln_kernel(const float* __restrict__ gamma,
                          const float* __restrict__ beta,
                          float* __restrict__ out) {
    const int r = blockIdx.x;
    const int tid = threadIdx.x;        // 256
    const float* in = g_t2 + (size_t)r * EE;
    __shared__ float red[8];

    float v0 = in[tid], v1 = in[tid + 256];
    float s = v0 + v1;
    #pragma unroll
    for (int o = 16; o; o >>= 1) s += __shfl_xor_sync(0xffffffffu, s, o);
    if ((tid & 31) == 0) red[tid >> 5] = s;
    __syncthreads();
    float tot = 0.f;
    #pragma unroll
    for (int i = 0; i < 8; i++) tot += red[i];
    float mu = tot * (1.f / EE);
    __syncthreads();

    float d0 = v0 - mu, d1 = v1 - mu;
    float vs = d0 * d0 + d1 * d1;
    #pragma unroll
    for (int o = 16; o; o >>= 1) vs += __shfl_xor_sync(0xffffffffu, vs, o);
    if ((tid & 31) == 0) red[tid >> 5] = vs;
    __syncthreads();
    float vtot = 0.f;
    #pragma unroll
    for (int i = 0; i < 8; i++) vtot += red[i];
    float inv = rsqrtf(vtot * (1.f / EE) + 1e-5f);

    out[(size_t)r * EE + tid]       = d0 * inv * gamma[tid]       + beta[tid];
    out[(size_t)r * EE + tid + 256] = d1 * inv * gamma[tid + 256] + beta[tid + 256];
}

// ------------------------------ launcher -----------------------------------
extern "C" void kernel_launch(void* const* d_in, const int* in_sizes, int n_in,
                              void* d_out, int out_size) {
    const float* x        = (const float*)d_in[0];
    const int*   seq_mask = (const int*)  d_in[1];
    const float* Wq       = (const float*)d_in[2];
    const float* Wk       = (const float*)d_in[3];
    const float* Wv       = (const float*)d_in[4];
    const float* Wo       = (const float*)d_in[5];
    const float* bo       = (const float*)d_in[6];
    const float* pre_th   = (const float*)d_in[7];
    const float* post_th  = (const float*)d_in[8];
    const float* pk       = (const float*)d_in[9];
    const float* pv       = (const float*)d_in[10];
    const float* c1W      = (const float*)d_in[11];
    const float* c1b      = (const float*)d_in[12];
    const float* c2W      = (const float*)d_in[13];
    const float* c2b      = (const float*)d_in[14];
    const float* ln_g     = (const float*)d_in[15];
    const float* ln_b     = (const float*)d_in[16];
    float* out = (float*)d_out;

    qkv_kernel<<<2048, 256>>>(x, Wq, Wk, Wv);
    persist_kernel<<<256, 256>>>(pk, pv);
    energy_kernel<<<dim3(17, 16, 64), 256>>>();
    softmax_kernel<<<8192, 256>>>(pre_th, post_th, seq_mask);
    av_kernel<<<dim3(16, 64), 256>>>();
    outproj_kernel<<<dim3(8, 128), 256>>>(Wo, bo, x);
    conv_kernel<<<dim3(8, 128), 256>>>(0, c1W, c1b, seq_mask);
    conv_kernel<<<dim3(8, 128), 256>>>(1, c2W, c2b, seq_mask);
    ln_kernel<<<8192, 256>>>(ln_g, ln_b, out);
}

// round 4
// speedup vs baseline: 1.5485x; 1.5485x over previous
#include <cuda_runtime.h>
#include <cuda_bf16.h>
#include <math.h>
#include <stdint.h>

// ---------------------------------------------------------------------------
// TCNAttentionBlock: ALiBi + persistent-memory + talking-heads MHA -> residual
// -> causal TCN (2x conv k=3) -> LayerNorm.
// N=8, T=1024, E=512, H=8, D=64, P=16.
// R4: outproj + conv1 + conv2 on mma.sync (HMMA) bf16 split-pair.
//     Fix vs R3: B operand uses ldmatrix NON-trans (B stored [n][k]).
// ---------------------------------------------------------------------------

#define NB   8
#define TT   1024
#define EE   512
#define HH   8
#define DD   64
#define PP   16
#define LP   1040            // TT + PP
#define NT   8192            // NB*TT
#define SOFTMAX_SCALE 0.044194173824159216f   // 1/sqrt(512)

// ------------------------------ scratch -----------------------------------
__device__ float g_q  [NB * TT * HH * DD];
__device__ float g_k  [NB * LP * HH * DD];
__device__ float g_v  [NB * LP * HH * DD];
__device__ float g_att[(size_t)NB * HH * TT * LP];
__device__ float g_ctx[NB * TT * EE];
__device__ float g_h  [NB * TT * EE];
__device__ float g_t1 [NB * TT * EE];
__device__ float g_t2 [NB * TT * EE];

// preconverted bf16 split weights, layout [chunk][co(512)][64]
__device__ __nv_bfloat16 g_WoHi[8  * 512 * 64];
__device__ __nv_bfloat16 g_WoLo[8  * 512 * 64];
__device__ __nv_bfloat16 g_c1Hi[24 * 512 * 64];
__device__ __nv_bfloat16 g_c1Lo[24 * 512 * 64];
__device__ __nv_bfloat16 g_c2Hi[24 * 512 * 64];
__device__ __nv_bfloat16 g_c2Lo[24 * 512 * 64];

// ---------------------------- PTX helpers ----------------------------------
__device__ __forceinline__ uint32_t smem_u32(const void* p) {
    uint32_t a;
    asm("{ .reg .u64 t; cvta.to.shared.u64 t, %1; cvt.u32.u64 %0, t; }"
        : "=r"(a) : "l"(p));
    return a;
}
#define SWZ(o) ((o) ^ (((o) >> 3) & 0x70))

__device__ __forceinline__ void ldsm4(uint32_t* r, uint32_t addr) {
    asm volatile("ldmatrix.sync.aligned.m8n8.x4.shared.b16 {%0,%1,%2,%3}, [%4];"
                 : "=r"(r[0]), "=r"(r[1]), "=r"(r[2]), "=r"(r[3]) : "r"(addr));
}
__device__ __forceinline__ void mma16816(float* c, const uint32_t* a, const uint32_t* b) {
    asm volatile(
        "mma.sync.aligned.m16n8k16.row.col.f32.bf16.bf16.f32 "
        "{%0,%1,%2,%3}, {%4,%5,%6,%7}, {%8,%9}, {%0,%1,%2,%3};"
        : "+f"(c[0]), "+f"(c[1]), "+f"(c[2]), "+f"(c[3])
        : "r"(a[0]), "r"(a[1]), "r"(a[2]), "r"(a[3]), "r"(b[0]), "r"(b[1]));
}
__device__ __forceinline__ void cpasync16(uint32_t saddr, const void* g) {
    asm volatile("cp.async.cg.shared.global [%0], [%1], 16;" :: "r"(saddr), "l"(g));
}
__device__ __forceinline__ void cp_commit() {
    asm volatile("cp.async.commit_group;" ::: "memory");
}
__device__ __forceinline__ void cp_wait0() {
    asm volatile("cp.async.wait_group 0;" ::: "memory");
}
__device__ __forceinline__ uint32_t pack_bf2(__nv_bfloat16 a, __nv_bfloat16 b) {
    return (uint32_t)__bfloat16_as_ushort(a) | ((uint32_t)__bfloat16_as_ushort(b) << 16);
}

// ---------------------- weight preconversion -------------------------------
__global__ void conv_w_convert(const float* __restrict__ W,
                               __nv_bfloat16* __restrict__ hi,
                               __nv_bfloat16* __restrict__ lo) {
    int d = blockIdx.x * 256 + threadIdx.x;          // 24*512*64 = 786432
    int c  = d >> 15;
    int co = (d >> 6) & 511;
    int ci = d & 63;
    int tap = c >> 3, cib = (c & 7) << 6;
    float v = W[(size_t)(co * 512 + cib + ci) * 3 + tap];
    __nv_bfloat16 h = __float2bfloat16(v);
    hi[d] = h;
    lo[d] = __float2bfloat16(v - __bfloat162float(h));
}
__global__ void wo_convert(const float* __restrict__ W,
                           __nv_bfloat16* __restrict__ hi,
                           __nv_bfloat16* __restrict__ lo) {
    int d = blockIdx.x * 256 + threadIdx.x;          // 8*512*64 = 262144
    int c  = d >> 15;
    int co = (d >> 6) & 511;
    int ci = d & 63;
    float v = W[co * 512 + (c << 6) + ci];
    __nv_bfloat16 h = __float2bfloat16(v);
    hi[d] = h;
    lo[d] = __float2bfloat16(v - __bfloat162float(h));
}

// ---------------------- HMMA GEMM (outproj / conv) --------------------------
// C[t-tile 128, co-tile 128] = A[t,K] @ B[co,K]^T, bf16 split-pair (3 terms).
// mode 0: outproj (K=512): OUT = acc + bias + resid
// mode 1: conv1   (K=1536 im2col): OUT = relu((acc+bias)*valid)
// mode 2: conv2   (K=1536): OUT = relu(relu((acc+bias)*valid) + resid)
#define A_HI 0
#define A_LO 16384
#define B_HI 32768
#define B_LO 49152
#define BUF_STRIDE 65536
#define GEMM_SMEM (2 * BUF_STRIDE)

__global__ void __launch_bounds__(256) gemm_hmma_kernel(
    int mode, int nchunk,
    const float* __restrict__ IN,
    const __nv_bfloat16* __restrict__ BHg,
    const __nv_bfloat16* __restrict__ BLg,
    const float* __restrict__ bias,
    const float* __restrict__ resid,
    const int* __restrict__ seq_mask,
    float* __restrict__ OUT)
{
    extern __shared__ char smem[];
    const uint32_t sbase = smem_u32(smem);
    const int tid = threadIdx.x;
    const int lane = tid & 31, wid = tid >> 5;
    const int t0 = blockIdx.x * 128;
    const int co0 = blockIdx.y * 128;
    const int nBseq = t0 & ~1023;
    const int m0w = (wid & 1) * 64;
    const int n0w = (wid >> 1) * 32;

    float C[4][4][4];
    #pragma unroll
    for (int mt = 0; mt < 4; ++mt)
        #pragma unroll
        for (int nt = 0; nt < 4; ++nt)
            #pragma unroll
            for (int i = 0; i < 4; ++i) C[mt][nt][i] = 0.f;

    float4 areg[8];

    // ---- prologue: stage chunk 0
    {
        int shift, cib;
        if (mode == 0) { shift = 0; cib = 0; }
        else           { shift = -2; cib = 0; }
        #pragma unroll
        for (int it = 0; it < 8; ++it) {
            int lin = it * 1024 + tid * 4;
            int r = lin >> 6, ci = lin & 63;
            int grow = t0 + r + shift;
            areg[it] = make_float4(0.f, 0.f, 0.f, 0.f);
            if (grow >= nBseq)
                areg[it] = *(const float4*)(IN + (size_t)grow * 512 + cib + ci);
        }
        char* bp = smem;
        #pragma unroll
        for (int it = 0; it < 8; ++it) {
            int lin = it * 1024 + tid * 4;
            int r = lin >> 6, ci = lin & 63;
            float4 v = areg[it];
            __nv_bfloat16 h0 = __float2bfloat16(v.x), h1 = __float2bfloat16(v.y);
            __nv_bfloat16 h2 = __float2bfloat16(v.z), h3 = __float2bfloat16(v.w);
            __nv_bfloat16 l0 = __float2bfloat16(v.x - __bfloat162float(h0));
            __nv_bfloat16 l1 = __float2bfloat16(v.y - __bfloat162float(h1));
            __nv_bfloat16 l2 = __float2bfloat16(v.z - __bfloat162float(h2));
            __nv_bfloat16 l3 = __float2bfloat16(v.w - __bfloat162float(h3));
            uint32_t off = SWZ((uint32_t)(r * 128 + ci * 2));
            *(uint2*)(bp + A_HI + off) = make_uint2(pack_bf2(h0, h1), pack_bf2(h2, h3));
            *(uint2*)(bp + A_LO + off) = make_uint2(pack_bf2(l0, l1), pack_bf2(l2, l3));
        }
        #pragma unroll
        for (int it = 0; it < 4; ++it) {
            int s = it * 256 + tid;
            int r = s >> 3, cb = s & 7;
            size_t gb = ((size_t)(co0 + r)) * 64 + cb * 8;
            uint32_t off = SWZ((uint32_t)(r * 128 + cb * 16));
            cpasync16(sbase + B_HI + off, BHg + gb);
            cpasync16(sbase + B_LO + off, BLg + gb);
        }
        cp_commit();
    }

    for (int c = 0; c < nchunk; ++c) {
        cp_wait0();
        __syncthreads();
        const bool hn = (c + 1 < nchunk);
        const int nb = (c + 1) & 1;

        if (hn) {
            int cn = c + 1;
            int shift, cib;
            if (mode == 0) { shift = 0; cib = cn << 6; }
            else           { shift = (cn >> 3) - 2; cib = (cn & 7) << 6; }
            #pragma unroll
            for (int it = 0; it < 8; ++it) {
                int lin = it * 1024 + tid * 4;
                int r = lin >> 6, ci = lin & 63;
                int grow = t0 + r + shift;
                areg[it] = make_float4(0.f, 0.f, 0.f, 0.f);
                if (grow >= nBseq)
                    areg[it] = *(const float4*)(IN + (size_t)grow * 512 + cib + ci);
            }
            uint32_t bb = sbase + nb * BUF_STRIDE;
            #pragma unroll
            for (int it = 0; it < 4; ++it) {
                int s = it * 256 + tid;
                int r = s >> 3, cb = s & 7;
                size_t gb = ((size_t)cn * 512 + co0 + r) * 64 + cb * 8;
                uint32_t off = SWZ((uint32_t)(r * 128 + cb * 16));
                cpasync16(bb + B_HI + off, BHg + gb);
                cpasync16(bb + B_LO + off, BLg + gb);
            }
            cp_commit();
        }

        // ---- compute on buffer c&1
        const uint32_t Ab = sbase + (c & 1) * BUF_STRIDE;
        #pragma unroll
        for (int ks = 0; ks < 4; ++ks) {
            uint32_t ah[4][4], al[4][4];
            #pragma unroll
            for (int mt = 0; mt < 4; ++mt) {
                uint32_t off = SWZ((uint32_t)((m0w + mt * 16 + (lane & 15)) * 128
                                              + ks * 32 + (lane >> 4) * 16));
                ldsm4(ah[mt], Ab + A_HI + off);
                ldsm4(al[mt], Ab + A_LO + off);
            }
            uint32_t bh[8], bl[8];
            #pragma unroll
            for (int p = 0; p < 2; ++p) {
                uint32_t off = SWZ((uint32_t)((n0w + p * 16 + (lane & 7) + ((lane >> 4) & 1) * 8) * 128
                                              + ks * 32 + ((lane >> 3) & 1) * 16));
                ldsm4(&bh[p * 4], Ab + B_HI + off);   // NON-trans: B stored [n][k]
                ldsm4(&bl[p * 4], Ab + B_LO + off);
            }
            #pragma unroll
            for (int mt = 0; mt < 4; ++mt)
                #pragma unroll
                for (int nt = 0; nt < 4; ++nt) {
                    const uint32_t* bhp = &bh[(nt >> 1) * 4 + (nt & 1) * 2];
                    const uint32_t* blp = &bl[(nt >> 1) * 4 + (nt & 1) * 2];
                    mma16816(C[mt][nt], ah[mt], bhp);
                    mma16816(C[mt][nt], ah[mt], blp);
                    mma16816(C[mt][nt], al[mt], bhp);
                }
        }

        // ---- stage A(c+1) into buffer (c+1)&1
        if (hn) {
            char* bp = smem + nb * BUF_STRIDE;
            #pragma unroll
            for (int it = 0; it < 8; ++it) {
                int lin = it * 1024 + tid * 4;
                int r = lin >> 6, ci = lin & 63;
                float4 v = areg[it];
                __nv_bfloat16 h0 = __float2bfloat16(v.x), h1 = __float2bfloat16(v.y);
                __nv_bfloat16 h2 = __float2bfloat16(v.z), h3 = __float2bfloat16(v.w);
                __nv_bfloat16 l0 = __float2bfloat16(v.x - __bfloat162float(h0));
                __nv_bfloat16 l1 = __float2bfloat16(v.y - __bfloat162float(h1));
                __nv_bfloat16 l2 = __float2bfloat16(v.z - __bfloat162float(h2));
                __nv_bfloat16 l3 = __float2bfloat16(v.w - __bfloat162float(h3));
                uint32_t off = SWZ((uint32_t)(r * 128 + ci * 2));
                *(uint2*)(bp + A_HI + off) = make_uint2(pack_bf2(h0, h1), pack_bf2(h2, h3));
                *(uint2*)(bp + A_LO + off) = make_uint2(pack_bf2(l0, l1), pack_bf2(l2, l3));
            }
        }
    }

    // ---- epilogue: direct stores with fused bias/mask/relu/residual
    #pragma unroll
    for (int mt = 0; mt < 4; ++mt) {
        int rb = t0 + m0w + mt * 16 + (lane >> 2);
        #pragma unroll
        for (int nt = 0; nt < 4; ++nt) {
            int col = co0 + n0w + nt * 8 + (lane & 3) * 2;
            float b0 = bias[col], b1 = bias[col + 1];
            #pragma unroll
            for (int hf = 0; hf < 2; ++hf) {
                int r = rb + hf * 8;
                float y0 = C[mt][nt][hf * 2 + 0] + b0;
                float y1 = C[mt][nt][hf * 2 + 1] + b1;
                if (mode == 0) {
                    const float2 rs = *(const float2*)(resid + (size_t)r * 512 + col);
                    y0 += rs.x; y1 += rs.y;
                } else {
                    float valid = (float)seq_mask[r];
                    y0 = fmaxf(y0 * valid, 0.f);
                    y1 = fmaxf(y1 * valid, 0.f);
                    if (mode == 2) {
                        const float2 rs = *(const float2*)(resid + (size_t)r * 512 + col);
                        y0 = fmaxf(y0 + rs.x, 0.f);
                        y1 = fmaxf(y1 + rs.y, 0.f);
                    }
                }
                *(float2*)(OUT + (size_t)r * 512 + col) = make_float2(y0, y1);
            }
        }
    }
}

// ------------------------------ QKV projection -----------------------------
__global__ void qkv_kernel(const float* __restrict__ x,
                           const float* __restrict__ Wq,
                           const float* __restrict__ Wk,
                           const float* __restrict__ Wv) {
    __shared__ float xs[32][65];
    __shared__ float Wt[64][65];
    const int rbase = blockIdx.x * 32;
    const int tid = threadIdx.x;

    #pragma unroll
    for (int l = 0; l < 8; l++) {
        int idx = tid + l * 256;
        int r = idx >> 6, c = idx & 63;
        xs[r][c] = x[(size_t)(rbase + r) * 64 + c];
    }

    const int i  = tid & 63;
    const int rg = tid >> 6;

    for (int m = 0; m < 3; m++) {
        const float* Wm = (m == 0) ? Wq : (m == 1) ? Wk : Wv;
        #pragma unroll
        for (int l = 0; l < 16; l++) {
            int idx = tid + l * 256;
            int wi = idx >> 6, wj = idx & 63;
            Wt[wj][wi] = Wm[idx];
        }
        __syncthreads();

        float acc[8];
        #pragma unroll
        for (int rr = 0; rr < 8; rr++) acc[rr] = 0.f;
        #pragma unroll
        for (int j = 0; j < 64; j++) {
            float w = Wt[j][i];
            #pragma unroll
            for (int rr = 0; rr < 8; rr++)
                acc[rr] += xs[rg * 8 + rr][j] * w;
        }
        #pragma unroll
        for (int rr = 0; rr < 8; rr++) {
            int row = rbase + rg * 8 + rr;
            if (m == 0) {
                g_q[(size_t)row * 64 + i] = acc[rr];
            } else {
                int n = row >> 13;
                int t = (row >> 3) & 1023;
                int h = row & 7;
                size_t o = (((size_t)(n * LP + t) * HH + h) << 6) + i;
                if (m == 1) g_k[o] = acc[rr]; else g_v[o] = acc[rr];
            }
        }
        __syncthreads();
    }
}

// -------------------- persistent kv slots ----------------------------------
__global__ void persist_kernel(const float* __restrict__ pk,
                               const float* __restrict__ pv) {
    int idx = blockIdx.x * 256 + threadIdx.x;
    if (idx >= NB * PP * HH * DD) return;
    int d = idx & 63, h = (idx >> 6) & 7, p = (idx >> 9) & 15, n = idx >> 13;
    size_t o = (((size_t)(n * LP + TT + p) * HH + h) << 6) + d;
    int src = ((p * HH + h) << 6) + d;
    g_k[o] = pk[src];
    g_v[o] = pv[src];
}

// -------------------- per-head energy + ALiBi bias -------------------------
__global__ void energy_kernel() {
    const int kt = blockIdx.x;
    const int qt = blockIdx.y;
    const int ng = blockIdx.z;
    const int n = ng >> 3, h = ng & 7;
    __shared__ __align__(16) float As[32][68];
    __shared__ __align__(16) float Bs[32][68];
    const int tid = threadIdx.x;
    const int tx = tid & 15, ty = tid >> 4;

    float acc[4][4];
    #pragma unroll
    for (int i = 0; i < 4; i++)
        #pragma unroll
        for (int j = 0; j < 4; j++) acc[i][j] = 0.f;

    const float* qbase = g_q + ((size_t)n * TT + qt * 64) * EE + h * 64;
    const float* kbase = g_k + ((size_t)n * LP + kt * 64) * EE + h * 64;
    int krows = LP - kt * 64; if (krows > 64) krows = 64;

    for (int cc = 0; cc < 64; cc += 32) {
        #pragma unroll
        for (int l = 0; l < 8; l++) {
            int idx = tid + l * 256;
            int row = idx >> 5, c = idx & 31;
            As[c][row] = qbase[(size_t)row * EE + cc + c];
            Bs[c][row] = (row < krows) ? kbase[(size_t)row * EE + cc + c] : 0.f;
        }
        __syncthreads();
        #pragma unroll
        for (int k2 = 0; k2 < 32; k2++) {
            float4 a4 = *(const float4*)(&As[k2][ty * 4]);
            float4 b4 = *(const float4*)(&Bs[k2][tx * 4]);
            float a[4] = {a4.x, a4.y, a4.z, a4.w};
            float b[4] = {b4.x, b4.y, b4.z, b4.w};
            #pragma unroll
            for (int i = 0; i < 4; i++)
                #pragma unroll
                for (int j = 0; j < 4; j++)
                    acc[i][j] += a[i] * b[j];
        }
        __syncthreads();
    }

    const float slope = exp2f(-(float)(h + 1));
    const int q0 = qt * 64 + ty * 4;
    const int k0 = kt * 64 + tx * 4;
    #pragma unroll
    for (int i = 0; i < 4; i++) {
        int Q = q0 + i;
        #pragma unroll
        for (int j = 0; j < 4; j++) {
            int Kk = k0 + j;
            if (Kk < LP) {
                float e = acc[i][j];
                if (Kk < TT) e -= fabsf((float)(Q - Kk)) * slope;
                g_att[((size_t)(ng * TT + Q)) * LP + Kk] = e;
            }
        }
    }
}

// ------------- pre-mix -> mask -> softmax -> post-mix (fused) ---------------
__global__ void softmax_kernel(const float* __restrict__ pre,
                               const float* __restrict__ post,
                               const int* __restrict__ seq_mask) {
    __shared__ float sm[8][LP];
    __shared__ float ps_pre[64];
    __shared__ float ps_post[64];
    const int nq = blockIdx.x;
    const int n = nq >> 10, q = nq & 1023;
    const int tid = threadIdx.x;

    if (tid < 64) { ps_pre[tid] = pre[tid]; ps_post[tid] = post[tid]; }

    for (int idx = tid; idx < 8 * LP; idx += 256) {
        int h = idx / LP, kk = idx - h * LP;
        sm[h][kk] = g_att[((size_t)((n * 8 + h) * TT + q)) * LP + kk];
    }
    __syncthreads();

    for (int kk = tid; kk < LP; kk += 256) {
        float a[8];
        #pragma unroll
        for (int h = 0; h < 8; h++) a[h] = sm[h][kk];
        bool masked = (kk < TT) && (seq_mask[n * TT + kk] == 0);
        #pragma unroll
        for (int g = 0; g < 8; g++) {
            float o = 0.f;
            #pragma unroll
            for (int h = 0; h < 8; h++) o += ps_pre[g * 8 + h] * a[h];
            sm[g][kk] = masked ? -1e4f : o;
        }
    }
    __syncthreads();

    const int w = tid >> 5, lane = tid & 31;
    float mx = -1e30f;
    for (int kk = lane; kk < LP; kk += 32) {
        float v = sm[w][kk] * SOFTMAX_SCALE;
        sm[w][kk] = v;
        mx = fmaxf(mx, v);
    }
    #pragma unroll
    for (int o = 16; o; o >>= 1) mx = fmaxf(mx, __shfl_xor_sync(0xffffffffu, mx, o));
    float s = 0.f;
    for (int kk = lane; kk < LP; kk += 32) {
        float p = __expf(sm[w][kk] - mx);
        sm[w][kk] = p;
        s += p;
    }
    #pragma unroll
    for (int o = 16; o; o >>= 1) s += __shfl_xor_sync(0xffffffffu, s, o);
    float inv = 1.f / s;
    for (int kk = lane; kk < LP; kk += 32) sm[w][kk] *= inv;
    __syncthreads();

    for (int kk = tid; kk < LP; kk += 256) {
        float a[8];
        #pragma unroll
        for (int h = 0; h < 8; h++) a[h] = sm[h][kk];
        #pragma unroll
        for (int g = 0; g < 8; g++) {
            float o = 0.f;
            #pragma unroll
            for (int h = 0; h < 8; h++) o += ps_post[g * 8 + h] * a[h];
            g_att[((size_t)((n * 8 + g) * TT + q)) * LP + kk] = o;
        }
    }
}

// ------------------------- attn @ V ----------------------------------------
__global__ void av_kernel() {
    const int qt = blockIdx.x;
    const int ng = blockIdx.y;
    const int n = ng >> 3, h = ng & 7;
    __shared__ __align__(16) float As[32][68];
    __shared__ __align__(16) float Bs[32][68];
    const int tid = threadIdx.x;
    const int tx = tid & 15, ty = tid >> 4;

    float acc[4][4];
    #pragma unroll
    for (int i = 0; i < 4; i++)
        #pragma unroll
        for (int j = 0; j < 4; j++) acc[i][j] = 0.f;

    const float* abase = g_att + ((size_t)(ng * TT + qt * 64)) * LP;
    for (int ll = 0; ll < LP; ll += 32) {
        #pragma unroll
        for (int l = 0; l < 8; l++) {
            int idx = tid + l * 256;
            int row = idx >> 5, c = idx & 31;
            As[c][row] = (ll + c < LP) ? abase[(size_t)row * LP + ll + c] : 0.f;
            int vl = idx >> 6, d = idx & 63;
            Bs[vl][d] = (ll + vl < LP)
                ? g_v[(((size_t)(n * LP + ll + vl)) * HH + h) * 64 + d] : 0.f;
        }
        __syncthreads();
        #pragma unroll
        for (int k2 = 0; k2 < 32; k2++) {
            float4 a4 = *(const float4*)(&As[k2][ty * 4]);
            float4 b4 = *(const float4*)(&Bs[k2][tx * 4]);
            float a[4] = {a4.x, a4.y, a4.z, a4.w};
            float b[4] = {b4.x, b4.y, b4.z, b4.w};
            #pragma unroll
            for (int i = 0; i < 4; i++)
                #pragma unroll
                for (int j = 0; j < 4; j++)
                    acc[i][j] += a[i] * b[j];
        }
        __syncthreads();
    }

    const int q0 = qt * 64 + ty * 4;
    const int d0 = tx * 4;
    #pragma unroll
    for (int i = 0; i < 4; i++)
        #pragma unroll
        for (int j = 0; j < 4; j++)
            g_ctx[(((size_t)(n * TT + q0 + i)) * HH + h) * 64 + d0 + j] = acc[i][j];
}

// ------------------------------ LayerNorm ----------------------------------
__global__ void ln_kernel(const float* __restrict__ gamma,
                          const float* __restrict__ beta,
                          float* __restrict__ out) {
    const int r = blockIdx.x;
    const int tid = threadIdx.x;
    const float* in = g_t2 + (size_t)r * EE;
    __shared__ float red[8];

    float v0 = in[tid], v1 = in[tid + 256];
    float s = v0 + v1;
    #pragma unroll
    for (int o = 16; o; o >>= 1) s += __shfl_xor_sync(0xffffffffu, s, o);
    if ((tid & 31) == 0) red[tid >> 5] = s;
    __syncthreads();
    float tot = 0.f;
    #pragma unroll
    for (int i = 0; i < 8; i++) tot += red[i];
    float mu = tot * (1.f / EE);
    __syncthreads();

    float d0 = v0 - mu, d1 = v1 - mu;
    float vs = d0 * d0 + d1 * d1;
    #pragma unroll
    for (int o = 16; o; o >>= 1) vs += __shfl_xor_sync(0xffffffffu, vs, o);
    if ((tid & 31) == 0) red[tid >> 5] = vs;
    __syncthreads();
    float vtot = 0.f;
    #pragma unroll
    for (int i = 0; i < 8; i++) vtot += red[i];
    float inv = rsqrtf(vtot * (1.f / EE) + 1e-5f);

    out[(size_t)r * EE + tid]       = d0 * inv * gamma[tid]       + beta[tid];
    out[(size_t)r * EE + tid + 256] = d1 * inv * gamma[tid + 256] + beta[tid + 256];
}

// ------------------------------ launcher -----------------------------------
extern "C" void kernel_launch(void* const* d_in, const int* in_sizes, int n_in,
                              void* d_out, int out_size) {
    const float* x        = (const float*)d_in[0];
    const int*   seq_mask = (const int*)  d_in[1];
    const float* Wq       = (const float*)d_in[2];
    const float* Wk       = (const float*)d_in[3];
    const float* Wv       = (const float*)d_in[4];
    const float* Wo       = (const float*)d_in[5];
    const float* bo       = (const float*)d_in[6];
    const float* pre_th   = (const float*)d_in[7];
    const float* post_th  = (const float*)d_in[8];
    const float* pk       = (const float*)d_in[9];
    const float* pv       = (const float*)d_in[10];
    const float* c1W      = (const float*)d_in[11];
    const float* c1b      = (const float*)d_in[12];
    const float* c2W      = (const float*)d_in[13];
    const float* c2b      = (const float*)d_in[14];
    const float* ln_g     = (const float*)d_in[15];
    const float* ln_b     = (const float*)d_in[16];
    float* out = (float*)d_out;

    __nv_bfloat16 *pWoHi, *pWoLo, *pC1Hi, *pC1Lo, *pC2Hi, *pC2Lo;
    cudaGetSymbolAddress((void**)&pWoHi, g_WoHi);
    cudaGetSymbolAddress((void**)&pWoLo, g_WoLo);
    cudaGetSymbolAddress((void**)&pC1Hi, g_c1Hi);
    cudaGetSymbolAddress((void**)&pC1Lo, g_c1Lo);
    cudaGetSymbolAddress((void**)&pC2Hi, g_c2Hi);
    cudaGetSymbolAddress((void**)&pC2Lo, g_c2Lo);

    float *pCtx, *pH, *pT1, *pT2;
    cudaGetSymbolAddress((void**)&pCtx, g_ctx);
    cudaGetSymbolAddress((void**)&pH,   g_h);
    cudaGetSymbolAddress((void**)&pT1,  g_t1);
    cudaGetSymbolAddress((void**)&pT2,  g_t2);

    cudaFuncSetAttribute(gemm_hmma_kernel,
                         cudaFuncAttributeMaxDynamicSharedMemorySize, GEMM_SMEM);

    wo_convert<<<1024, 256>>>(Wo, pWoHi, pWoLo);
    conv_w_convert<<<3072, 256>>>(c1W, pC1Hi, pC1Lo);
    conv_w_convert<<<3072, 256>>>(c2W, pC2Hi, pC2Lo);

    qkv_kernel<<<2048, 256>>>(x, Wq, Wk, Wv);
    persist_kernel<<<256, 256>>>(pk, pv);
    energy_kernel<<<dim3(17, 16, 64), 256>>>();
    softmax_kernel<<<8192, 256>>>(pre_th, post_th, seq_mask);
    av_kernel<<<dim3(16, 64), 256>>>();

    // outproj: g_h = ctx @ Wo^T + bo + x
    gemm_hmma_kernel<<<dim3(64, 4), 256, GEMM_SMEM>>>(
        0, 8, pCtx, pWoHi, pWoLo, bo, x, seq_mask, pH);
    // conv1: g_t1 = relu((conv(g_h)+b1)*valid)
    gemm_hmma_kernel<<<dim3(64, 4), 256, GEMM_SMEM>>>(
        1, 24, pH, pC1Hi, pC1Lo, c1b, nullptr, seq_mask, pT1);
    // conv2: g_t2 = relu(relu((conv(g_t1)+b2)*valid) + g_h)
    gemm_hmma_kernel<<<dim3(64, 4), 256, GEMM_SMEM>>>(
        2, 24, pT1, pC2Hi, pC2Lo, c2b, pH, seq_mask, pT2);

    ln_kernel<<<8192, 256>>>(ln_g, ln_b, out);
}

// round 5
// speedup vs baseline: 2.3777x; 1.5355x over previous
#include <cuda_runtime.h>
#include <cuda_bf16.h>
#include <math.h>
#include <stdint.h>

// ---------------------------------------------------------------------------
// TCNAttentionBlock. R5: energy + av also on HMMA bf16 split-pair.
// N=8, T=1024, E=512, H=8, D=64, P=16.
// ---------------------------------------------------------------------------

#define NB   8
#define TT   1024
#define EE   512
#define HH   8
#define DD   64
#define PP   16
#define LP   1040            // TT + PP
#define LPAD 1088            // attn row padded (17 chunks of 64)
#define KPAD 1152            // K rows padded (9 tiles of 128)
#define SOFTMAX_SCALE 0.044194173824159216f   // 1/sqrt(512)

// ------------------------------ scratch -----------------------------------
__device__ float g_v  [NB * LP * HH * DD];                 // fp32 (n,l,h,d)
__device__ float g_att[(size_t)NB * HH * TT * LP];         // fp32 energies
__device__ float g_ctx[NB * TT * EE];
__device__ float g_h  [NB * TT * EE];
__device__ float g_t1 [NB * TT * EE];
__device__ float g_t2 [NB * TT * EE];

// bf16 split operands
__device__ __nv_bfloat16 g_qh [64 * TT * DD];              // [ng][q][64]
__device__ __nv_bfloat16 g_ql [64 * TT * DD];
__device__ __nv_bfloat16 g_kh [64 * KPAD * DD];            // [ng][l][64]
__device__ __nv_bfloat16 g_kl [64 * KPAD * DD];
__device__ __nv_bfloat16 g_vTh[64 * DD * LPAD];            // [ng][d][1088]
__device__ __nv_bfloat16 g_vTl[64 * DD * LPAD];
__device__ __nv_bfloat16 g_ah [(size_t)64 * TT * LPAD];    // attn hi [ng][q][1088]
__device__ __nv_bfloat16 g_al [(size_t)64 * TT * LPAD];    // attn lo

// preconverted bf16 split weights, layout [chunk][co(512)][64]
__device__ __nv_bfloat16 g_WoHi[8  * 512 * 64];
__device__ __nv_bfloat16 g_WoLo[8  * 512 * 64];
__device__ __nv_bfloat16 g_c1Hi[24 * 512 * 64];
__device__ __nv_bfloat16 g_c1Lo[24 * 512 * 64];
__device__ __nv_bfloat16 g_c2Hi[24 * 512 * 64];
__device__ __nv_bfloat16 g_c2Lo[24 * 512 * 64];

// ---------------------------- PTX helpers ----------------------------------
__device__ __forceinline__ uint32_t smem_u32(const void* p) {
    uint32_t a;
    asm("{ .reg .u64 t; cvta.to.shared.u64 t, %1; cvt.u32.u64 %0, t; }"
        : "=r"(a) : "l"(p));
    return a;
}
#define SWZ(o) ((o) ^ (((o) >> 3) & 0x70))

__device__ __forceinline__ void ldsm4(uint32_t* r, uint32_t addr) {
    asm volatile("ldmatrix.sync.aligned.m8n8.x4.shared.b16 {%0,%1,%2,%3}, [%4];"
                 : "=r"(r[0]), "=r"(r[1]), "=r"(r[2]), "=r"(r[3]) : "r"(addr));
}
__device__ __forceinline__ void mma16816(float* c, const uint32_t* a, const uint32_t* b) {
    asm volatile(
        "mma.sync.aligned.m16n8k16.row.col.f32.bf16.bf16.f32 "
        "{%0,%1,%2,%3}, {%4,%5,%6,%7}, {%8,%9}, {%0,%1,%2,%3};"
        : "+f"(c[0]), "+f"(c[1]), "+f"(c[2]), "+f"(c[3])
        : "r"(a[0]), "r"(a[1]), "r"(a[2]), "r"(a[3]), "r"(b[0]), "r"(b[1]));
}
__device__ __forceinline__ void cpasync16(uint32_t saddr, const void* g) {
    asm volatile("cp.async.cg.shared.global [%0], [%1], 16;" :: "r"(saddr), "l"(g));
}
__device__ __forceinline__ void cp_commit() {
    asm volatile("cp.async.commit_group;" ::: "memory");
}
__device__ __forceinline__ void cp_wait0() {
    asm volatile("cp.async.wait_group 0;" ::: "memory");
}
__device__ __forceinline__ void cp_wait1() {
    asm volatile("cp.async.wait_group 1;" ::: "memory");
}
__device__ __forceinline__ uint32_t pack_bf2(__nv_bfloat16 a, __nv_bfloat16 b) {
    return (uint32_t)__bfloat16_as_ushort(a) | ((uint32_t)__bfloat16_as_ushort(b) << 16);
}

// ---------------------- weight preconversion -------------------------------
__global__ void conv_w_convert(const float* __restrict__ W,
                               __nv_bfloat16* __restrict__ hi,
                               __nv_bfloat16* __restrict__ lo) {
    int d = blockIdx.x * 256 + threadIdx.x;
    int c  = d >> 15;
    int co = (d >> 6) & 511;
    int ci = d & 63;
    int tap = c >> 3, cib = (c & 7) << 6;
    float v = W[(size_t)(co * 512 + cib + ci) * 3 + tap];
    __nv_bfloat16 h = __float2bfloat16(v);
    hi[d] = h;
    lo[d] = __float2bfloat16(v - __bfloat162float(h));
}
__global__ void wo_convert(const float* __restrict__ W,
                           __nv_bfloat16* __restrict__ hi,
                           __nv_bfloat16* __restrict__ lo) {
    int d = blockIdx.x * 256 + threadIdx.x;
    int c  = d >> 15;
    int co = (d >> 6) & 511;
    int ci = d & 63;
    float v = W[co * 512 + (c << 6) + ci];
    __nv_bfloat16 h = __float2bfloat16(v);
    hi[d] = h;
    lo[d] = __float2bfloat16(v - __bfloat162float(h));
}

// ---------------------- HMMA GEMM (outproj / conv) --------------------------
#define A_HI 0
#define A_LO 16384
#define B_HI 32768
#define B_LO 49152
#define BUF_STRIDE 65536
#define GEMM_SMEM (2 * BUF_STRIDE)

__global__ void __launch_bounds__(256) gemm_hmma_kernel(
    int mode, int nchunk,
    const float* __restrict__ IN,
    const __nv_bfloat16* __restrict__ BHg,
    const __nv_bfloat16* __restrict__ BLg,
    const float* __restrict__ bias,
    const float* __restrict__ resid,
    const int* __restrict__ seq_mask,
    float* __restrict__ OUT)
{
    extern __shared__ char smem[];
    const uint32_t sbase = smem_u32(smem);
    const int tid = threadIdx.x;
    const int lane = tid & 31, wid = tid >> 5;
    const int t0 = blockIdx.x * 128;
    const int co0 = blockIdx.y * 128;
    const int nBseq = t0 & ~1023;
    const int m0w = (wid & 1) * 64;
    const int n0w = (wid >> 1) * 32;

    float C[4][4][4];
    #pragma unroll
    for (int mt = 0; mt < 4; ++mt)
        #pragma unroll
        for (int nt = 0; nt < 4; ++nt)
            #pragma unroll
            for (int i = 0; i < 4; ++i) C[mt][nt][i] = 0.f;

    float4 areg[8];

    {
        int shift = (mode == 0) ? 0 : -2;
        #pragma unroll
        for (int it = 0; it < 8; ++it) {
            int lin = it * 1024 + tid * 4;
            int r = lin >> 6, ci = lin & 63;
            int grow = t0 + r + shift;
            areg[it] = make_float4(0.f, 0.f, 0.f, 0.f);
            if (grow >= nBseq)
                areg[it] = *(const float4*)(IN + (size_t)grow * 512 + ci);
        }
        char* bp = smem;
        #pragma unroll
        for (int it = 0; it < 8; ++it) {
            int lin = it * 1024 + tid * 4;
            int r = lin >> 6, ci = lin & 63;
            float4 v = areg[it];
            __nv_bfloat16 h0 = __float2bfloat16(v.x), h1 = __float2bfloat16(v.y);
            __nv_bfloat16 h2 = __float2bfloat16(v.z), h3 = __float2bfloat16(v.w);
            __nv_bfloat16 l0 = __float2bfloat16(v.x - __bfloat162float(h0));
            __nv_bfloat16 l1 = __float2bfloat16(v.y - __bfloat162float(h1));
            __nv_bfloat16 l2 = __float2bfloat16(v.z - __bfloat162float(h2));
            __nv_bfloat16 l3 = __float2bfloat16(v.w - __bfloat162float(h3));
            uint32_t off = SWZ((uint32_t)(r * 128 + ci * 2));
            *(uint2*)(bp + A_HI + off) = make_uint2(pack_bf2(h0, h1), pack_bf2(h2, h3));
            *(uint2*)(bp + A_LO + off) = make_uint2(pack_bf2(l0, l1), pack_bf2(l2, l3));
        }
        #pragma unroll
        for (int it = 0; it < 4; ++it) {
            int s = it * 256 + tid;
            int r = s >> 3, cb = s & 7;
            size_t gb = ((size_t)(co0 + r)) * 64 + cb * 8;
            uint32_t off = SWZ((uint32_t)(r * 128 + cb * 16));
            cpasync16(sbase + B_HI + off, BHg + gb);
            cpasync16(sbase + B_LO + off, BLg + gb);
        }
        cp_commit();
    }

    for (int c = 0; c < nchunk; ++c) {
        cp_wait0();
        __syncthreads();
        const bool hn = (c + 1 < nchunk);
        const int nb = (c + 1) & 1;

        if (hn) {
            int cn = c + 1;
            int shift, cib;
            if (mode == 0) { shift = 0; cib = cn << 6; }
            else           { shift = (cn >> 3) - 2; cib = (cn & 7) << 6; }
            #pragma unroll
            for (int it = 0; it < 8; ++it) {
                int lin = it * 1024 + tid * 4;
                int r = lin >> 6, ci = lin & 63;
                int grow = t0 + r + shift;
                areg[it] = make_float4(0.f, 0.f, 0.f, 0.f);
                if (grow >= nBseq)
                    areg[it] = *(const float4*)(IN + (size_t)grow * 512 + cib + ci);
            }
            uint32_t bb = sbase + nb * BUF_STRIDE;
            #pragma unroll
            for (int it = 0; it < 4; ++it) {
                int s = it * 256 + tid;
                int r = s >> 3, cb = s & 7;
                size_t gb = ((size_t)cn * 512 + co0 + r) * 64 + cb * 8;
                uint32_t off = SWZ((uint32_t)(r * 128 + cb * 16));
                cpasync16(bb + B_HI + off, BHg + gb);
                cpasync16(bb + B_LO + off, BLg + gb);
            }
            cp_commit();
        }

        const uint32_t Ab = sbase + (c & 1) * BUF_STRIDE;
        #pragma unroll
        for (int ks = 0; ks < 4; ++ks) {
            uint32_t ah[4][4], al[4][4];
            #pragma unroll
            for (int mt = 0; mt < 4; ++mt) {
                uint32_t off = SWZ((uint32_t)((m0w + mt * 16 + (lane & 15)) * 128
                                              + ks * 32 + (lane >> 4) * 16));
                ldsm4(ah[mt], Ab + A_HI + off);
                ldsm4(al[mt], Ab + A_LO + off);
            }
            uint32_t bh[8], bl[8];
            #pragma unroll
            for (int p = 0; p < 2; ++p) {
                uint32_t off = SWZ((uint32_t)((n0w + p * 16 + (lane & 7) + ((lane >> 4) & 1) * 8) * 128
                                              + ks * 32 + ((lane >> 3) & 1) * 16));
                ldsm4(&bh[p * 4], Ab + B_HI + off);
                ldsm4(&bl[p * 4], Ab + B_LO + off);
            }
            #pragma unroll
            for (int mt = 0; mt < 4; ++mt)
                #pragma unroll
                for (int nt = 0; nt < 4; ++nt) {
                    const uint32_t* bhp = &bh[(nt >> 1) * 4 + (nt & 1) * 2];
                    const uint32_t* blp = &bl[(nt >> 1) * 4 + (nt & 1) * 2];
                    mma16816(C[mt][nt], ah[mt], bhp);
                    mma16816(C[mt][nt], ah[mt], blp);
                    mma16816(C[mt][nt], al[mt], bhp);
                }
        }

        if (hn) {
            char* bp = smem + nb * BUF_STRIDE;
            #pragma unroll
            for (int it = 0; it < 8; ++it) {
                int lin = it * 1024 + tid * 4;
                int r = lin >> 6, ci = lin & 63;
                float4 v = areg[it];
                __nv_bfloat16 h0 = __float2bfloat16(v.x), h1 = __float2bfloat16(v.y);
                __nv_bfloat16 h2 = __float2bfloat16(v.z), h3 = __float2bfloat16(v.w);
                __nv_bfloat16 l0 = __float2bfloat16(v.x - __bfloat162float(h0));
                __nv_bfloat16 l1 = __float2bfloat16(v.y - __bfloat162float(h1));
                __nv_bfloat16 l2 = __float2bfloat16(v.z - __bfloat162float(h2));
                __nv_bfloat16 l3 = __float2bfloat16(v.w - __bfloat162float(h3));
                uint32_t off = SWZ((uint32_t)(r * 128 + ci * 2));
                *(uint2*)(bp + A_HI + off) = make_uint2(pack_bf2(h0, h1), pack_bf2(h2, h3));
                *(uint2*)(bp + A_LO + off) = make_uint2(pack_bf2(l0, l1), pack_bf2(l2, l3));
            }
        }
    }

    #pragma unroll
    for (int mt = 0; mt < 4; ++mt) {
        int rb = t0 + m0w + mt * 16 + (lane >> 2);
        #pragma unroll
        for (int nt = 0; nt < 4; ++nt) {
            int col = co0 + n0w + nt * 8 + (lane & 3) * 2;
            float b0 = bias[col], b1 = bias[col + 1];
            #pragma unroll
            for (int hf = 0; hf < 2; ++hf) {
                int r = rb + hf * 8;
                float y0 = C[mt][nt][hf * 2 + 0] + b0;
                float y1 = C[mt][nt][hf * 2 + 1] + b1;
                if (mode == 0) {
                    const float2 rs = *(const float2*)(resid + (size_t)r * 512 + col);
                    y0 += rs.x; y1 += rs.y;
                } else {
                    float valid = (float)seq_mask[r];
                    y0 = fmaxf(y0 * valid, 0.f);
                    y1 = fmaxf(y1 * valid, 0.f);
                    if (mode == 2) {
                        const float2 rs = *(const float2*)(resid + (size_t)r * 512 + col);
                        y0 = fmaxf(y0 + rs.x, 0.f);
                        y1 = fmaxf(y1 + rs.y, 0.f);
                    }
                }
                *(float2*)(OUT + (size_t)r * 512 + col) = make_float2(y0, y1);
            }
        }
    }
}

// ------------------------------ QKV projection -----------------------------
// writes q,k as bf16 hi/lo; v fp32 (n,l,h,d).
__global__ void qkv_kernel(const float* __restrict__ x,
                           const float* __restrict__ Wq,
                           const float* __restrict__ Wk,
                           const float* __restrict__ Wv) {
    __shared__ float xs[32][65];
    __shared__ float Wt[64][65];
    const int rbase = blockIdx.x * 32;
    const int tid = threadIdx.x;

    #pragma unroll
    for (int l = 0; l < 8; l++) {
        int idx = tid + l * 256;
        int r = idx >> 6, c = idx & 63;
        xs[r][c] = x[(size_t)(rbase + r) * 64 + c];
    }

    const int i  = tid & 63;
    const int rg = tid >> 6;

    for (int m = 0; m < 3; m++) {
        const float* Wm = (m == 0) ? Wq : (m == 1) ? Wk : Wv;
        #pragma unroll
        for (int l = 0; l < 16; l++) {
            int idx = tid + l * 256;
            int wi = idx >> 6, wj = idx & 63;
            Wt[wj][wi] = Wm[idx];
        }
        __syncthreads();

        float acc[8];
        #pragma unroll
        for (int rr = 0; rr < 8; rr++) acc[rr] = 0.f;
        #pragma unroll
        for (int j = 0; j < 64; j++) {
            float w = Wt[j][i];
            #pragma unroll
            for (int rr = 0; rr < 8; rr++)
                acc[rr] += xs[rg * 8 + rr][j] * w;
        }
        #pragma unroll
        for (int rr = 0; rr < 8; rr++) {
            int row = rbase + rg * 8 + rr;
            int n = row >> 13;
            int t = (row >> 3) & 1023;
            int h = row & 7;
            int ng = n * 8 + h;
            if (m == 2) {
                size_t o = (((size_t)(n * LP + t) * HH + h) << 6) + i;
                g_v[o] = acc[rr];
            } else {
                float v = acc[rr];
                __nv_bfloat16 hi = __float2bfloat16(v);
                __nv_bfloat16 lo = __float2bfloat16(v - __bfloat162float(hi));
                if (m == 0) {
                    size_t o = ((size_t)ng * TT + t) * 64 + i;
                    g_qh[o] = hi; g_ql[o] = lo;
                } else {
                    size_t o = ((size_t)ng * KPAD + t) * 64 + i;
                    g_kh[o] = hi; g_kl[o] = lo;
                }
            }
        }
        __syncthreads();
    }
}

// -------------------- persistent kv slots + k padding ----------------------
__global__ void persist_kernel(const float* __restrict__ pk,
                               const float* __restrict__ pv) {
    int idx = blockIdx.x * 256 + threadIdx.x;       // 65536
    if (idx >= NB * PP * HH * DD) return;
    int d = idx & 63, h = (idx >> 6) & 7, p = (idx >> 9) & 15, n = idx >> 13;
    int src = ((p * HH + h) << 6) + d;
    // pv -> g_v fp32
    g_v[(((size_t)(n * LP + TT + p) * HH + h) << 6) + d] = pv[src];
    // pk -> g_kh/g_kl
    float v = pk[src];
    __nv_bfloat16 hi = __float2bfloat16(v);
    __nv_bfloat16 lo = __float2bfloat16(v - __bfloat162float(hi));
    size_t o = ((size_t)(n * 8 + h) * KPAD + TT + p) * 64 + d;
    g_kh[o] = hi; g_kl[o] = lo;
}

__global__ void kpad_kernel() {
    int idx = blockIdx.x * 256 + threadIdx.x;       // 64*112*64 = 458752
    if (idx >= 64 * 112 * 64) return;
    int d = idx & 63;
    int l = LP + ((idx >> 6) % 112);
    int ng = idx / (112 * 64);
    size_t o = ((size_t)ng * KPAD + l) * 64 + d;
    g_kh[o] = __float2bfloat16(0.f);
    g_kl[o] = __float2bfloat16(0.f);
}

// -------------------- V transpose -> bf16 hi/lo [ng][d][1088] ---------------
__global__ void vt_convert_kernel() {
    __shared__ float ts[64][65];
    const int lt = blockIdx.x;          // 0..16
    const int ng = blockIdx.y;          // 0..63
    const int n = ng >> 3, h = ng & 7;
    const int tid = threadIdx.x;

    for (int idx = tid; idx < 4096; idx += 256) {
        int lloc = idx >> 6, d = idx & 63;
        int l = lt * 64 + lloc;
        float v = 0.f;
        if (l < LP) v = g_v[(((size_t)(n * LP + l)) * HH + h) * 64 + d];
        ts[lloc][d] = v;
    }
    __syncthreads();
    for (int idx = tid; idx < 4096; idx += 256) {
        int d = idx >> 6, lloc = idx & 63;
        float v = ts[lloc][d];
        __nv_bfloat16 hi = __float2bfloat16(v);
        __nv_bfloat16 lo = __float2bfloat16(v - __bfloat162float(hi));
        size_t o = ((size_t)ng * 64 + d) * LPAD + lt * 64 + lloc;
        g_vTh[o] = hi; g_vTl[o] = lo;
    }
}

// -------------------- energy: Q@K^T + ALiBi (HMMA) --------------------------
#define EGY_SMEM 65536
__global__ void __launch_bounds__(256) energy_hmma_kernel() {
    extern __shared__ char smem[];
    const uint32_t sbase = smem_u32(smem);
    const int tid = threadIdx.x;
    const int lane = tid & 31, wid = tid >> 5;
    const int qt = blockIdx.x;          // 8
    const int kt = blockIdx.y;          // 9
    const int ng = blockIdx.z;          // 64
    const int m0w = (wid & 1) * 64;
    const int n0w = (wid >> 1) * 32;

    // load tiles: A = Q[128][64] hi/lo, B = K[128][64] hi/lo (all bf16)
    #pragma unroll
    for (int it = 0; it < 4; ++it) {
        int s = it * 256 + tid;         // 0..1023
        int r = s >> 3, cb = s & 7;
        uint32_t off = SWZ((uint32_t)(r * 128 + cb * 16));
        size_t qa = ((size_t)ng * TT + qt * 128 + r) * 64 + cb * 8;
        size_t ka = ((size_t)ng * KPAD + kt * 128 + r) * 64 + cb * 8;
        cpasync16(sbase + A_HI + off, g_qh + qa);
        cpasync16(sbase + A_LO + off, g_ql + qa);
        cpasync16(sbase + B_HI + off, g_kh + ka);
        cpasync16(sbase + B_LO + off, g_kl + ka);
    }
    cp_commit();

    float C[4][4][4];
    #pragma unroll
    for (int mt = 0; mt < 4; ++mt)
        #pragma unroll
        for (int nt = 0; nt < 4; ++nt)
            #pragma unroll
            for (int i = 0; i < 4; ++i) C[mt][nt][i] = 0.f;

    cp_wait0();
    __syncthreads();

    #pragma unroll
    for (int ks = 0; ks < 4; ++ks) {
        uint32_t ah[4][4], al[4][4];
        #pragma unroll
        for (int mt = 0; mt < 4; ++mt) {
            uint32_t off = SWZ((uint32_t)((m0w + mt * 16 + (lane & 15)) * 128
                                          + ks * 32 + (lane >> 4) * 16));
            ldsm4(ah[mt], sbase + A_HI + off);
            ldsm4(al[mt], sbase + A_LO + off);
        }
        uint32_t bh[8], bl[8];
        #pragma unroll
        for (int p = 0; p < 2; ++p) {
            uint32_t off = SWZ((uint32_t)((n0w + p * 16 + (lane & 7) + ((lane >> 4) & 1) * 8) * 128
                                          + ks * 32 + ((lane >> 3) & 1) * 16));
            ldsm4(&bh[p * 4], sbase + B_HI + off);
            ldsm4(&bl[p * 4], sbase + B_LO + off);
        }
        #pragma unroll
        for (int mt = 0; mt < 4; ++mt)
            #pragma unroll
            for (int nt = 0; nt < 4; ++nt) {
                const uint32_t* bhp = &bh[(nt >> 1) * 4 + (nt & 1) * 2];
                const uint32_t* blp = &bl[(nt >> 1) * 4 + (nt & 1) * 2];
                mma16816(C[mt][nt], ah[mt], bhp);
                mma16816(C[mt][nt], ah[mt], blp);
                mma16816(C[mt][nt], al[mt], bhp);
            }
    }

    const float slope = exp2f(-(float)((ng & 7) + 1));
    #pragma unroll
    for (int mt = 0; mt < 4; ++mt) {
        int qb = qt * 128 + m0w + mt * 16 + (lane >> 2);
        #pragma unroll
        for (int nt = 0; nt < 4; ++nt) {
            int k0 = kt * 128 + n0w + nt * 8 + (lane & 3) * 2;
            if (k0 >= LP) continue;
            #pragma unroll
            for (int hf = 0; hf < 2; ++hf) {
                int q = qb + hf * 8;
                float e0 = C[mt][nt][hf * 2 + 0];
                float e1 = C[mt][nt][hf * 2 + 1];
                if (k0 < TT) {
                    e0 -= fabsf((float)(q - k0)) * slope;
                    e1 -= fabsf((float)(q - k0 - 1)) * slope;
                }
                *(float2*)(g_att + ((size_t)(ng * TT + q)) * LP + k0) = make_float2(e0, e1);
            }
        }
    }
}

// ------------- pre-mix -> mask -> softmax -> post-mix (fused) ---------------
__global__ void __launch_bounds__(256, 3) softmax_kernel(
                               const float* __restrict__ pre,
                               const float* __restrict__ post,
                               const int* __restrict__ seq_mask) {
    __shared__ float sm[8][LP];
    __shared__ float ps_pre[64];
    __shared__ float ps_post[64];
    const int nq = blockIdx.x;
    const int n = nq >> 10, q = nq & 1023;
    const int tid = threadIdx.x;

    if (tid < 64) { ps_pre[tid] = pre[tid]; ps_post[tid] = post[tid]; }

    for (int idx = tid; idx < 8 * LP; idx += 256) {
        int h = idx / LP, kk = idx - h * LP;
        sm[h][kk] = g_att[((size_t)((n * 8 + h) * TT + q)) * LP + kk];
    }
    __syncthreads();

    for (int kk = tid; kk < LP; kk += 256) {
        float a[8];
        #pragma unroll
        for (int h = 0; h < 8; h++) a[h] = sm[h][kk];
        bool masked = (kk < TT) && (seq_mask[n * TT + kk] == 0);
        #pragma unroll
        for (int g = 0; g < 8; g++) {
            float o = 0.f;
            #pragma unroll
            for (int h = 0; h < 8; h++) o += ps_pre[g * 8 + h] * a[h];
            sm[g][kk] = masked ? -1e4f : o;
        }
    }
    __syncthreads();

    const int w = tid >> 5, lane = tid & 31;
    float mx = -1e30f;
    for (int kk = lane; kk < LP; kk += 32) {
        float v = sm[w][kk] * SOFTMAX_SCALE;
        sm[w][kk] = v;
        mx = fmaxf(mx, v);
    }
    #pragma unroll
    for (int o = 16; o; o >>= 1) mx = fmaxf(mx, __shfl_xor_sync(0xffffffffu, mx, o));
    float s = 0.f;
    for (int kk = lane; kk < LP; kk += 32) {
        float p = __expf(sm[w][kk] - mx);
        sm[w][kk] = p;
        s += p;
    }
    #pragma unroll
    for (int o = 16; o; o >>= 1) s += __shfl_xor_sync(0xffffffffu, s, o);
    float inv = 1.f / s;
    for (int kk = lane; kk < LP; kk += 32) sm[w][kk] *= inv;
    __syncthreads();

    // post-mix -> bf16 hi/lo (row stride LPAD, zero pad beyond LP)
    const __nv_bfloat16 z = __float2bfloat16(0.f);
    for (int kk = tid; kk < LPAD; kk += 256) {
        if (kk < LP) {
            float a[8];
            #pragma unroll
            for (int h = 0; h < 8; h++) a[h] = sm[h][kk];
            #pragma unroll
            for (int g = 0; g < 8; g++) {
                float o = 0.f;
                #pragma unroll
                for (int h = 0; h < 8; h++) o += ps_post[g * 8 + h] * a[h];
                __nv_bfloat16 hi = __float2bfloat16(o);
                __nv_bfloat16 lo = __float2bfloat16(o - __bfloat162float(hi));
                size_t idx = ((size_t)((n * 8 + g) * TT + q)) * LPAD + kk;
                g_ah[idx] = hi; g_al[idx] = lo;
            }
        } else {
            #pragma unroll
            for (int g = 0; g < 8; g++) {
                size_t idx = ((size_t)((n * 8 + g) * TT + q)) * LPAD + kk;
                g_ah[idx] = z; g_al[idx] = z;
            }
        }
    }
}

// ------------------------- attn @ V (HMMA) ----------------------------------
// C[128 q][64 d] per (qt, ng). K = 1088 over 17 chunks of 64.
#define V_AHI 0
#define V_ALO 16384
#define V_BHI 32768
#define V_BLO 40960
#define V_BUF 49152
#define AV_SMEM (2 * V_BUF)

__global__ void __launch_bounds__(256) av_hmma_kernel() {
    extern __shared__ char smem[];
    const uint32_t sbase = smem_u32(smem);
    const int tid = threadIdx.x;
    const int lane = tid & 31, wid = tid >> 5;
    const int qt = blockIdx.x;          // 8
    const int ng = blockIdx.y;          // 64
    const int m0w = (wid & 3) * 32;
    const int n0w = (wid >> 2) * 32;

    float C[2][4][4];
    #pragma unroll
    for (int mt = 0; mt < 2; ++mt)
        #pragma unroll
        for (int nt = 0; nt < 4; ++nt)
            #pragma unroll
            for (int i = 0; i < 4; ++i) C[mt][nt][i] = 0.f;

    // chunk loader
    auto load_chunk = [&](int c, uint32_t bb) {
        // A: 128 rows x 8 segs, hi+lo -> 2048 ops / 256 thr = 8
        #pragma unroll
        for (int it = 0; it < 4; ++it) {
            int s = it * 256 + tid;
            int r = s >> 3, cb = s & 7;
            size_t ga = ((size_t)ng * TT + qt * 128 + r) * LPAD + c * 64 + cb * 8;
            uint32_t off = SWZ((uint32_t)(r * 128 + cb * 16));
            cpasync16(bb + V_AHI + off, g_ah + ga);
            cpasync16(bb + V_ALO + off, g_al + ga);
        }
        // B: 64 rows x 8 segs, hi+lo -> 1024 / 256 = 4
        #pragma unroll
        for (int it = 0; it < 2; ++it) {
            int s = it * 256 + tid;
            int r = s >> 3, cb = s & 7;
            size_t gb = ((size_t)ng * 64 + r) * LPAD + c * 64 + cb * 8;
            uint32_t off = SWZ((uint32_t)(r * 128 + cb * 16));
            cpasync16(bb + V_BHI + off, g_vTh + gb);
            cpasync16(bb + V_BLO + off, g_vTl + gb);
        }
        cp_commit();
    };

    load_chunk(0, sbase);

    for (int c = 0; c < 17; ++c) {
        const bool hn = (c + 1 < 17);
        if (hn) load_chunk(c + 1, sbase + ((c + 1) & 1) * V_BUF);
        if (hn) cp_wait1(); else cp_wait0();
        __syncthreads();

        const uint32_t Ab = sbase + (c & 1) * V_BUF;
        #pragma unroll
        for (int ks = 0; ks < 4; ++ks) {
            uint32_t ah[2][4], al[2][4];
            #pragma unroll
            for (int mt = 0; mt < 2; ++mt) {
                uint32_t off = SWZ((uint32_t)((m0w + mt * 16 + (lane & 15)) * 128
                                              + ks * 32 + (lane >> 4) * 16));
                ldsm4(ah[mt], Ab + V_AHI + off);
                ldsm4(al[mt], Ab + V_ALO + off);
            }
            uint32_t bh[8], bl[8];
            #pragma unroll
            for (int p = 0; p < 2; ++p) {
                uint32_t off = SWZ((uint32_t)((n0w + p * 16 + (lane & 7) + ((lane >> 4) & 1) * 8) * 128
                                              + ks * 32 + ((lane >> 3) & 1) * 16));
                ldsm4(&bh[p * 4], Ab + V_BHI + off);
                ldsm4(&bl[p * 4], Ab + V_BLO + off);
            }
            #pragma unroll
            for (int mt = 0; mt < 2; ++mt)
                #pragma unroll
                for (int nt = 0; nt < 4; ++nt) {
                    const uint32_t* bhp = &bh[(nt >> 1) * 4 + (nt & 1) * 2];
                    const uint32_t* blp = &bl[(nt >> 1) * 4 + (nt & 1) * 2];
                    mma16816(C[mt][nt], ah[mt], bhp);
                    mma16816(C[mt][nt], ah[mt], blp);
                    mma16816(C[mt][nt], al[mt], bhp);
                }
        }
        __syncthreads();
    }

    const int n = ng >> 3, h = ng & 7;
    #pragma unroll
    for (int mt = 0; mt < 2; ++mt) {
        int qb = qt * 128 + m0w + mt * 16 + (lane >> 2);
        #pragma unroll
        for (int nt = 0; nt < 4; ++nt) {
            int dcol = n0w + nt * 8 + (lane & 3) * 2;
            #pragma unroll
            for (int hf = 0; hf < 2; ++hf) {
                int q = qb + hf * 8;
                size_t o = ((size_t)(n * TT + q)) * 512 + h * 64 + dcol;
                *(float2*)(g_ctx + o) = make_float2(C[mt][nt][hf * 2 + 0],
                                                    C[mt][nt][hf * 2 + 1]);
            }
        }
    }
}

// ------------------------------ LayerNorm ----------------------------------
__global__ void ln_kernel(const float* __restrict__ gamma,
                          const float* __restrict__ beta,
                          float* __restrict__ out) {
    const int r = blockIdx.x;
    const int tid = threadIdx.x;
    const float* in = g_t2 + (size_t)r * EE;
    __shared__ float red[8];

    float v0 = in[tid], v1 = in[tid + 256];
    float s = v0 + v1;
    #pragma unroll
    for (int o = 16; o; o >>= 1) s += __shfl_xor_sync(0xffffffffu, s, o);
    if ((tid & 31) == 0) red[tid >> 5] = s;
    __syncthreads();
    float tot = 0.f;
    #pragma unroll
    for (int i = 0; i < 8; i++) tot += red[i];
    float mu = tot * (1.f / EE);
    __syncthreads();

    float d0 = v0 - mu, d1 = v1 - mu;
    float vs = d0 * d0 + d1 * d1;
    #pragma unroll
    for (int o = 16; o; o >>= 1) vs += __shfl_xor_sync(0xffffffffu, vs, o);
    if ((tid & 31) == 0) red[tid >> 5] = vs;
    __syncthreads();
    float vtot = 0.f;
    #pragma unroll
    for (int i = 0; i < 8; i++) vtot += red[i];
    float inv = rsqrtf(vtot * (1.f / EE) + 1e-5f);

    out[(size_t)r * EE + tid]       = d0 * inv * gamma[tid]       + beta[tid];
    out[(size_t)r * EE + tid + 256] = d1 * inv * gamma[tid + 256] + beta[tid + 256];
}

// ------------------------------ launcher -----------------------------------
extern "C" void kernel_launch(void* const* d_in, const int* in_sizes, int n_in,
                              void* d_out, int out_size) {
    const float* x        = (const float*)d_in[0];
    const int*   seq_mask = (const int*)  d_in[1];
    const float* Wq       = (const float*)d_in[2];
    const float* Wk       = (const float*)d_in[3];
    const float* Wv       = (const float*)d_in[4];
    const float* Wo       = (const float*)d_in[5];
    const float* bo       = (const float*)d_in[6];
    const float* pre_th   = (const float*)d_in[7];
    const float* post_th  = (const float*)d_in[8];
    const float* pk       = (const float*)d_in[9];
    const float* pv       = (const float*)d_in[10];
    const float* c1W      = (const float*)d_in[11];
    const float* c1b      = (const float*)d_in[12];
    const float* c2W      = (const float*)d_in[13];
    const float* c2b      = (const float*)d_in[14];
    const float* ln_g     = (const float*)d_in[15];
    const float* ln_b     = (const float*)d_in[16];
    float* out = (float*)d_out;

    __nv_bfloat16 *pWoHi, *pWoLo, *pC1Hi, *pC1Lo, *pC2Hi, *pC2Lo;
    cudaGetSymbolAddress((void**)&pWoHi, g_WoHi);
    cudaGetSymbolAddress((void**)&pWoLo, g_WoLo);
    cudaGetSymbolAddress((void**)&pC1Hi, g_c1Hi);
    cudaGetSymbolAddress((void**)&pC1Lo, g_c1Lo);
    cudaGetSymbolAddress((void**)&pC2Hi, g_c2Hi);
    cudaGetSymbolAddress((void**)&pC2Lo, g_c2Lo);

    float *pCtx, *pH, *pT1, *pT2;
    cudaGetSymbolAddress((void**)&pCtx, g_ctx);
    cudaGetSymbolAddress((void**)&pH,   g_h);
    cudaGetSymbolAddress((void**)&pT1,  g_t1);
    cudaGetSymbolAddress((void**)&pT2,  g_t2);

    cudaFuncSetAttribute(gemm_hmma_kernel,
                         cudaFuncAttributeMaxDynamicSharedMemorySize, GEMM_SMEM);
    cudaFuncSetAttribute(energy_hmma_kernel,
                         cudaFuncAttributeMaxDynamicSharedMemorySize, EGY_SMEM);
    cudaFuncSetAttribute(av_hmma_kernel,
                         cudaFuncAttributeMaxDynamicSharedMemorySize, AV_SMEM);

    wo_convert<<<1024, 256>>>(Wo, pWoHi, pWoLo);
    conv_w_convert<<<3072, 256>>>(c1W, pC1Hi, pC1Lo);
    conv_w_convert<<<3072, 256>>>(c2W, pC2Hi, pC2Lo);

    qkv_kernel<<<2048, 256>>>(x, Wq, Wk, Wv);
    persist_kernel<<<256, 256>>>(pk, pv);
    kpad_kernel<<<1792, 256>>>();
    vt_convert_kernel<<<dim3(17, 64), 256>>>();

    energy_hmma_kernel<<<dim3(8, 9, 64), 256, EGY_SMEM>>>();
    softmax_kernel<<<8192, 256>>>(pre_th, post_th, seq_mask);
    av_hmma_kernel<<<dim3(8, 64), 256, AV_SMEM>>>();

    gemm_hmma_kernel<<<dim3(64, 4), 256, GEMM_SMEM>>>(
        0, 8, pCtx, pWoHi, pWoLo, bo, x, seq_mask, pH);
    gemm_hmma_kernel<<<dim3(64, 4), 256, GEMM_SMEM>>>(
        1, 24, pH, pC1Hi, pC1Lo, c1b, nullptr, seq_mask, pT1);
    gemm_hmma_kernel<<<dim3(64, 4), 256, GEMM_SMEM>>>(
        2, 24, pT1, pC2Hi, pC2Lo, c2b, pH, seq_mask, pT2);

    ln_kernel<<<8192, 256>>>(ln_g, ln_b, out);
}

// round 6
// speedup vs baseline: 2.8713x; 1.2076x over previous
#include <cuda_runtime.h>
#include <cuda_bf16.h>
#include <math.h>
#include <stdint.h>

// ---------------------------------------------------------------------------
// TCNAttentionBlock. R6: all GEMMs on tf32 mma.sync (single pass),
// streamlined softmax. N=8, T=1024, E=512, H=8, D=64, P=16.
// ---------------------------------------------------------------------------

#define NB   8
#define TT   1024
#define EE   512
#define HH   8
#define DD   64
#define PP   16
#define LP   1040            // TT + PP
#define LPAD 1088            // attn row padded (34 chunks of 32)
#define KPAD 1152            // K rows padded (9 tiles of 128)
#define SOFTMAX_SCALE 0.044194173824159216f   // 1/sqrt(512)

// ------------------------------ scratch -----------------------------------
__device__ float g_q  [64 * TT * DD];                      // tf32 [ng][q][64]
__device__ float g_k  [64 * KPAD * DD];                    // tf32 [ng][l][64]
__device__ float g_v  [NB * LP * HH * DD];                 // fp32 (n,l,h,d)
__device__ float g_vT [64 * DD * LPAD];                    // tf32 [ng][d][1088]
__device__ float g_att[(size_t)NB * HH * TT * LP];         // fp32 energies
__device__ float g_a  [(size_t)64 * TT * LPAD];            // tf32 attn
__device__ float g_ctx[NB * TT * EE];
__device__ float g_h  [NB * TT * EE];
__device__ float g_t1 [NB * TT * EE];
__device__ float g_t2 [NB * TT * EE];

// preconverted tf32 weights, layout [chunk][co(512)][32]
__device__ float g_Wo[16 * 512 * 32];
__device__ float g_c1[48 * 512 * 32];
__device__ float g_c2[48 * 512 * 32];

// ---------------------------- PTX helpers ----------------------------------
__device__ __forceinline__ uint32_t smem_u32(const void* p) {
    uint32_t a;
    asm("{ .reg .u64 t; cvta.to.shared.u64 t, %1; cvt.u32.u64 %0, t; }"
        : "=r"(a) : "l"(p));
    return a;
}
#define SWZ(o) ((o) ^ (((o) >> 3) & 0x70))

__device__ __forceinline__ uint32_t tf32r_u(float v) {
    uint32_t u;
    asm("cvt.rna.tf32.f32 %0, %1;" : "=r"(u) : "f"(v));
    return u;
}
__device__ __forceinline__ float tf32r(float v) {
    return __uint_as_float(tf32r_u(v));
}
__device__ __forceinline__ void ldsm4(uint32_t* r, uint32_t addr) {
    asm volatile("ldmatrix.sync.aligned.m8n8.x4.shared.b16 {%0,%1,%2,%3}, [%4];"
                 : "=r"(r[0]), "=r"(r[1]), "=r"(r[2]), "=r"(r[3]) : "r"(addr));
}
__device__ __forceinline__ void mma_tf32(float* c, const uint32_t* a, const uint32_t* b) {
    asm volatile(
        "mma.sync.aligned.m16n8k8.row.col.f32.tf32.tf32.f32 "
        "{%0,%1,%2,%3}, {%4,%5,%6,%7}, {%8,%9}, {%0,%1,%2,%3};"
        : "+f"(c[0]), "+f"(c[1]), "+f"(c[2]), "+f"(c[3])
        : "r"(a[0]), "r"(a[1]), "r"(a[2]), "r"(a[3]), "r"(b[0]), "r"(b[1]));
}
__device__ __forceinline__ void cpasync16(uint32_t saddr, const void* g) {
    asm volatile("cp.async.cg.shared.global [%0], [%1], 16;" :: "r"(saddr), "l"(g));
}
__device__ __forceinline__ void cp_commit() {
    asm volatile("cp.async.commit_group;" ::: "memory");
}
__device__ __forceinline__ void cp_wait0() {
    asm volatile("cp.async.wait_group 0;" ::: "memory");
}
__device__ __forceinline__ void cp_wait1() {
    asm volatile("cp.async.wait_group 1;" ::: "memory");
}

// ---------------------- weight preconversion -------------------------------
__global__ void conv_w_convert(const float* __restrict__ W, float* __restrict__ o) {
    int d = blockIdx.x * 256 + threadIdx.x;          // 48*512*32 = 786432
    int c  = d >> 14;
    int co = (d >> 5) & 511;
    int ci = d & 31;
    int tap = c >> 4, cib = (c & 15) << 5;
    o[d] = tf32r(W[(size_t)(co * 512 + cib + ci) * 3 + tap]);
}
__global__ void wo_convert(const float* __restrict__ W, float* __restrict__ o) {
    int d = blockIdx.x * 256 + threadIdx.x;          // 16*512*32 = 262144
    int c  = d >> 14;
    int co = (d >> 5) & 511;
    int ci = d & 31;
    o[d] = tf32r(W[co * 512 + (c << 5) + ci]);
}

// ---------------------- tf32 HMMA GEMM (outproj / conv) ---------------------
// C[t 128, co 128] = A[t,K] @ B[co,K]^T. K-chunk = 32.
// mode 0: outproj (16 chunks): OUT = acc + bias + resid
// mode 1: conv1   (48 chunks): OUT = relu((acc+bias)*valid)
// mode 2: conv2   (48 chunks): OUT = relu(relu((acc+bias)*valid) + resid)
#define G_A 0
#define G_B 16384
#define G_BUF 32768
#define GEMM_SMEM (2 * G_BUF)

__global__ void __launch_bounds__(256) gemm_hmma_kernel(
    int mode, int nchunk,
    const float* __restrict__ IN,
    const float* __restrict__ Bg,
    const float* __restrict__ bias,
    const float* __restrict__ resid,
    const int* __restrict__ seq_mask,
    float* __restrict__ OUT)
{
    extern __shared__ char smem[];
    const uint32_t sbase = smem_u32(smem);
    const int tid = threadIdx.x;
    const int lane = tid & 31, wid = tid >> 5;
    const int t0 = blockIdx.x * 128;
    const int co0 = blockIdx.y * 128;
    const int nBseq = t0 & ~1023;
    const int m0w = (wid & 1) * 64;
    const int n0w = (wid >> 1) * 32;

    float C[4][4][4];
    #pragma unroll
    for (int mt = 0; mt < 4; ++mt)
        #pragma unroll
        for (int nt = 0; nt < 4; ++nt)
            #pragma unroll
            for (int i = 0; i < 4; ++i) C[mt][nt][i] = 0.f;

    float4 areg[4];

    // prologue: chunk 0
    {
        int shift = (mode == 0) ? 0 : -2;
        #pragma unroll
        for (int it = 0; it < 4; ++it) {
            int lin = it * 1024 + tid * 4;
            int r = lin >> 5, ci = lin & 31;
            int grow = t0 + r + shift;
            areg[it] = make_float4(0.f, 0.f, 0.f, 0.f);
            if (grow >= nBseq)
                areg[it] = *(const float4*)(IN + (size_t)grow * 512 + ci);
        }
        char* bp = smem;
        #pragma unroll
        for (int it = 0; it < 4; ++it) {
            int lin = it * 1024 + tid * 4;
            int r = lin >> 5, ci = lin & 31;
            float4 v = areg[it];
            uint32_t off = SWZ((uint32_t)(r * 128 + ci * 4));
            *(uint4*)(bp + G_A + off) = make_uint4(tf32r_u(v.x), tf32r_u(v.y),
                                                   tf32r_u(v.z), tf32r_u(v.w));
        }
        #pragma unroll
        for (int it = 0; it < 4; ++it) {
            int s = it * 256 + tid;
            int r = s >> 3, cb = s & 7;
            size_t gb = ((size_t)(co0 + r) << 5) + cb * 4;
            cpasync16(sbase + G_B + SWZ((uint32_t)(r * 128 + cb * 16)), Bg + gb);
        }
        cp_commit();
    }

    for (int c = 0; c < nchunk; ++c) {
        cp_wait0();
        __syncthreads();
        const bool hn = (c + 1 < nchunk);
        const int nb = (c + 1) & 1;

        if (hn) {
            int cn = c + 1;
            int shift, cib;
            if (mode == 0) { shift = 0; cib = cn << 5; }
            else           { shift = (cn >> 4) - 2; cib = (cn & 15) << 5; }
            #pragma unroll
            for (int it = 0; it < 4; ++it) {
                int lin = it * 1024 + tid * 4;
                int r = lin >> 5, ci = lin & 31;
                int grow = t0 + r + shift;
                areg[it] = make_float4(0.f, 0.f, 0.f, 0.f);
                if (grow >= nBseq)
                    areg[it] = *(const float4*)(IN + (size_t)grow * 512 + cib + ci);
            }
            uint32_t bb = sbase + nb * G_BUF;
            #pragma unroll
            for (int it = 0; it < 4; ++it) {
                int s = it * 256 + tid;
                int r = s >> 3, cb = s & 7;
                size_t gb = ((size_t)(cn * 512 + co0 + r) << 5) + cb * 4;
                cpasync16(bb + G_B + SWZ((uint32_t)(r * 128 + cb * 16)), Bg + gb);
            }
            cp_commit();
        }

        const uint32_t Ab = sbase + (c & 1) * G_BUF;
        #pragma unroll
        for (int ks = 0; ks < 4; ++ks) {
            uint32_t a[4][4];
            #pragma unroll
            for (int mt = 0; mt < 4; ++mt) {
                uint32_t off = SWZ((uint32_t)((m0w + mt * 16 + (lane & 15)) * 128
                                              + ks * 32 + (lane >> 4) * 16));
                ldsm4(a[mt], Ab + G_A + off);
            }
            uint32_t b[8];
            #pragma unroll
            for (int p = 0; p < 2; ++p) {
                uint32_t off = SWZ((uint32_t)((n0w + p * 16 + (lane & 7) + ((lane >> 4) & 1) * 8) * 128
                                              + ks * 32 + ((lane >> 3) & 1) * 16));
                ldsm4(&b[p * 4], Ab + G_B + off);
            }
            #pragma unroll
            for (int mt = 0; mt < 4; ++mt)
                #pragma unroll
                for (int nt = 0; nt < 4; ++nt)
                    mma_tf32(C[mt][nt], a[mt], &b[(nt >> 1) * 4 + (nt & 1) * 2]);
        }

        if (hn) {
            char* bp = smem + nb * G_BUF;
            #pragma unroll
            for (int it = 0; it < 4; ++it) {
                int lin = it * 1024 + tid * 4;
                int r = lin >> 5, ci = lin & 31;
                float4 v = areg[it];
                uint32_t off = SWZ((uint32_t)(r * 128 + ci * 4));
                *(uint4*)(bp + G_A + off) = make_uint4(tf32r_u(v.x), tf32r_u(v.y),
                                                       tf32r_u(v.z), tf32r_u(v.w));
            }
        }
    }

    #pragma unroll
    for (int mt = 0; mt < 4; ++mt) {
        int rb = t0 + m0w + mt * 16 + (lane >> 2);
        #pragma unroll
        for (int nt = 0; nt < 4; ++nt) {
            int col = co0 + n0w + nt * 8 + (lane & 3) * 2;
            float b0 = bias[col], b1 = bias[col + 1];
            #pragma unroll
            for (int hf = 0; hf < 2; ++hf) {
                int r = rb + hf * 8;
                float y0 = C[mt][nt][hf * 2 + 0] + b0;
                float y1 = C[mt][nt][hf * 2 + 1] + b1;
                if (mode == 0) {
                    const float2 rs = *(const float2*)(resid + (size_t)r * 512 + col);
                    y0 += rs.x; y1 += rs.y;
                } else {
                    float valid = (float)seq_mask[r];
                    y0 = fmaxf(y0 * valid, 0.f);
                    y1 = fmaxf(y1 * valid, 0.f);
                    if (mode == 2) {
                        const float2 rs = *(const float2*)(resid + (size_t)r * 512 + col);
                        y0 = fmaxf(y0 + rs.x, 0.f);
                        y1 = fmaxf(y1 + rs.y, 0.f);
                    }
                }
                *(float2*)(OUT + (size_t)r * 512 + col) = make_float2(y0, y1);
            }
        }
    }
}

// ------------------------------ QKV projection -----------------------------
// blockIdx.y selects matrix (0=q tf32, 1=k tf32, 2=v fp32)
__global__ void qkv_kernel(const float* __restrict__ x,
                           const float* __restrict__ Wq,
                           const float* __restrict__ Wk,
                           const float* __restrict__ Wv) {
    __shared__ float xs[32][65];
    __shared__ float Wt[64][65];
    const int rbase = blockIdx.x * 32;
    const int m = blockIdx.y;
    const float* Wm = (m == 0) ? Wq : (m == 1) ? Wk : Wv;
    const int tid = threadIdx.x;

    #pragma unroll
    for (int l = 0; l < 8; l++) {
        int idx = tid + l * 256;
        int r = idx >> 6, c = idx & 63;
        xs[r][c] = x[(size_t)(rbase + r) * 64 + c];
    }
    #pragma unroll
    for (int l = 0; l < 16; l++) {
        int idx = tid + l * 256;
        int wi = idx >> 6, wj = idx & 63;
        Wt[wj][wi] = Wm[idx];
    }
    __syncthreads();

    const int i  = tid & 63;
    const int rg = tid >> 6;

    float acc[8];
    #pragma unroll
    for (int rr = 0; rr < 8; rr++) acc[rr] = 0.f;
    #pragma unroll
    for (int j = 0; j < 64; j++) {
        float w = Wt[j][i];
        #pragma unroll
        for (int rr = 0; rr < 8; rr++)
            acc[rr] += xs[rg * 8 + rr][j] * w;
    }
    #pragma unroll
    for (int rr = 0; rr < 8; rr++) {
        int row = rbase + rg * 8 + rr;
        int n = row >> 13;
        int t = (row >> 3) & 1023;
        int h = row & 7;
        int ng = n * 8 + h;
        if (m == 0) {
            g_q[((size_t)ng * TT + t) * 64 + i] = tf32r(acc[rr]);
        } else if (m == 1) {
            g_k[((size_t)ng * KPAD + t) * 64 + i] = tf32r(acc[rr]);
        } else {
            g_v[(((size_t)(n * LP + t) * HH + h) << 6) + i] = acc[rr];
        }
    }
}

// -------------------- persistent kv slots + k padding ----------------------
__global__ void persist_kernel(const float* __restrict__ pk,
                               const float* __restrict__ pv) {
    int idx = blockIdx.x * 256 + threadIdx.x;
    if (idx >= NB * PP * HH * DD) return;
    int d = idx & 63, h = (idx >> 6) & 7, p = (idx >> 9) & 15, n = idx >> 13;
    int src = ((p * HH + h) << 6) + d;
    g_v[(((size_t)(n * LP + TT + p) * HH + h) << 6) + d] = pv[src];
    g_k[((size_t)(n * 8 + h) * KPAD + TT + p) * 64 + d] = tf32r(pk[src]);
}

__global__ void kpad_kernel() {
    int idx = blockIdx.x * 256 + threadIdx.x;       // 64*112*64
    if (idx >= 64 * 112 * 64) return;
    int d = idx & 63;
    int l = LP + ((idx >> 6) % 112);
    int ng = idx / (112 * 64);
    g_k[((size_t)ng * KPAD + l) * 64 + d] = 0.f;
}

// -------------------- V transpose -> tf32 [ng][d][1088] ---------------------
__global__ void vt_convert_kernel() {
    __shared__ float ts[64][65];
    const int lt = blockIdx.x;          // 0..16
    const int ng = blockIdx.y;          // 0..63
    const int n = ng >> 3, h = ng & 7;
    const int tid = threadIdx.x;

    for (int idx = tid; idx < 4096; idx += 256) {
        int lloc = idx >> 6, d = idx & 63;
        int l = lt * 64 + lloc;
        float v = 0.f;
        if (l < LP) v = g_v[(((size_t)(n * LP + l)) * HH + h) * 64 + d];
        ts[lloc][d] = v;
    }
    __syncthreads();
    for (int idx = tid; idx < 4096; idx += 256) {
        int d = idx >> 6, lloc = idx & 63;
        g_vT[((size_t)ng * 64 + d) * LPAD + lt * 64 + lloc] = tf32r(ts[lloc][d]);
    }
}

// -------------------- energy: Q@K^T + ALiBi (tf32 HMMA) --------------------
#define E_A0 0
#define E_B0 32768
#define EGY_SMEM 65536
__global__ void __launch_bounds__(256) energy_hmma_kernel() {
    extern __shared__ char smem[];
    const uint32_t sbase = smem_u32(smem);
    const int tid = threadIdx.x;
    const int lane = tid & 31, wid = tid >> 5;
    const int qt = blockIdx.x;          // 8
    const int kt = blockIdx.y;          // 9
    const int ng = blockIdx.z;          // 64
    const int m0w = (wid & 1) * 64;
    const int n0w = (wid >> 1) * 32;

    #pragma unroll
    for (int panel = 0; panel < 2; ++panel) {
        #pragma unroll
        for (int it = 0; it < 4; ++it) {
            int s = it * 256 + tid;
            int r = s >> 3, cb = s & 7;
            uint32_t off = SWZ((uint32_t)(r * 128 + cb * 16)) + panel * 16384;
            size_t qa = ((size_t)ng * TT + qt * 128 + r) * 64 + panel * 32 + cb * 4;
            size_t ka = ((size_t)ng * KPAD + kt * 128 + r) * 64 + panel * 32 + cb * 4;
            cpasync16(sbase + E_A0 + off, g_q + qa);
            cpasync16(sbase + E_B0 + off, g_k + ka);
        }
    }
    cp_commit();

    float C[4][4][4];
    #pragma unroll
    for (int mt = 0; mt < 4; ++mt)
        #pragma unroll
        for (int nt = 0; nt < 4; ++nt)
            #pragma unroll
            for (int i = 0; i < 4; ++i) C[mt][nt][i] = 0.f;

    cp_wait0();
    __syncthreads();

    #pragma unroll
    for (int panel = 0; panel < 2; ++panel) {
        #pragma unroll
        for (int ks = 0; ks < 4; ++ks) {
            uint32_t a[4][4];
            #pragma unroll
            for (int mt = 0; mt < 4; ++mt) {
                uint32_t off = SWZ((uint32_t)((m0w + mt * 16 + (lane & 15)) * 128
                                              + ks * 32 + (lane >> 4) * 16)) + panel * 16384;
                ldsm4(a[mt], sbase + E_A0 + off);
            }
            uint32_t b[8];
            #pragma unroll
            for (int p = 0; p < 2; ++p) {
                uint32_t off = SWZ((uint32_t)((n0w + p * 16 + (lane & 7) + ((lane >> 4) & 1) * 8) * 128
                                              + ks * 32 + ((lane >> 3) & 1) * 16)) + panel * 16384;
                ldsm4(&b[p * 4], sbase + E_B0 + off);
            }
            #pragma unroll
            for (int mt = 0; mt < 4; ++mt)
                #pragma unroll
                for (int nt = 0; nt < 4; ++nt)
                    mma_tf32(C[mt][nt], a[mt], &b[(nt >> 1) * 4 + (nt & 1) * 2]);
        }
    }

    const float slope = exp2f(-(float)((ng & 7) + 1));
    #pragma unroll
    for (int mt = 0; mt < 4; ++mt) {
        int qb = qt * 128 + m0w + mt * 16 + (lane >> 2);
        #pragma unroll
        for (int nt = 0; nt < 4; ++nt) {
            int k0 = kt * 128 + n0w + nt * 8 + (lane & 3) * 2;
            if (k0 >= LP) continue;
            #pragma unroll
            for (int hf = 0; hf < 2; ++hf) {
                int q = qb + hf * 8;
                float e0 = C[mt][nt][hf * 2 + 0];
                float e1 = C[mt][nt][hf * 2 + 1];
                if (k0 < TT) {
                    e0 -= fabsf((float)(q - k0)) * slope;
                    e1 -= fabsf((float)(q - k0 - 1)) * slope;
                }
                *(float2*)(g_att + ((size_t)(ng * TT + q)) * LP + k0) = make_float2(e0, e1);
            }
        }
    }
}

// ------------- pre-mix -> mask -> softmax -> post-mix (fused) ---------------
__global__ void __launch_bounds__(256, 3) softmax_kernel(
                               const float* __restrict__ pre,
                               const float* __restrict__ post,
                               const int* __restrict__ seq_mask) {
    __shared__ float sm[8][LP];
    __shared__ float ps_pre[64];
    __shared__ float ps_post[64];
    __shared__ float inv_s[8];
    const int nq = blockIdx.x;
    const int n = nq >> 10, q = nq & 1023;
    const int tid = threadIdx.x;

    if (tid < 64) { ps_pre[tid] = pre[tid]; ps_post[tid] = post[tid]; }

    // load 8 head-rows (float4)
    for (int i4 = tid; i4 < 8 * (LP / 4); i4 += 256) {
        int h = i4 / (LP / 4), kk4 = (i4 - h * (LP / 4)) * 4;
        float4 v = *(const float4*)(g_att + ((size_t)((n * 8 + h) * TT + q)) * LP + kk4);
        *(float4*)&sm[h][kk4] = v;
    }
    __syncthreads();

    // pre-mix + mask + scale (vectorized, in place)
    for (int kk0 = tid * 4; kk0 < LP; kk0 += 1024) {
        float4 a[8];
        #pragma unroll
        for (int h = 0; h < 8; h++) a[h] = *(const float4*)&sm[h][kk0];
        int4 msk = make_int4(1, 1, 1, 1);
        if (kk0 < TT) msk = *(const int4*)(seq_mask + n * TT + kk0);
        #pragma unroll
        for (int g = 0; g < 8; g++) {
            float4 o = make_float4(0.f, 0.f, 0.f, 0.f);
            #pragma unroll
            for (int h = 0; h < 8; h++) {
                float w = ps_pre[g * 8 + h];
                o.x += w * a[h].x; o.y += w * a[h].y;
                o.z += w * a[h].z; o.w += w * a[h].w;
            }
            o.x = msk.x ? o.x * SOFTMAX_SCALE : -442.f;
            o.y = msk.y ? o.y * SOFTMAX_SCALE : -442.f;
            o.z = msk.z ? o.z * SOFTMAX_SCALE : -442.f;
            o.w = msk.w ? o.w * SOFTMAX_SCALE : -442.f;
            *(float4*)&sm[g][kk0] = o;
        }
    }
    __syncthreads();

    // warp w: row max + exp + sum (no normalize pass; 1/s saved to shared)
    const int w = tid >> 5, lane = tid & 31;
    float mx = -1e30f;
    for (int kk = lane; kk < LP; kk += 32) mx = fmaxf(mx, sm[w][kk]);
    #pragma unroll
    for (int o = 16; o; o >>= 1) mx = fmaxf(mx, __shfl_xor_sync(0xffffffffu, mx, o));
    float s = 0.f;
    for (int kk = lane; kk < LP; kk += 32) {
        float p = __expf(sm[w][kk] - mx);
        sm[w][kk] = p;
        s += p;
    }
    #pragma unroll
    for (int o = 16; o; o >>= 1) s += __shfl_xor_sync(0xffffffffu, s, o);
    if (lane == 0) inv_s[w] = 1.f / s;
    __syncthreads();

    // post-mix (fold 1/s) -> tf32 attn, zero pad
    float inv[8];
    #pragma unroll
    for (int h = 0; h < 8; h++) inv[h] = inv_s[h];
    for (int kk0 = tid * 4; kk0 < LPAD; kk0 += 1024) {
        float4 a[8];
        if (kk0 < LP) {
            #pragma unroll
            for (int h = 0; h < 8; h++) {
                a[h] = *(const float4*)&sm[h][kk0];
                a[h].x *= inv[h]; a[h].y *= inv[h];
                a[h].z *= inv[h]; a[h].w *= inv[h];
            }
        } else {
            #pragma unroll
            for (int h = 0; h < 8; h++) a[h] = make_float4(0.f, 0.f, 0.f, 0.f);
        }
        #pragma unroll
        for (int g = 0; g < 8; g++) {
            float4 o = make_float4(0.f, 0.f, 0.f, 0.f);
            #pragma unroll
            for (int h = 0; h < 8; h++) {
                float wgt = ps_post[g * 8 + h];
                o.x += wgt * a[h].x; o.y += wgt * a[h].y;
                o.z += wgt * a[h].z; o.w += wgt * a[h].w;
            }
            o.x = tf32r(o.x); o.y = tf32r(o.y);
            o.z = tf32r(o.z); o.w = tf32r(o.w);
            *(float4*)(g_a + ((size_t)((n * 8 + g) * TT + q)) * LPAD + kk0) = o;
        }
    }
}

// ------------------------- attn @ V (tf32 HMMA) -----------------------------
#define V_A 0
#define V_B 16384
#define V_BUF 24576
#define AV_SMEM (2 * V_BUF)

__global__ void __launch_bounds__(256) av_hmma_kernel() {
    extern __shared__ char smem[];
    const uint32_t sbase = smem_u32(smem);
    const int tid = threadIdx.x;
    const int lane = tid & 31, wid = tid >> 5;
    const int qt = blockIdx.x;          // 8
    const int ng = blockIdx.y;          // 64
    const int m0w = (wid & 3) * 32;
    const int n0w = (wid >> 2) * 32;

    float C[2][4][4];
    #pragma unroll
    for (int mt = 0; mt < 2; ++mt)
        #pragma unroll
        for (int nt = 0; nt < 4; ++nt)
            #pragma unroll
            for (int i = 0; i < 4; ++i) C[mt][nt][i] = 0.f;

    auto load_chunk = [&](int c, uint32_t bb) {
        #pragma unroll
        for (int it = 0; it < 4; ++it) {
            int s = it * 256 + tid;
            int r = s >> 3, cb = s & 7;
            size_t ga = ((size_t)ng * TT + qt * 128 + r) * LPAD + c * 32 + cb * 4;
            cpasync16(bb + V_A + SWZ((uint32_t)(r * 128 + cb * 16)), g_a + ga);
        }
        #pragma unroll
        for (int it = 0; it < 2; ++it) {
            int s = it * 256 + tid;
            int r = s >> 3, cb = s & 7;
            size_t gb = ((size_t)ng * 64 + r) * LPAD + c * 32 + cb * 4;
            cpasync16(bb + V_B + SWZ((uint32_t)(r * 128 + cb * 16)), g_vT + gb);
        }
        cp_commit();
    };

    load_chunk(0, sbase);

    for (int c = 0; c < 34; ++c) {
        const bool hn = (c + 1 < 34);
        if (hn) load_chunk(c + 1, sbase + ((c + 1) & 1) * V_BUF);
        if (hn) cp_wait1(); else cp_wait0();
        __syncthreads();

        const uint32_t Ab = sbase + (c & 1) * V_BUF;
        #pragma unroll
        for (int ks = 0; ks < 4; ++ks) {
            uint32_t a[2][4];
            #pragma unroll
            for (int mt = 0; mt < 2; ++mt) {
                uint32_t off = SWZ((uint32_t)((m0w + mt * 16 + (lane & 15)) * 128
                                              + ks * 32 + (lane >> 4) * 16));
                ldsm4(a[mt], Ab + V_A + off);
            }
            uint32_t b[8];
            #pragma unroll
            for (int p = 0; p < 2; ++p) {
                uint32_t off = SWZ((uint32_t)((n0w + p * 16 + (lane & 7) + ((lane >> 4) & 1) * 8) * 128
                                              + ks * 32 + ((lane >> 3) & 1) * 16));
                ldsm4(&b[p * 4], Ab + V_B + off);
            }
            #pragma unroll
            for (int mt = 0; mt < 2; ++mt)
                #pragma unroll
                for (int nt = 0; nt < 4; ++nt)
                    mma_tf32(C[mt][nt], a[mt], &b[(nt >> 1) * 4 + (nt & 1) * 2]);
        }
        __syncthreads();
    }

    const int n = ng >> 3, h = ng & 7;
    #pragma unroll
    for (int mt = 0; mt < 2; ++mt) {
        int qb = qt * 128 + m0w + mt * 16 + (lane >> 2);
        #pragma unroll
        for (int nt = 0; nt < 4; ++nt) {
            int dcol = n0w + nt * 8 + (lane & 3) * 2;
            #pragma unroll
            for (int hf = 0; hf < 2; ++hf) {
                int q = qb + hf * 8;
                size_t o = ((size_t)(n * TT + q)) * 512 + h * 64 + dcol;
                *(float2*)(g_ctx + o) = make_float2(C[mt][nt][hf * 2 + 0],
                                                    C[mt][nt][hf * 2 + 1]);
            }
        }
    }
}

// ------------------------------ LayerNorm ----------------------------------
__global__ void ln_kernel(const float* __restrict__ gamma,
                          const float* __restrict__ beta,
                          float* __restrict__ out) {
    const int r = blockIdx.x;
    const int tid = threadIdx.x;
    const float* in = g_t2 + (size_t)r * EE;
    __shared__ float red[8];

    float v0 = in[tid], v1 = in[tid + 256];
    float s = v0 + v1;
    #pragma unroll
    for (int o = 16; o; o >>= 1) s += __shfl_xor_sync(0xffffffffu, s, o);
    if ((tid & 31) == 0) red[tid >> 5] = s;
    __syncthreads();
    float tot = 0.f;
    #pragma unroll
    for (int i = 0; i < 8; i++) tot += red[i];
    float mu = tot * (1.f / EE);
    __syncthreads();

    float d0 = v0 - mu, d1 = v1 - mu;
    float vs = d0 * d0 + d1 * d1;
    #pragma unroll
    for (int o = 16; o; o >>= 1) vs += __shfl_xor_sync(0xffffffffu, vs, o);
    if ((tid & 31) == 0) red[tid >> 5] = vs;
    __syncthreads();
    float vtot = 0.f;
    #pragma unroll
    for (int i = 0; i < 8; i++) vtot += red[i];
    float inv = rsqrtf(vtot * (1.f / EE) + 1e-5f);

    out[(size_t)r * EE + tid]       = d0 * inv * gamma[tid]       + beta[tid];
    out[(size_t)r * EE + tid + 256] = d1 * inv * gamma[tid + 256] + beta[tid + 256];
}

// ------------------------------ launcher -----------------------------------
extern "C" void kernel_launch(void* const* d_in, const int* in_sizes, int n_in,
                              void* d_out, int out_size) {
    const float* x        = (const float*)d_in[0];
    const int*   seq_mask = (const int*)  d_in[1];
    const float* Wq       = (const float*)d_in[2];
    const float* Wk       = (const float*)d_in[3];
    const float* Wv       = (const float*)d_in[4];
    const float* Wo       = (const float*)d_in[5];
    const float* bo       = (const float*)d_in[6];
    const float* pre_th   = (const float*)d_in[7];
    const float* post_th  = (const float*)d_in[8];
    const float* pk       = (const float*)d_in[9];
    const float* pv       = (const float*)d_in[10];
    const float* c1W      = (const float*)d_in[11];
    const float* c1b      = (const float*)d_in[12];
    const float* c2W      = (const float*)d_in[13];
    const float* c2b      = (const float*)d_in[14];
    const float* ln_g     = (const float*)d_in[15];
    const float* ln_b     = (const float*)d_in[16];
    float* out = (float*)d_out;

    float *pWo, *pC1, *pC2, *pCtx, *pH, *pT1, *pT2;
    cudaGetSymbolAddress((void**)&pWo,  g_Wo);
    cudaGetSymbolAddress((void**)&pC1,  g_c1);
    cudaGetSymbolAddress((void**)&pC2,  g_c2);
    cudaGetSymbolAddress((void**)&pCtx, g_ctx);
    cudaGetSymbolAddress((void**)&pH,   g_h);
    cudaGetSymbolAddress((void**)&pT1,  g_t1);
    cudaGetSymbolAddress((void**)&pT2,  g_t2);

    cudaFuncSetAttribute(gemm_hmma_kernel,
                         cudaFuncAttributeMaxDynamicSharedMemorySize, GEMM_SMEM);
    cudaFuncSetAttribute(energy_hmma_kernel,
                         cudaFuncAttributeMaxDynamicSharedMemorySize, EGY_SMEM);
    cudaFuncSetAttribute(av_hmma_kernel,
                         cudaFuncAttributeMaxDynamicSharedMemorySize, AV_SMEM);

    wo_convert<<<1024, 256>>>(Wo, pWo);
    conv_w_convert<<<3072, 256>>>(c1W, pC1);
    conv_w_convert<<<3072, 256>>>(c2W, pC2);

    qkv_kernel<<<dim3(2048, 3), 256>>>(x, Wq, Wk, Wv);
    persist_kernel<<<256, 256>>>(pk, pv);
    kpad_kernel<<<1792, 256>>>();
    vt_convert_kernel<<<dim3(17, 64), 256>>>();

    energy_hmma_kernel<<<dim3(8, 9, 64), 256, EGY_SMEM>>>();
    softmax_kernel<<<8192, 256>>>(pre_th, post_th, seq_mask);
    av_hmma_kernel<<<dim3(8, 64), 256, AV_SMEM>>>();

    gemm_hmma_kernel<<<dim3(64, 4), 256, GEMM_SMEM>>>(
        0, 16, pCtx, pWo, bo, x, seq_mask, pH);
    gemm_hmma_kernel<<<dim3(64, 4), 256, GEMM_SMEM>>>(
        1, 48, pH, pC1, c1b, nullptr, seq_mask, pT1);
    gemm_hmma_kernel<<<dim3(64, 4), 256, GEMM_SMEM>>>(
        2, 48, pT1, pC2, c2b, pH, seq_mask, pT2);

    ln_kernel<<<8192, 256>>>(ln_g, ln_b, out);
}

// round 8
// speedup vs baseline: 3.2634x; 1.1365x over previous
#include <cuda_runtime.h>
#include <cuda_bf16.h>
#include <math.h>
#include <stdint.h>

// ---------------------------------------------------------------------------
// TCNAttentionBlock. R8 = R7 resubmit (infra failure, no signal):
// qkv on tf32 HMMA; gemm A-operands pre-rounded to tf32 by producers ->
// pure cp.async GEMM pipeline. N=8, T=1024, E=512, H=8, D=64, P=16.
// ---------------------------------------------------------------------------

#define NB   8
#define TT   1024
#define EE   512
#define HH   8
#define DD   64
#define PP   16
#define LP   1040            // TT + PP
#define LPAD 1088            // attn row padded (34 chunks of 32)
#define KPAD 1152            // K rows padded (9 tiles of 128)
#define SOFTMAX_SCALE 0.044194173824159216f   // 1/sqrt(512)

// ------------------------------ scratch -----------------------------------
__device__ float g_q  [64 * TT * DD];                      // tf32 [ng][q][64]
__device__ float g_k  [64 * KPAD * DD];                    // tf32 [ng][l][64]
__device__ float g_v  [NB * LP * HH * DD];                 // fp32 (n,l,h,d)
__device__ float g_vT [64 * DD * LPAD];                    // tf32 [ng][d][1088]
__device__ float g_att[(size_t)NB * HH * TT * LP];         // fp32 energies
__device__ float g_a  [(size_t)64 * TT * LPAD];            // tf32 attn
__device__ float g_ctx[NB * TT * EE];                      // tf32
__device__ float g_h  [NB * TT * EE];                      // tf32
__device__ float g_t1 [NB * TT * EE];                      // tf32
__device__ float g_t2 [NB * TT * EE];                      // fp32

// preconverted tf32 weights, layout [chunk][co(512)][32]
__device__ float g_Wo[16 * 512 * 32];
__device__ float g_c1[48 * 512 * 32];
__device__ float g_c2[48 * 512 * 32];

// ---------------------------- PTX helpers ----------------------------------
__device__ __forceinline__ uint32_t smem_u32(const void* p) {
    uint32_t a;
    asm("{ .reg .u64 t; cvta.to.shared.u64 t, %1; cvt.u32.u64 %0, t; }"
        : "=r"(a) : "l"(p));
    return a;
}
#define SWZ(o) ((o) ^ (((o) >> 3) & 0x70))

__device__ __forceinline__ uint32_t tf32r_u(float v) {
    uint32_t u;
    asm("cvt.rna.tf32.f32 %0, %1;" : "=r"(u) : "f"(v));
    return u;
}
__device__ __forceinline__ float tf32r(float v) {
    return __uint_as_float(tf32r_u(v));
}
__device__ __forceinline__ void ldsm4(uint32_t* r, uint32_t addr) {
    asm volatile("ldmatrix.sync.aligned.m8n8.x4.shared.b16 {%0,%1,%2,%3}, [%4];"
                 : "=r"(r[0]), "=r"(r[1]), "=r"(r[2]), "=r"(r[3]) : "r"(addr));
}
__device__ __forceinline__ void mma_tf32(float* c, const uint32_t* a, const uint32_t* b) {
    asm volatile(
        "mma.sync.aligned.m16n8k8.row.col.f32.tf32.tf32.f32 "
        "{%0,%1,%2,%3}, {%4,%5,%6,%7}, {%8,%9}, {%0,%1,%2,%3};"
        : "+f"(c[0]), "+f"(c[1]), "+f"(c[2]), "+f"(c[3])
        : "r"(a[0]), "r"(a[1]), "r"(a[2]), "r"(a[3]), "r"(b[0]), "r"(b[1]));
}
__device__ __forceinline__ void cpasync16(uint32_t saddr, const void* g) {
    asm volatile("cp.async.cg.shared.global [%0], [%1], 16;" :: "r"(saddr), "l"(g));
}
__device__ __forceinline__ void cpasync16z(uint32_t saddr, const void* g, int sz) {
    asm volatile("cp.async.cg.shared.global [%0], [%1], 16, %2;"
                 :: "r"(saddr), "l"(g), "r"(sz));
}
__device__ __forceinline__ void cp_commit() {
    asm volatile("cp.async.commit_group;" ::: "memory");
}
__device__ __forceinline__ void cp_wait0() {
    asm volatile("cp.async.wait_group 0;" ::: "memory");
}
__device__ __forceinline__ void cp_wait1() {
    asm volatile("cp.async.wait_group 1;" ::: "memory");
}

// ---------------------- weight preconversion -------------------------------
__global__ void conv_w_convert(const float* __restrict__ W, float* __restrict__ o) {
    int d = blockIdx.x * 256 + threadIdx.x;          // 48*512*32
    int c  = d >> 14;
    int co = (d >> 5) & 511;
    int ci = d & 31;
    int tap = c >> 4, cib = (c & 15) << 5;
    o[d] = tf32r(W[(size_t)(co * 512 + cib + ci) * 3 + tap]);
}
__global__ void wo_convert(const float* __restrict__ W, float* __restrict__ o) {
    int d = blockIdx.x * 256 + threadIdx.x;          // 16*512*32
    int c  = d >> 14;
    int co = (d >> 5) & 511;
    int ci = d & 31;
    o[d] = tf32r(W[co * 512 + (c << 5) + ci]);
}

// ------------------------ QKV on tf32 HMMA ----------------------------------
// grid (64 t-tiles, 8 heads). A = x[t,h*64..], B = Wq/Wk/Wv 64x64.
#define QKV_B0 32768
#define QKV_SMEM (32768 + 3 * 16384)
__global__ void __launch_bounds__(256) qkv_hmma_kernel(
    const float* __restrict__ x,
    const float* __restrict__ Wq,
    const float* __restrict__ Wk,
    const float* __restrict__ Wv)
{
    extern __shared__ char smem[];
    const uint32_t sbase = smem_u32(smem);
    const int tid = threadIdx.x;
    const int lane = tid & 31, wid = tid >> 5;
    const int t0 = blockIdx.x * 128;
    const int h  = blockIdx.y;
    const int n  = t0 >> 10;
    const int ng = n * 8 + h;
    const int m0w = (wid & 3) * 32;
    const int n0w = (wid >> 2) * 32;

    // A: 128x64 tf32 (2 panels of 128x32)
    #pragma unroll
    for (int it = 0; it < 8; ++it) {
        int lin = it * 1024 + tid * 4;
        int r = lin >> 6, ci = lin & 63;
        float4 v = *(const float4*)(x + (size_t)(t0 + r) * 512 + h * 64 + ci);
        uint32_t off = (ci >> 5) * 16384 + SWZ((uint32_t)(r * 128 + (ci & 31) * 4));
        *(uint4*)(smem + off) = make_uint4(tf32r_u(v.x), tf32r_u(v.y),
                                           tf32r_u(v.z), tf32r_u(v.w));
    }
    // B: 3 matrices 64x64 tf32 (2 panels of 64x32 each)
    #pragma unroll
    for (int m = 0; m < 3; ++m) {
        const float* Wm = (m == 0) ? Wq : (m == 1) ? Wk : Wv;
        #pragma unroll
        for (int it = 0; it < 4; ++it) {
            int lin = it * 1024 + tid * 4;
            int r = lin >> 6, ci = lin & 63;
            float4 v = *(const float4*)(Wm + r * 64 + ci);
            uint32_t off = QKV_B0 + m * 16384 + (ci >> 5) * 8192
                         + SWZ((uint32_t)(r * 128 + (ci & 31) * 4));
            *(uint4*)(smem + off) = make_uint4(tf32r_u(v.x), tf32r_u(v.y),
                                               tf32r_u(v.z), tf32r_u(v.w));
        }
    }
    __syncthreads();

    for (int m = 0; m < 3; ++m) {
        float C[2][4][4];
        #pragma unroll
        for (int mt = 0; mt < 2; ++mt)
            #pragma unroll
            for (int nt = 0; nt < 4; ++nt)
                #pragma unroll
                for (int i = 0; i < 4; ++i) C[mt][nt][i] = 0.f;

        const uint32_t bbase = sbase + QKV_B0 + m * 16384;
        #pragma unroll
        for (int panel = 0; panel < 2; ++panel) {
            #pragma unroll
            for (int ks = 0; ks < 4; ++ks) {
                uint32_t a[2][4];
                #pragma unroll
                for (int mt = 0; mt < 2; ++mt) {
                    uint32_t off = panel * 16384
                        + SWZ((uint32_t)((m0w + mt * 16 + (lane & 15)) * 128
                                         + ks * 32 + (lane >> 4) * 16));
                    ldsm4(a[mt], sbase + off);
                }
                uint32_t b[8];
                #pragma unroll
                for (int p = 0; p < 2; ++p) {
                    uint32_t off = panel * 8192
                        + SWZ((uint32_t)((n0w + p * 16 + (lane & 7) + ((lane >> 4) & 1) * 8) * 128
                                         + ks * 32 + ((lane >> 3) & 1) * 16));
                    ldsm4(&b[p * 4], bbase + off);
                }
                #pragma unroll
                for (int mt = 0; mt < 2; ++mt)
                    #pragma unroll
                    for (int nt = 0; nt < 4; ++nt)
                        mma_tf32(C[mt][nt], a[mt], &b[(nt >> 1) * 4 + (nt & 1) * 2]);
            }
        }

        #pragma unroll
        for (int mt = 0; mt < 2; ++mt) {
            int tb = t0 + m0w + mt * 16 + (lane >> 2);
            #pragma unroll
            for (int nt = 0; nt < 4; ++nt) {
                int col = n0w + nt * 8 + (lane & 3) * 2;
                #pragma unroll
                for (int hf = 0; hf < 2; ++hf) {
                    int ts = (tb + hf * 8) & 1023;
                    float y0 = C[mt][nt][hf * 2 + 0];
                    float y1 = C[mt][nt][hf * 2 + 1];
                    if (m == 0) {
                        size_t o = ((size_t)ng * TT + ts) * 64 + col;
                        *(float2*)(g_q + o) = make_float2(tf32r(y0), tf32r(y1));
                    } else if (m == 1) {
                        size_t o = ((size_t)ng * KPAD + ts) * 64 + col;
                        *(float2*)(g_k + o) = make_float2(tf32r(y0), tf32r(y1));
                    } else {
                        size_t o = (((size_t)(n * LP + ts) * HH + h) << 6) + col;
                        *(float2*)(g_v + o) = make_float2(y0, y1);
                    }
                }
            }
        }
    }
}

// ---------------------- tf32 HMMA GEMM (outproj / conv) ---------------------
// IN is already tf32-rounded in memory -> cp.async both operands.
// mode 0: outproj (16 chunks): OUT = acc + bias + resid            (tf32 out)
// mode 1: conv1   (48 chunks): OUT = relu((acc+bias)*valid)        (tf32 out)
// mode 2: conv2   (48 chunks): OUT = relu(relu((acc+bias)*valid)+resid) (fp32)
#define G_A 0
#define G_B 16384
#define G_BUF 32768
#define GEMM_SMEM (2 * G_BUF)

__global__ void __launch_bounds__(256, 2) gemm_hmma_kernel(
    int mode, int nchunk,
    const float* __restrict__ IN,
    const float* __restrict__ Bg,
    const float* __restrict__ bias,
    const float* __restrict__ resid,
    const int* __restrict__ seq_mask,
    float* __restrict__ OUT)
{
    extern __shared__ char smem[];
    const uint32_t sbase = smem_u32(smem);
    const int tid = threadIdx.x;
    const int lane = tid & 31, wid = tid >> 5;
    const int t0 = blockIdx.x * 128;
    const int co0 = blockIdx.y * 128;
    const int nBseq = t0 & ~1023;
    const int m0w = (wid & 1) * 64;
    const int n0w = (wid >> 1) * 32;

    float C[4][4][4];
    #pragma unroll
    for (int mt = 0; mt < 4; ++mt)
        #pragma unroll
        for (int nt = 0; nt < 4; ++nt)
            #pragma unroll
            for (int i = 0; i < 4; ++i) C[mt][nt][i] = 0.f;

    auto load_chunk = [&](int c, uint32_t bb) {
        int shift, cib;
        if (mode == 0) { shift = 0; cib = c << 5; }
        else           { shift = (c >> 4) - 2; cib = (c & 15) << 5; }
        #pragma unroll
        for (int it = 0; it < 4; ++it) {
            int s = it * 256 + tid;
            int r = s >> 3, cb = s & 7;
            int grow = t0 + r + shift;
            int ok = (grow >= nBseq);
            int ga = ok ? grow : nBseq;
            cpasync16z(bb + G_A + SWZ((uint32_t)(r * 128 + cb * 16)),
                       IN + (size_t)ga * 512 + cib + cb * 4, ok ? 16 : 0);
        }
        #pragma unroll
        for (int it = 0; it < 4; ++it) {
            int s = it * 256 + tid;
            int r = s >> 3, cb = s & 7;
            size_t gb = ((size_t)(c * 512 + co0 + r) << 5) + cb * 4;
            cpasync16(bb + G_B + SWZ((uint32_t)(r * 128 + cb * 16)), Bg + gb);
        }
        cp_commit();
    };

    load_chunk(0, sbase);

    for (int c = 0; c < nchunk; ++c) {
        const bool hn = (c + 1 < nchunk);
        if (hn) load_chunk(c + 1, sbase + ((c + 1) & 1) * G_BUF);
        if (hn) cp_wait1(); else cp_wait0();
        __syncthreads();

        const uint32_t Ab = sbase + (c & 1) * G_BUF;
        #pragma unroll
        for (int ks = 0; ks < 4; ++ks) {
            uint32_t a[4][4];
            #pragma unroll
            for (int mt = 0; mt < 4; ++mt) {
                uint32_t off = SWZ((uint32_t)((m0w + mt * 16 + (lane & 15)) * 128
                                              + ks * 32 + (lane >> 4) * 16));
                ldsm4(a[mt], Ab + G_A + off);
            }
            uint32_t b[8];
            #pragma unroll
            for (int p = 0; p < 2; ++p) {
                uint32_t off = SWZ((uint32_t)((n0w + p * 16 + (lane & 7) + ((lane >> 4) & 1) * 8) * 128
                                              + ks * 32 + ((lane >> 3) & 1) * 16));
                ldsm4(&b[p * 4], Ab + G_B + off);
            }
            #pragma unroll
            for (int mt = 0; mt < 4; ++mt)
                #pragma unroll
                for (int nt = 0; nt < 4; ++nt)
                    mma_tf32(C[mt][nt], a[mt], &b[(nt >> 1) * 4 + (nt & 1) * 2]);
        }
        __syncthreads();
    }

    #pragma unroll
    for (int mt = 0; mt < 4; ++mt) {
        int rb = t0 + m0w + mt * 16 + (lane >> 2);
        #pragma unroll
        for (int nt = 0; nt < 4; ++nt) {
            int col = co0 + n0w + nt * 8 + (lane & 3) * 2;
            float b0 = bias[col], b1 = bias[col + 1];
            #pragma unroll
            for (int hf = 0; hf < 2; ++hf) {
                int r = rb + hf * 8;
                float y0 = C[mt][nt][hf * 2 + 0] + b0;
                float y1 = C[mt][nt][hf * 2 + 1] + b1;
                if (mode == 0) {
                    const float2 rs = *(const float2*)(resid + (size_t)r * 512 + col);
                    y0 = tf32r(y0 + rs.x);
                    y1 = tf32r(y1 + rs.y);
                } else {
                    float valid = (float)seq_mask[r];
                    y0 = fmaxf(y0 * valid, 0.f);
                    y1 = fmaxf(y1 * valid, 0.f);
                    if (mode == 2) {
                        const float2 rs = *(const float2*)(resid + (size_t)r * 512 + col);
                        y0 = fmaxf(y0 + rs.x, 0.f);
                        y1 = fmaxf(y1 + rs.y, 0.f);
                    } else {
                        y0 = tf32r(y0);
                        y1 = tf32r(y1);
                    }
                }
                *(float2*)(OUT + (size_t)r * 512 + col) = make_float2(y0, y1);
            }
        }
    }
}

// -------------------- persistent kv slots + k padding ----------------------
__global__ void persist_pad_kernel(const float* __restrict__ pk,
                                   const float* __restrict__ pv) {
    int idx = blockIdx.x * 256 + threadIdx.x;       // 65536 + 458752
    if (idx < NB * PP * HH * DD) {
        int d = idx & 63, h = (idx >> 6) & 7, p = (idx >> 9) & 15, n = idx >> 13;
        int src = ((p * HH + h) << 6) + d;
        g_v[(((size_t)(n * LP + TT + p) * HH + h) << 6) + d] = pv[src];
        g_k[((size_t)(n * 8 + h) * KPAD + TT + p) * 64 + d] = tf32r(pk[src]);
    } else {
        int j = idx - NB * PP * HH * DD;
        if (j >= 64 * 112 * 64) return;
        int d = j & 63;
        int l = LP + ((j >> 6) % 112);
        int ng = j / (112 * 64);
        g_k[((size_t)ng * KPAD + l) * 64 + d] = 0.f;
    }
}

// -------------------- V transpose -> tf32 [ng][d][1088] ---------------------
__global__ void vt_convert_kernel() {
    __shared__ float ts[64][65];
    const int lt = blockIdx.x;          // 0..16
    const int ng = blockIdx.y;          // 0..63
    const int n = ng >> 3, h = ng & 7;
    const int tid = threadIdx.x;

    for (int idx = tid; idx < 4096; idx += 256) {
        int lloc = idx >> 6, d = idx & 63;
        int l = lt * 64 + lloc;
        float v = 0.f;
        if (l < LP) v = g_v[(((size_t)(n * LP + l)) * HH + h) * 64 + d];
        ts[lloc][d] = v;
    }
    __syncthreads();
    for (int idx = tid; idx < 4096; idx += 256) {
        int d = idx >> 6, lloc = idx & 63;
        g_vT[((size_t)ng * 64 + d) * LPAD + lt * 64 + lloc] = tf32r(ts[lloc][d]);
    }
}

// -------------------- energy: Q@K^T + ALiBi (tf32 HMMA) --------------------
#define E_A0 0
#define E_B0 32768
#define EGY_SMEM 65536
__global__ void __launch_bounds__(256) energy_hmma_kernel() {
    extern __shared__ char smem[];
    const uint32_t sbase = smem_u32(smem);
    const int tid = threadIdx.x;
    const int lane = tid & 31, wid = tid >> 5;
    const int qt = blockIdx.x;          // 8
    const int kt = blockIdx.y;          // 9
    const int ng = blockIdx.z;          // 64
    const int m0w = (wid & 1) * 64;
    const int n0w = (wid >> 1) * 32;

    #pragma unroll
    for (int panel = 0; panel < 2; ++panel) {
        #pragma unroll
        for (int it = 0; it < 4; ++it) {
            int s = it * 256 + tid;
            int r = s >> 3, cb = s & 7;
            uint32_t off = SWZ((uint32_t)(r * 128 + cb * 16)) + panel * 16384;
            size_t qa = ((size_t)ng * TT + qt * 128 + r) * 64 + panel * 32 + cb * 4;
            size_t ka = ((size_t)ng * KPAD + kt * 128 + r) * 64 + panel * 32 + cb * 4;
            cpasync16(sbase + E_A0 + off, g_q + qa);
            cpasync16(sbase + E_B0 + off, g_k + ka);
        }
    }
    cp_commit();

    float C[4][4][4];
    #pragma unroll
    for (int mt = 0; mt < 4; ++mt)
        #pragma unroll
        for (int nt = 0; nt < 4; ++nt)
            #pragma unroll
            for (int i = 0; i < 4; ++i) C[mt][nt][i] = 0.f;

    cp_wait0();
    __syncthreads();

    #pragma unroll
    for (int panel = 0; panel < 2; ++panel) {
        #pragma unroll
        for (int ks = 0; ks < 4; ++ks) {
            uint32_t a[4][4];
            #pragma unroll
            for (int mt = 0; mt < 4; ++mt) {
                uint32_t off = SWZ((uint32_t)((m0w + mt * 16 + (lane & 15)) * 128
                                              + ks * 32 + (lane >> 4) * 16)) + panel * 16384;
                ldsm4(a[mt], sbase + E_A0 + off);
            }
            uint32_t b[8];
            #pragma unroll
            for (int p = 0; p < 2; ++p) {
                uint32_t off = SWZ((uint32_t)((n0w + p * 16 + (lane & 7) + ((lane >> 4) & 1) * 8) * 128
                                              + ks * 32 + ((lane >> 3) & 1) * 16)) + panel * 16384;
                ldsm4(&b[p * 4], sbase + E_B0 + off);
            }
            #pragma unroll
            for (int mt = 0; mt < 4; ++mt)
                #pragma unroll
                for (int nt = 0; nt < 4; ++nt)
                    mma_tf32(C[mt][nt], a[mt], &b[(nt >> 1) * 4 + (nt & 1) * 2]);
        }
    }

    const float slope = exp2f(-(float)((ng & 7) + 1));
    #pragma unroll
    for (int mt = 0; mt < 4; ++mt) {
        int qb = qt * 128 + m0w + mt * 16 + (lane >> 2);
        #pragma unroll
        for (int nt = 0; nt < 4; ++nt) {
            int k0 = kt * 128 + n0w + nt * 8 + (lane & 3) * 2;
            if (k0 >= LP) continue;
            #pragma unroll
            for (int hf = 0; hf < 2; ++hf) {
                int q = qb + hf * 8;
                float e0 = C[mt][nt][hf * 2 + 0];
                float e1 = C[mt][nt][hf * 2 + 1];
                if (k0 < TT) {
                    e0 -= fabsf((float)(q - k0)) * slope;
                    e1 -= fabsf((float)(q - k0 - 1)) * slope;
                }
                *(float2*)(g_att + ((size_t)(ng * TT + q)) * LP + k0) = make_float2(e0, e1);
            }
        }
    }
}

// ------------- pre-mix -> mask -> softmax -> post-mix (fused) ---------------
__global__ void __launch_bounds__(256, 3) softmax_kernel(
                               const float* __restrict__ pre,
                               const float* __restrict__ post,
                               const int* __restrict__ seq_mask) {
    __shared__ float sm[8][LP];
    __shared__ float ps_pre[64];
    __shared__ float ps_post[64];
    __shared__ float inv_s[8];
    const int nq = blockIdx.x;
    const int n = nq >> 10, q = nq & 1023;
    const int tid = threadIdx.x;

    if (tid < 64) { ps_pre[tid] = pre[tid]; ps_post[tid] = post[tid]; }

    for (int i4 = tid; i4 < 8 * (LP / 4); i4 += 256) {
        int h = i4 / (LP / 4), kk4 = (i4 - h * (LP / 4)) * 4;
        float4 v = *(const float4*)(g_att + ((size_t)((n * 8 + h) * TT + q)) * LP + kk4);
        *(float4*)&sm[h][kk4] = v;
    }
    __syncthreads();

    for (int kk0 = tid * 4; kk0 < LP; kk0 += 1024) {
        float4 a[8];
        #pragma unroll
        for (int h = 0; h < 8; h++) a[h] = *(const float4*)&sm[h][kk0];
        int4 msk = make_int4(1, 1, 1, 1);
        if (kk0 < TT) msk = *(const int4*)(seq_mask + n * TT + kk0);
        #pragma unroll
        for (int g = 0; g < 8; g++) {
            float4 o = make_float4(0.f, 0.f, 0.f, 0.f);
            #pragma unroll
            for (int h = 0; h < 8; h++) {
                float w = ps_pre[g * 8 + h];
                o.x += w * a[h].x; o.y += w * a[h].y;
                o.z += w * a[h].z; o.w += w * a[h].w;
            }
            o.x = msk.x ? o.x * SOFTMAX_SCALE : -442.f;
            o.y = msk.y ? o.y * SOFTMAX_SCALE : -442.f;
            o.z = msk.z ? o.z * SOFTMAX_SCALE : -442.f;
            o.w = msk.w ? o.w * SOFTMAX_SCALE : -442.f;
            *(float4*)&sm[g][kk0] = o;
        }
    }
    __syncthreads();

    const int w = tid >> 5, lane = tid & 31;
    float mx = -1e30f;
    for (int kk = lane; kk < LP; kk += 32) mx = fmaxf(mx, sm[w][kk]);
    #pragma unroll
    for (int o = 16; o; o >>= 1) mx = fmaxf(mx, __shfl_xor_sync(0xffffffffu, mx, o));
    float s = 0.f;
    for (int kk = lane; kk < LP; kk += 32) {
        float p = __expf(sm[w][kk] - mx);
        sm[w][kk] = p;
        s += p;
    }
    #pragma unroll
    for (int o = 16; o; o >>= 1) s += __shfl_xor_sync(0xffffffffu, s, o);
    if (lane == 0) inv_s[w] = 1.f / s;
    __syncthreads();

    float inv[8];
    #pragma unroll
    for (int h = 0; h < 8; h++) inv[h] = inv_s[h];
    for (int kk0 = tid * 4; kk0 < LPAD; kk0 += 1024) {
        float4 a[8];
        if (kk0 < LP) {
            #pragma unroll
            for (int h = 0; h < 8; h++) {
                a[h] = *(const float4*)&sm[h][kk0];
                a[h].x *= inv[h]; a[h].y *= inv[h];
                a[h].z *= inv[h]; a[h].w *= inv[h];
            }
        } else {
            #pragma unroll
            for (int h = 0; h < 8; h++) a[h] = make_float4(0.f, 0.f, 0.f, 0.f);
        }
        #pragma unroll
        for (int g = 0; g < 8; g++) {
            float4 o = make_float4(0.f, 0.f, 0.f, 0.f);
            #pragma unroll
            for (int h = 0; h < 8; h++) {
                float wgt = ps_post[g * 8 + h];
                o.x += wgt * a[h].x; o.y += wgt * a[h].y;
                o.z += wgt * a[h].z; o.w += wgt * a[h].w;
            }
            o.x = tf32r(o.x); o.y = tf32r(o.y);
            o.z = tf32r(o.z); o.w = tf32r(o.w);
            *(float4*)(g_a + ((size_t)((n * 8 + g) * TT + q)) * LPAD + kk0) = o;
        }
    }
}

// ------------------------- attn @ V (tf32 HMMA) -----------------------------
#define V_A 0
#define V_B 16384
#define V_BUF 24576
#define AV_SMEM (2 * V_BUF)

__global__ void __launch_bounds__(256) av_hmma_kernel() {
    extern __shared__ char smem[];
    const uint32_t sbase = smem_u32(smem);
    const int tid = threadIdx.x;
    const int lane = tid & 31, wid = tid >> 5;
    const int qt = blockIdx.x;          // 8
    const int ng = blockIdx.y;          // 64
    const int m0w = (wid & 3) * 32;
    const int n0w = (wid >> 2) * 32;

    float C[2][4][4];
    #pragma unroll
    for (int mt = 0; mt < 2; ++mt)
        #pragma unroll
        for (int nt = 0; nt < 4; ++nt)
            #pragma unroll
            for (int i = 0; i < 4; ++i) C[mt][nt][i] = 0.f;

    auto load_chunk = [&](int c, uint32_t bb) {
        #pragma unroll
        for (int it = 0; it < 4; ++it) {
            int s = it * 256 + tid;
            int r = s >> 3, cb = s & 7;
            size_t ga = ((size_t)ng * TT + qt * 128 + r) * LPAD + c * 32 + cb * 4;
            cpasync16(bb + V_A + SWZ((uint32_t)(r * 128 + cb * 16)), g_a + ga);
        }
        #pragma unroll
        for (int it = 0; it < 2; ++it) {
            int s = it * 256 + tid;
            int r = s >> 3, cb = s & 7;
            size_t gb = ((size_t)ng * 64 + r) * LPAD + c * 32 + cb * 4;
            cpasync16(bb + V_B + SWZ((uint32_t)(r * 128 + cb * 16)), g_vT + gb);
        }
        cp_commit();
    };

    load_chunk(0, sbase);

    for (int c = 0; c < 34; ++c) {
        const bool hn = (c + 1 < 34);
        if (hn) load_chunk(c + 1, sbase + ((c + 1) & 1) * V_BUF);
        if (hn) cp_wait1(); else cp_wait0();
        __syncthreads();

        const uint32_t Ab = sbase + (c & 1) * V_BUF;
        #pragma unroll
        for (int ks = 0; ks < 4; ++ks) {
            uint32_t a[2][4];
            #pragma unroll
            for (int mt = 0; mt < 2; ++mt) {
                uint32_t off = SWZ((uint32_t)((m0w + mt * 16 + (lane & 15)) * 128
                                              + ks * 32 + (lane >> 4) * 16));
                ldsm4(a[mt], Ab + V_A + off);
            }
            uint32_t b[8];
            #pragma unroll
            for (int p = 0; p < 2; ++p) {
                uint32_t off = SWZ((uint32_t)((n0w + p * 16 + (lane & 7) + ((lane >> 4) & 1) * 8) * 128
                                              + ks * 32 + ((lane >> 3) & 1) * 16));
                ldsm4(&b[p * 4], Ab + V_B + off);
            }
            #pragma unroll
            for (int mt = 0; mt < 2; ++mt)
                #pragma unroll
                for (int nt = 0; nt < 4; ++nt)
                    mma_tf32(C[mt][nt], a[mt], &b[(nt >> 1) * 4 + (nt & 1) * 2]);
        }
        __syncthreads();
    }

    const int n = ng >> 3, h = ng & 7;
    #pragma unroll
    for (int mt = 0; mt < 2; ++mt) {
        int qb = qt * 128 + m0w + mt * 16 + (lane >> 2);
        #pragma unroll
        for (int nt = 0; nt < 4; ++nt) {
            int dcol = n0w + nt * 8 + (lane & 3) * 2;
            #pragma unroll
            for (int hf = 0; hf < 2; ++hf) {
                int q = qb + hf * 8;
                size_t o = ((size_t)(n * TT + q)) * 512 + h * 64 + dcol;
                *(float2*)(g_ctx + o) = make_float2(tf32r(C[mt][nt][hf * 2 + 0]),
                                                    tf32r(C[mt][nt][hf * 2 + 1]));
            }
        }
    }
}

// ------------------------------ LayerNorm ----------------------------------
__global__ void ln_kernel(const float* __restrict__ gamma,
                          const float* __restrict__ beta,
                          float* __restrict__ out) {
    const int r = blockIdx.x;
    const int tid = threadIdx.x;
    const float* in = g_t2 + (size_t)r * EE;
    __shared__ float red[8];

    float v0 = in[tid], v1 = in[tid + 256];
    float s = v0 + v1;
    #pragma unroll
    for (int o = 16; o; o >>= 1) s += __shfl_xor_sync(0xffffffffu, s, o);
    if ((tid & 31) == 0) red[tid >> 5] = s;
    __syncthreads();
    float tot = 0.f;
    #pragma unroll
    for (int i = 0; i < 8; i++) tot += red[i];
    float mu = tot * (1.f / EE);
    __syncthreads();

    float d0 = v0 - mu, d1 = v1 - mu;
    float vs = d0 * d0 + d1 * d1;
    #pragma unroll
    for (int o = 16; o; o >>= 1) vs += __shfl_xor_sync(0xffffffffu, vs, o);
    if ((tid & 31) == 0) red[tid >> 5] = vs;
    __syncthreads();
    float vtot = 0.f;
    #pragma unroll
    for (int i = 0; i < 8; i++) vtot += red[i];
    float inv = rsqrtf(vtot * (1.f / EE) + 1e-5f);

    out[(size_t)r * EE + tid]       = d0 * inv * gamma[tid]       + beta[tid];
    out[(size_t)r * EE + tid + 256] = d1 * inv * gamma[tid + 256] + beta[tid + 256];
}

// ------------------------------ launcher -----------------------------------
extern "C" void kernel_launch(void* const* d_in, const int* in_sizes, int n_in,
                              void* d_out, int out_size) {
    const float* x        = (const float*)d_in[0];
    const int*   seq_mask = (const int*)  d_in[1];
    const float* Wq       = (const float*)d_in[2];
    const float* Wk       = (const float*)d_in[3];
    const float* Wv       = (const float*)d_in[4];
    const float* Wo       = (const float*)d_in[5];
    const float* bo       = (const float*)d_in[6];
    const float* pre_th   = (const float*)d_in[7];
    const float* post_th  = (const float*)d_in[8];
    const float* pk       = (const float*)d_in[9];
    const float* pv       = (const float*)d_in[10];
    const float* c1W      = (const float*)d_in[11];
    const float* c1b      = (const float*)d_in[12];
    const float* c2W      = (const float*)d_in[13];
    const float* c2b      = (const float*)d_in[14];
    const float* ln_g     = (const float*)d_in[15];
    const float* ln_b     = (const float*)d_in[16];
    float* out = (float*)d_out;

    float *pWo, *pC1, *pC2, *pCtx, *pH, *pT1, *pT2;
    cudaGetSymbolAddress((void**)&pWo,  g_Wo);
    cudaGetSymbolAddress((void**)&pC1,  g_c1);
    cudaGetSymbolAddress((void**)&pC2,  g_c2);
    cudaGetSymbolAddress((void**)&pCtx, g_ctx);
    cudaGetSymbolAddress((void**)&pH,   g_h);
    cudaGetSymbolAddress((void**)&pT1,  g_t1);
    cudaGetSymbolAddress((void**)&pT2,  g_t2);

    cudaFuncSetAttribute(gemm_hmma_kernel,
                         cudaFuncAttributeMaxDynamicSharedMemorySize, GEMM_SMEM);
    cudaFuncSetAttribute(energy_hmma_kernel,
                         cudaFuncAttributeMaxDynamicSharedMemorySize, EGY_SMEM);
    cudaFuncSetAttribute(av_hmma_kernel,
                         cudaFuncAttributeMaxDynamicSharedMemorySize, AV_SMEM);
    cudaFuncSetAttribute(qkv_hmma_kernel,
                         cudaFuncAttributeMaxDynamicSharedMemorySize, QKV_SMEM);

    wo_convert<<<1024, 256>>>(Wo, pWo);
    conv_w_convert<<<3072, 256>>>(c1W, pC1);
    conv_w_convert<<<3072, 256>>>(c2W, pC2);

    qkv_hmma_kernel<<<dim3(64, 8), 256, QKV_SMEM>>>(x, Wq, Wk, Wv);
    persist_pad_kernel<<<2048, 256>>>(pk, pv);
    vt_convert_kernel<<<dim3(17, 64), 256>>>();

    energy_hmma_kernel<<<dim3(8, 9, 64), 256, EGY_SMEM>>>();
    softmax_kernel<<<8192, 256>>>(pre_th, post_th, seq_mask);
    av_hmma_kernel<<<dim3(8, 64), 256, AV_SMEM>>>();

    gemm_hmma_kernel<<<dim3(64, 4), 256, GEMM_SMEM>>>(
        0, 16, pCtx, pWo, bo, x, seq_mask, pH);
    gemm_hmma_kernel<<<dim3(64, 4), 256, GEMM_SMEM>>>(
        1, 48, pH, pC1, c1b, nullptr, seq_mask, pT1);
    gemm_hmma_kernel<<<dim3(64, 4), 256, GEMM_SMEM>>>(
        2, 48, pT1, pC2, c2b, pH, seq_mask, pT2);

    ln_kernel<<<8192, 256>>>(ln_g, ln_b, out);
}

// round 9
// speedup vs baseline: 3.7818x; 1.1589x over previous
#include <cuda_runtime.h>
#include <cuda_bf16.h>
#include <cuda_fp16.h>
#include <math.h>
#include <stdint.h>

// ---------------------------------------------------------------------------
// TCNAttentionBlock. R9: attn (g_a) + vT stored fp16 (eps == tf32) ->
// av on fp16 m16n8k16 HMMA; softmax writes half2. Rest as R8.
// N=8, T=1024, E=512, H=8, D=64, P=16.
// ---------------------------------------------------------------------------

#define NB   8
#define TT   1024
#define EE   512
#define HH   8
#define DD   64
#define PP   16
#define LP   1040            // TT + PP
#define LPAD 1088            // attn row padded (17 chunks of 64)
#define KPAD 1152            // K rows padded (9 tiles of 128)
#define SOFTMAX_SCALE 0.044194173824159216f   // 1/sqrt(512)

// ------------------------------ scratch -----------------------------------
__device__ float  g_q  [64 * TT * DD];                     // tf32 [ng][q][64]
__device__ float  g_k  [64 * KPAD * DD];                   // tf32 [ng][l][64]
__device__ float  g_v  [NB * LP * HH * DD];                // fp32 (n,l,h,d)
__device__ __half g_vT [64 * DD * LPAD];                   // fp16 [ng][d][1088]
__device__ float  g_att[(size_t)NB * HH * TT * LP];        // fp32 energies
__device__ __half g_a  [(size_t)64 * TT * LPAD];           // fp16 attn
__device__ float  g_ctx[NB * TT * EE];                     // tf32
__device__ float  g_h  [NB * TT * EE];                     // tf32
__device__ float  g_t1 [NB * TT * EE];                     // tf32
__device__ float  g_t2 [NB * TT * EE];                     // fp32

// preconverted tf32 weights, layout [chunk][co(512)][32]
__device__ float g_Wo[16 * 512 * 32];
__device__ float g_c1[48 * 512 * 32];
__device__ float g_c2[48 * 512 * 32];

// ---------------------------- PTX helpers ----------------------------------
__device__ __forceinline__ uint32_t smem_u32(const void* p) {
    uint32_t a;
    asm("{ .reg .u64 t; cvta.to.shared.u64 t, %1; cvt.u32.u64 %0, t; }"
        : "=r"(a) : "l"(p));
    return a;
}
#define SWZ(o) ((o) ^ (((o) >> 3) & 0x70))

__device__ __forceinline__ uint32_t tf32r_u(float v) {
    uint32_t u;
    asm("cvt.rna.tf32.f32 %0, %1;" : "=r"(u) : "f"(v));
    return u;
}
__device__ __forceinline__ float tf32r(float v) {
    return __uint_as_float(tf32r_u(v));
}
__device__ __forceinline__ void ldsm4(uint32_t* r, uint32_t addr) {
    asm volatile("ldmatrix.sync.aligned.m8n8.x4.shared.b16 {%0,%1,%2,%3}, [%4];"
                 : "=r"(r[0]), "=r"(r[1]), "=r"(r[2]), "=r"(r[3]) : "r"(addr));
}
__device__ __forceinline__ void mma_tf32(float* c, const uint32_t* a, const uint32_t* b) {
    asm volatile(
        "mma.sync.aligned.m16n8k8.row.col.f32.tf32.tf32.f32 "
        "{%0,%1,%2,%3}, {%4,%5,%6,%7}, {%8,%9}, {%0,%1,%2,%3};"
        : "+f"(c[0]), "+f"(c[1]), "+f"(c[2]), "+f"(c[3])
        : "r"(a[0]), "r"(a[1]), "r"(a[2]), "r"(a[3]), "r"(b[0]), "r"(b[1]));
}
__device__ __forceinline__ void mma_f16(float* c, const uint32_t* a, const uint32_t* b) {
    asm volatile(
        "mma.sync.aligned.m16n8k16.row.col.f32.f16.f16.f32 "
        "{%0,%1,%2,%3}, {%4,%5,%6,%7}, {%8,%9}, {%0,%1,%2,%3};"
        : "+f"(c[0]), "+f"(c[1]), "+f"(c[2]), "+f"(c[3])
        : "r"(a[0]), "r"(a[1]), "r"(a[2]), "r"(a[3]), "r"(b[0]), "r"(b[1]));
}
__device__ __forceinline__ void cpasync16(uint32_t saddr, const void* g) {
    asm volatile("cp.async.cg.shared.global [%0], [%1], 16;" :: "r"(saddr), "l"(g));
}
__device__ __forceinline__ void cpasync16z(uint32_t saddr, const void* g, int sz) {
    asm volatile("cp.async.cg.shared.global [%0], [%1], 16, %2;"
                 :: "r"(saddr), "l"(g), "r"(sz));
}
__device__ __forceinline__ void cp_commit() {
    asm volatile("cp.async.commit_group;" ::: "memory");
}
__device__ __forceinline__ void cp_wait0() {
    asm volatile("cp.async.wait_group 0;" ::: "memory");
}
__device__ __forceinline__ void cp_wait1() {
    asm volatile("cp.async.wait_group 1;" ::: "memory");
}

// ---------------------- weight preconversion -------------------------------
__global__ void conv_w_convert(const float* __restrict__ W, float* __restrict__ o) {
    int d = blockIdx.x * 256 + threadIdx.x;          // 48*512*32
    int c  = d >> 14;
    int co = (d >> 5) & 511;
    int ci = d & 31;
    int tap = c >> 4, cib = (c & 15) << 5;
    o[d] = tf32r(W[(size_t)(co * 512 + cib + ci) * 3 + tap]);
}
__global__ void wo_convert(const float* __restrict__ W, float* __restrict__ o) {
    int d = blockIdx.x * 256 + threadIdx.x;          // 16*512*32
    int c  = d >> 14;
    int co = (d >> 5) & 511;
    int ci = d & 31;
    o[d] = tf32r(W[co * 512 + (c << 5) + ci]);
}

// ------------------------ QKV on tf32 HMMA ----------------------------------
#define QKV_B0 32768
#define QKV_SMEM (32768 + 3 * 16384)
__global__ void __launch_bounds__(256) qkv_hmma_kernel(
    const float* __restrict__ x,
    const float* __restrict__ Wq,
    const float* __restrict__ Wk,
    const float* __restrict__ Wv)
{
    extern __shared__ char smem[];
    const uint32_t sbase = smem_u32(smem);
    const int tid = threadIdx.x;
    const int lane = tid & 31, wid = tid >> 5;
    const int t0 = blockIdx.x * 128;
    const int h  = blockIdx.y;
    const int n  = t0 >> 10;
    const int ng = n * 8 + h;
    const int m0w = (wid & 3) * 32;
    const int n0w = (wid >> 2) * 32;

    #pragma unroll
    for (int it = 0; it < 8; ++it) {
        int lin = it * 1024 + tid * 4;
        int r = lin >> 6, ci = lin & 63;
        float4 v = *(const float4*)(x + (size_t)(t0 + r) * 512 + h * 64 + ci);
        uint32_t off = (ci >> 5) * 16384 + SWZ((uint32_t)(r * 128 + (ci & 31) * 4));
        *(uint4*)(smem + off) = make_uint4(tf32r_u(v.x), tf32r_u(v.y),
                                           tf32r_u(v.z), tf32r_u(v.w));
    }
    #pragma unroll
    for (int m = 0; m < 3; ++m) {
        const float* Wm = (m == 0) ? Wq : (m == 1) ? Wk : Wv;
        #pragma unroll
        for (int it = 0; it < 4; ++it) {
            int lin = it * 1024 + tid * 4;
            int r = lin >> 6, ci = lin & 63;
            float4 v = *(const float4*)(Wm + r * 64 + ci);
            uint32_t off = QKV_B0 + m * 16384 + (ci >> 5) * 8192
                         + SWZ((uint32_t)(r * 128 + (ci & 31) * 4));
            *(uint4*)(smem + off) = make_uint4(tf32r_u(v.x), tf32r_u(v.y),
                                               tf32r_u(v.z), tf32r_u(v.w));
        }
    }
    __syncthreads();

    for (int m = 0; m < 3; ++m) {
        float C[2][4][4];
        #pragma unroll
        for (int mt = 0; mt < 2; ++mt)
            #pragma unroll
            for (int nt = 0; nt < 4; ++nt)
                #pragma unroll
                for (int i = 0; i < 4; ++i) C[mt][nt][i] = 0.f;

        const uint32_t bbase = sbase + QKV_B0 + m * 16384;
        #pragma unroll
        for (int panel = 0; panel < 2; ++panel) {
            #pragma unroll
            for (int ks = 0; ks < 4; ++ks) {
                uint32_t a[2][4];
                #pragma unroll
                for (int mt = 0; mt < 2; ++mt) {
                    uint32_t off = panel * 16384
                        + SWZ((uint32_t)((m0w + mt * 16 + (lane & 15)) * 128
                                         + ks * 32 + (lane >> 4) * 16));
                    ldsm4(a[mt], sbase + off);
                }
                uint32_t b[8];
                #pragma unroll
                for (int p = 0; p < 2; ++p) {
                    uint32_t off = panel * 8192
                        + SWZ((uint32_t)((n0w + p * 16 + (lane & 7) + ((lane >> 4) & 1) * 8) * 128
                                         + ks * 32 + ((lane >> 3) & 1) * 16));
                    ldsm4(&b[p * 4], bbase + off);
                }
                #pragma unroll
                for (int mt = 0; mt < 2; ++mt)
                    #pragma unroll
                    for (int nt = 0; nt < 4; ++nt)
                        mma_tf32(C[mt][nt], a[mt], &b[(nt >> 1) * 4 + (nt & 1) * 2]);
            }
        }

        #pragma unroll
        for (int mt = 0; mt < 2; ++mt) {
            int tb = t0 + m0w + mt * 16 + (lane >> 2);
            #pragma unroll
            for (int nt = 0; nt < 4; ++nt) {
                int col = n0w + nt * 8 + (lane & 3) * 2;
                #pragma unroll
                for (int hf = 0; hf < 2; ++hf) {
                    int ts = (tb + hf * 8) & 1023;
                    float y0 = C[mt][nt][hf * 2 + 0];
                    float y1 = C[mt][nt][hf * 2 + 1];
                    if (m == 0) {
                        size_t o = ((size_t)ng * TT + ts) * 64 + col;
                        *(float2*)(g_q + o) = make_float2(tf32r(y0), tf32r(y1));
                    } else if (m == 1) {
                        size_t o = ((size_t)ng * KPAD + ts) * 64 + col;
                        *(float2*)(g_k + o) = make_float2(tf32r(y0), tf32r(y1));
                    } else {
                        size_t o = (((size_t)(n * LP + ts) * HH + h) << 6) + col;
                        *(float2*)(g_v + o) = make_float2(y0, y1);
                    }
                }
            }
        }
    }
}

// ---------------------- tf32 HMMA GEMM (outproj / conv) ---------------------
#define G_A 0
#define G_B 16384
#define G_BUF 32768
#define GEMM_SMEM (2 * G_BUF)

__global__ void __launch_bounds__(256, 2) gemm_hmma_kernel(
    int mode, int nchunk,
    const float* __restrict__ IN,
    const float* __restrict__ Bg,
    const float* __restrict__ bias,
    const float* __restrict__ resid,
    const int* __restrict__ seq_mask,
    float* __restrict__ OUT)
{
    extern __shared__ char smem[];
    const uint32_t sbase = smem_u32(smem);
    const int tid = threadIdx.x;
    const int lane = tid & 31, wid = tid >> 5;
    const int t0 = blockIdx.x * 128;
    const int co0 = blockIdx.y * 128;
    const int nBseq = t0 & ~1023;
    const int m0w = (wid & 1) * 64;
    const int n0w = (wid >> 1) * 32;

    float C[4][4][4];
    #pragma unroll
    for (int mt = 0; mt < 4; ++mt)
        #pragma unroll
        for (int nt = 0; nt < 4; ++nt)
            #pragma unroll
            for (int i = 0; i < 4; ++i) C[mt][nt][i] = 0.f;

    auto load_chunk = [&](int c, uint32_t bb) {
        int shift, cib;
        if (mode == 0) { shift = 0; cib = c << 5; }
        else           { shift = (c >> 4) - 2; cib = (c & 15) << 5; }
        #pragma unroll
        for (int it = 0; it < 4; ++it) {
            int s = it * 256 + tid;
            int r = s >> 3, cb = s & 7;
            int grow = t0 + r + shift;
            int ok = (grow >= nBseq);
            int ga = ok ? grow : nBseq;
            cpasync16z(bb + G_A + SWZ((uint32_t)(r * 128 + cb * 16)),
                       IN + (size_t)ga * 512 + cib + cb * 4, ok ? 16 : 0);
        }
        #pragma unroll
        for (int it = 0; it < 4; ++it) {
            int s = it * 256 + tid;
            int r = s >> 3, cb = s & 7;
            size_t gb = ((size_t)(c * 512 + co0 + r) << 5) + cb * 4;
            cpasync16(bb + G_B + SWZ((uint32_t)(r * 128 + cb * 16)), Bg + gb);
        }
        cp_commit();
    };

    load_chunk(0, sbase);

    for (int c = 0; c < nchunk; ++c) {
        const bool hn = (c + 1 < nchunk);
        if (hn) load_chunk(c + 1, sbase + ((c + 1) & 1) * G_BUF);
        if (hn) cp_wait1(); else cp_wait0();
        __syncthreads();

        const uint32_t Ab = sbase + (c & 1) * G_BUF;
        #pragma unroll
        for (int ks = 0; ks < 4; ++ks) {
            uint32_t a[4][4];
            #pragma unroll
            for (int mt = 0; mt < 4; ++mt) {
                uint32_t off = SWZ((uint32_t)((m0w + mt * 16 + (lane & 15)) * 128
                                              + ks * 32 + (lane >> 4) * 16));
                ldsm4(a[mt], Ab + G_A + off);
            }
            uint32_t b[8];
            #pragma unroll
            for (int p = 0; p < 2; ++p) {
                uint32_t off = SWZ((uint32_t)((n0w + p * 16 + (lane & 7) + ((lane >> 4) & 1) * 8) * 128
                                              + ks * 32 + ((lane >> 3) & 1) * 16));
                ldsm4(&b[p * 4], Ab + G_B + off);
            }
            #pragma unroll
            for (int mt = 0; mt < 4; ++mt)
                #pragma unroll
                for (int nt = 0; nt < 4; ++nt)
                    mma_tf32(C[mt][nt], a[mt], &b[(nt >> 1) * 4 + (nt & 1) * 2]);
        }
        __syncthreads();
    }

    #pragma unroll
    for (int mt = 0; mt < 4; ++mt) {
        int rb = t0 + m0w + mt * 16 + (lane >> 2);
        #pragma unroll
        for (int nt = 0; nt < 4; ++nt) {
            int col = co0 + n0w + nt * 8 + (lane & 3) * 2;
            float b0 = bias[col], b1 = bias[col + 1];
            #pragma unroll
            for (int hf = 0; hf < 2; ++hf) {
                int r = rb + hf * 8;
                float y0 = C[mt][nt][hf * 2 + 0] + b0;
                float y1 = C[mt][nt][hf * 2 + 1] + b1;
                if (mode == 0) {
                    const float2 rs = *(const float2*)(resid + (size_t)r * 512 + col);
                    y0 = tf32r(y0 + rs.x);
                    y1 = tf32r(y1 + rs.y);
                } else {
                    float valid = (float)seq_mask[r];
                    y0 = fmaxf(y0 * valid, 0.f);
                    y1 = fmaxf(y1 * valid, 0.f);
                    if (mode == 2) {
                        const float2 rs = *(const float2*)(resid + (size_t)r * 512 + col);
                        y0 = fmaxf(y0 + rs.x, 0.f);
                        y1 = fmaxf(y1 + rs.y, 0.f);
                    } else {
                        y0 = tf32r(y0);
                        y1 = tf32r(y1);
                    }
                }
                *(float2*)(OUT + (size_t)r * 512 + col) = make_float2(y0, y1);
            }
        }
    }
}

// -------------------- persistent kv slots + k padding ----------------------
__global__ void persist_pad_kernel(const float* __restrict__ pk,
                                   const float* __restrict__ pv) {
    int idx = blockIdx.x * 256 + threadIdx.x;
    if (idx < NB * PP * HH * DD) {
        int d = idx & 63, h = (idx >> 6) & 7, p = (idx >> 9) & 15, n = idx >> 13;
        int src = ((p * HH + h) << 6) + d;
        g_v[(((size_t)(n * LP + TT + p) * HH + h) << 6) + d] = pv[src];
        g_k[((size_t)(n * 8 + h) * KPAD + TT + p) * 64 + d] = tf32r(pk[src]);
    } else {
        int j = idx - NB * PP * HH * DD;
        if (j >= 64 * 112 * 64) return;
        int d = j & 63;
        int l = LP + ((j >> 6) % 112);
        int ng = j / (112 * 64);
        g_k[((size_t)ng * KPAD + l) * 64 + d] = 0.f;
    }
}

// -------------------- V transpose -> fp16 [ng][d][1088] ---------------------
__global__ void vt_convert_kernel() {
    __shared__ float ts[64][65];
    const int lt = blockIdx.x;          // 0..16
    const int ng = blockIdx.y;          // 0..63
    const int n = ng >> 3, h = ng & 7;
    const int tid = threadIdx.x;

    for (int idx = tid; idx < 4096; idx += 256) {
        int lloc = idx >> 6, d = idx & 63;
        int l = lt * 64 + lloc;
        float v = 0.f;
        if (l < LP) v = g_v[(((size_t)(n * LP + l)) * HH + h) * 64 + d];
        ts[lloc][d] = v;
    }
    __syncthreads();
    for (int idx = tid; idx < 4096; idx += 256) {
        int d = idx >> 6, lloc = idx & 63;
        g_vT[((size_t)ng * 64 + d) * LPAD + lt * 64 + lloc] = __float2half(ts[lloc][d]);
    }
}

// -------------------- energy: Q@K^T + ALiBi (tf32 HMMA) --------------------
#define E_A0 0
#define E_B0 32768
#define EGY_SMEM 65536
__global__ void __launch_bounds__(256) energy_hmma_kernel() {
    extern __shared__ char smem[];
    const uint32_t sbase = smem_u32(smem);
    const int tid = threadIdx.x;
    const int lane = tid & 31, wid = tid >> 5;
    const int qt = blockIdx.x;          // 8
    const int kt = blockIdx.y;          // 9
    const int ng = blockIdx.z;          // 64
    const int m0w = (wid & 1) * 64;
    const int n0w = (wid >> 1) * 32;

    #pragma unroll
    for (int panel = 0; panel < 2; ++panel) {
        #pragma unroll
        for (int it = 0; it < 4; ++it) {
            int s = it * 256 + tid;
            int r = s >> 3, cb = s & 7;
            uint32_t off = SWZ((uint32_t)(r * 128 + cb * 16)) + panel * 16384;
            size_t qa = ((size_t)ng * TT + qt * 128 + r) * 64 + panel * 32 + cb * 4;
            size_t ka = ((size_t)ng * KPAD + kt * 128 + r) * 64 + panel * 32 + cb * 4;
            cpasync16(sbase + E_A0 + off, g_q + qa);
            cpasync16(sbase + E_B0 + off, g_k + ka);
        }
    }
    cp_commit();

    float C[4][4][4];
    #pragma unroll
    for (int mt = 0; mt < 4; ++mt)
        #pragma unroll
        for (int nt = 0; nt < 4; ++nt)
            #pragma unroll
            for (int i = 0; i < 4; ++i) C[mt][nt][i] = 0.f;

    cp_wait0();
    __syncthreads();

    #pragma unroll
    for (int panel = 0; panel < 2; ++panel) {
        #pragma unroll
        for (int ks = 0; ks < 4; ++ks) {
            uint32_t a[4][4];
            #pragma unroll
            for (int mt = 0; mt < 4; ++mt) {
                uint32_t off = SWZ((uint32_t)((m0w + mt * 16 + (lane & 15)) * 128
                                              + ks * 32 + (lane >> 4) * 16)) + panel * 16384;
                ldsm4(a[mt], sbase + E_A0 + off);
            }
            uint32_t b[8];
            #pragma unroll
            for (int p = 0; p < 2; ++p) {
                uint32_t off = SWZ((uint32_t)((n0w + p * 16 + (lane & 7) + ((lane >> 4) & 1) * 8) * 128
                                              + ks * 32 + ((lane >> 3) & 1) * 16)) + panel * 16384;
                ldsm4(&b[p * 4], sbase + E_B0 + off);
            }
            #pragma unroll
            for (int mt = 0; mt < 4; ++mt)
                #pragma unroll
                for (int nt = 0; nt < 4; ++nt)
                    mma_tf32(C[mt][nt], a[mt], &b[(nt >> 1) * 4 + (nt & 1) * 2]);
        }
    }

    const float slope = exp2f(-(float)((ng & 7) + 1));
    #pragma unroll
    for (int mt = 0; mt < 4; ++mt) {
        int qb = qt * 128 + m0w + mt * 16 + (lane >> 2);
        #pragma unroll
        for (int nt = 0; nt < 4; ++nt) {
            int k0 = kt * 128 + n0w + nt * 8 + (lane & 3) * 2;
            if (k0 >= LP) continue;
            #pragma unroll
            for (int hf = 0; hf < 2; ++hf) {
                int q = qb + hf * 8;
                float e0 = C[mt][nt][hf * 2 + 0];
                float e1 = C[mt][nt][hf * 2 + 1];
                if (k0 < TT) {
                    e0 -= fabsf((float)(q - k0)) * slope;
                    e1 -= fabsf((float)(q - k0 - 1)) * slope;
                }
                *(float2*)(g_att + ((size_t)(ng * TT + q)) * LP + k0) = make_float2(e0, e1);
            }
        }
    }
}

// ------------- pre-mix -> mask -> softmax -> post-mix (fused) ---------------
__global__ void __launch_bounds__(256, 4) softmax_kernel(
                               const float* __restrict__ pre,
                               const float* __restrict__ post,
                               const int* __restrict__ seq_mask) {
    __shared__ float sm[8][LP];
    __shared__ float ps_pre[64];
    __shared__ float ps_post[64];
    __shared__ float inv_s[8];
    const int nq = blockIdx.x;
    const int n = nq >> 10, q = nq & 1023;
    const int tid = threadIdx.x;

    if (tid < 64) { ps_pre[tid] = pre[tid]; ps_post[tid] = post[tid]; }

    for (int i4 = tid; i4 < 8 * (LP / 4); i4 += 256) {
        int h = i4 / (LP / 4), kk4 = (i4 - h * (LP / 4)) * 4;
        float4 v = *(const float4*)(g_att + ((size_t)((n * 8 + h) * TT + q)) * LP + kk4);
        *(float4*)&sm[h][kk4] = v;
    }
    __syncthreads();

    for (int kk0 = tid * 4; kk0 < LP; kk0 += 1024) {
        float4 a[8];
        #pragma unroll
        for (int h = 0; h < 8; h++) a[h] = *(const float4*)&sm[h][kk0];
        int4 msk = make_int4(1, 1, 1, 1);
        if (kk0 < TT) msk = *(const int4*)(seq_mask + n * TT + kk0);
        #pragma unroll
        for (int g = 0; g < 8; g++) {
            float4 o = make_float4(0.f, 0.f, 0.f, 0.f);
            #pragma unroll
            for (int h = 0; h < 8; h++) {
                float w = ps_pre[g * 8 + h];
                o.x += w * a[h].x; o.y += w * a[h].y;
                o.z += w * a[h].z; o.w += w * a[h].w;
            }
            o.x = msk.x ? o.x * SOFTMAX_SCALE : -442.f;
            o.y = msk.y ? o.y * SOFTMAX_SCALE : -442.f;
            o.z = msk.z ? o.z * SOFTMAX_SCALE : -442.f;
            o.w = msk.w ? o.w * SOFTMAX_SCALE : -442.f;
            *(float4*)&sm[g][kk0] = o;
        }
    }
    __syncthreads();

    const int w = tid >> 5, lane = tid & 31;
    float mx = -1e30f;
    for (int kk = lane; kk < LP; kk += 32) mx = fmaxf(mx, sm[w][kk]);
    #pragma unroll
    for (int o = 16; o; o >>= 1) mx = fmaxf(mx, __shfl_xor_sync(0xffffffffu, mx, o));
    float s = 0.f;
    for (int kk = lane; kk < LP; kk += 32) {
        float p = __expf(sm[w][kk] - mx);
        sm[w][kk] = p;
        s += p;
    }
    #pragma unroll
    for (int o = 16; o; o >>= 1) s += __shfl_xor_sync(0xffffffffu, s, o);
    if (lane == 0) inv_s[w] = 1.f / s;
    __syncthreads();

    float inv[8];
    #pragma unroll
    for (int h = 0; h < 8; h++) inv[h] = inv_s[h];
    for (int kk0 = tid * 4; kk0 < LPAD; kk0 += 1024) {
        float4 a[8];
        if (kk0 < LP) {
            #pragma unroll
            for (int h = 0; h < 8; h++) {
                a[h] = *(const float4*)&sm[h][kk0];
                a[h].x *= inv[h]; a[h].y *= inv[h];
                a[h].z *= inv[h]; a[h].w *= inv[h];
            }
        } else {
            #pragma unroll
            for (int h = 0; h < 8; h++) a[h] = make_float4(0.f, 0.f, 0.f, 0.f);
        }
        #pragma unroll
        for (int g = 0; g < 8; g++) {
            float4 o = make_float4(0.f, 0.f, 0.f, 0.f);
            #pragma unroll
            for (int h = 0; h < 8; h++) {
                float wgt = ps_post[g * 8 + h];
                o.x += wgt * a[h].x; o.y += wgt * a[h].y;
                o.z += wgt * a[h].z; o.w += wgt * a[h].w;
            }
            __half2 h01 = __floats2half2_rn(o.x, o.y);
            __half2 h23 = __floats2half2_rn(o.z, o.w);
            __half2* dst = (__half2*)(g_a + ((size_t)((n * 8 + g) * TT + q)) * LPAD + kk0);
            dst[0] = h01;
            dst[1] = h23;
        }
    }
}

// ------------------------- attn @ V (fp16 HMMA) -----------------------------
// C[128 q][64 d] per (qt, ng). K = 1088 over 17 chunks of 64 halves.
#define V_A 0
#define V_B 16384
#define V_BUF 24576
#define AV_SMEM (2 * V_BUF)

__global__ void __launch_bounds__(256, 2) av_hmma_kernel() {
    extern __shared__ char smem[];
    const uint32_t sbase = smem_u32(smem);
    const int tid = threadIdx.x;
    const int lane = tid & 31, wid = tid >> 5;
    const int qt = blockIdx.x;          // 8
    const int ng = blockIdx.y;          // 64
    const int m0w = (wid & 3) * 32;
    const int n0w = (wid >> 2) * 32;

    float C[2][4][4];
    #pragma unroll
    for (int mt = 0; mt < 2; ++mt)
        #pragma unroll
        for (int nt = 0; nt < 4; ++nt)
            #pragma unroll
            for (int i = 0; i < 4; ++i) C[mt][nt][i] = 0.f;

    auto load_chunk = [&](int c, uint32_t bb) {
        // A: 128 rows x 128B (64 halves)
        #pragma unroll
        for (int it = 0; it < 4; ++it) {
            int s = it * 256 + tid;
            int r = s >> 3, cb = s & 7;
            size_t ga = ((size_t)ng * TT + qt * 128 + r) * LPAD + c * 64 + cb * 8;
            cpasync16(bb + V_A + SWZ((uint32_t)(r * 128 + cb * 16)), g_a + ga);
        }
        // B: 64 rows x 128B
        #pragma unroll
        for (int it = 0; it < 2; ++it) {
            int s = it * 256 + tid;
            int r = s >> 3, cb = s & 7;
            size_t gb = ((size_t)ng * 64 + r) * LPAD + c * 64 + cb * 8;
            cpasync16(bb + V_B + SWZ((uint32_t)(r * 128 + cb * 16)), g_vT + gb);
        }
        cp_commit();
    };

    load_chunk(0, sbase);

    for (int c = 0; c < 17; ++c) {
        const bool hn = (c + 1 < 17);
        if (hn) load_chunk(c + 1, sbase + ((c + 1) & 1) * V_BUF);
        if (hn) cp_wait1(); else cp_wait0();
        __syncthreads();

        const uint32_t Ab = sbase + (c & 1) * V_BUF;
        #pragma unroll
        for (int ks = 0; ks < 4; ++ks) {
            uint32_t a[2][4];
            #pragma unroll
            for (int mt = 0; mt < 2; ++mt) {
                uint32_t off = SWZ((uint32_t)((m0w + mt * 16 + (lane & 15)) * 128
                                              + ks * 32 + (lane >> 4) * 16));
                ldsm4(a[mt], Ab + V_A + off);
            }
            uint32_t b[8];
            #pragma unroll
            for (int p = 0; p < 2; ++p) {
                uint32_t off = SWZ((uint32_t)((n0w + p * 16 + (lane & 7) + ((lane >> 4) & 1) * 8) * 128
                                              + ks * 32 + ((lane >> 3) & 1) * 16));
                ldsm4(&b[p * 4], Ab + V_B + off);
            }
            #pragma unroll
            for (int mt = 0; mt < 2; ++mt)
                #pragma unroll
                for (int nt = 0; nt < 4; ++nt)
                    mma_f16(C[mt][nt], a[mt], &b[(nt >> 1) * 4 + (nt & 1) * 2]);
        }
        __syncthreads();
    }

    const int n = ng >> 3, h = ng & 7;
    #pragma unroll
    for (int mt = 0; mt < 2; ++mt) {
        int qb = qt * 128 + m0w + mt * 16 + (lane >> 2);
        #pragma unroll
        for (int nt = 0; nt < 4; ++nt) {
            int dcol = n0w + nt * 8 + (lane & 3) * 2;
            #pragma unroll
            for (int hf = 0; hf < 2; ++hf) {
                int q = qb + hf * 8;
                size_t o = ((size_t)(n * TT + q)) * 512 + h * 64 + dcol;
                *(float2*)(g_ctx + o) = make_float2(tf32r(C[mt][nt][hf * 2 + 0]),
                                                    tf32r(C[mt][nt][hf * 2 + 1]));
            }
        }
    }
}

// ------------------------------ LayerNorm ----------------------------------
__global__ void ln_kernel(const float* __restrict__ gamma,
                          const float* __restrict__ beta,
                          float* __restrict__ out) {
    const int r = blockIdx.x;
    const int tid = threadIdx.x;
    const float* in = g_t2 + (size_t)r * EE;
    __shared__ float red[8];

    float v0 = in[tid], v1 = in[tid + 256];
    float s = v0 + v1;
    #pragma unroll
    for (int o = 16; o; o >>= 1) s += __shfl_xor_sync(0xffffffffu, s, o);
    if ((tid & 31) == 0) red[tid >> 5] = s;
    __syncthreads();
    float tot = 0.f;
    #pragma unroll
    for (int i = 0; i < 8; i++) tot += red[i];
    float mu = tot * (1.f / EE);
    __syncthreads();

    float d0 = v0 - mu, d1 = v1 - mu;
    float vs = d0 * d0 + d1 * d1;
    #pragma unroll
    for (int o = 16; o; o >>= 1) vs += __shfl_xor_sync(0xffffffffu, vs, o);
    if ((tid & 31) == 0) red[tid >> 5] = vs;
    __syncthreads();
    float vtot = 0.f;
    #pragma unroll
    for (int i = 0; i < 8; i++) vtot += red[i];
    float inv = rsqrtf(vtot * (1.f / EE) + 1e-5f);

    out[(size_t)r * EE + tid]       = d0 * inv * gamma[tid]       + beta[tid];
    out[(size_t)r * EE + tid + 256] = d1 * inv * gamma[tid + 256] + beta[tid + 256];
}

// ------------------------------ launcher -----------------------------------
extern "C" void kernel_launch(void* const* d_in, const int* in_sizes, int n_in,
                              void* d_out, int out_size) {
    const float* x        = (const float*)d_in[0];
    const int*   seq_mask = (const int*)  d_in[1];
    const float* Wq       = (const float*)d_in[2];
    const float* Wk       = (const float*)d_in[3];
    const float* Wv       = (const float*)d_in[4];
    const float* Wo       = (const float*)d_in[5];
    const float* bo       = (const float*)d_in[6];
    const float* pre_th   = (const float*)d_in[7];
    const float* post_th  = (const float*)d_in[8];
    const float* pk       = (const float*)d_in[9];
    const float* pv       = (const float*)d_in[10];
    const float* c1W      = (const float*)d_in[11];
    const float* c1b      = (const float*)d_in[12];
    const float* c2W      = (const float*)d_in[13];
    const float* c2b      = (const float*)d_in[14];
    const float* ln_g     = (const float*)d_in[15];
    const float* ln_b     = (const float*)d_in[16];
    float* out = (float*)d_out;

    float *pWo, *pC1, *pC2, *pCtx, *pH, *pT1, *pT2;
    cudaGetSymbolAddress((void**)&pWo,  g_Wo);
    cudaGetSymbolAddress((void**)&pC1,  g_c1);
    cudaGetSymbolAddress((void**)&pC2,  g_c2);
    cudaGetSymbolAddress((void**)&pCtx, g_ctx);
    cudaGetSymbolAddress((void**)&pH,   g_h);
    cudaGetSymbolAddress((void**)&pT1,  g_t1);
    cudaGetSymbolAddress((void**)&pT2,  g_t2);

    cudaFuncSetAttribute(gemm_hmma_kernel,
                         cudaFuncAttributeMaxDynamicSharedMemorySize, GEMM_SMEM);
    cudaFuncSetAttribute(energy_hmma_kernel,
                         cudaFuncAttributeMaxDynamicSharedMemorySize, EGY_SMEM);
    cudaFuncSetAttribute(av_hmma_kernel,
                         cudaFuncAttributeMaxDynamicSharedMemorySize, AV_SMEM);
    cudaFuncSetAttribute(qkv_hmma_kernel,
                         cudaFuncAttributeMaxDynamicSharedMemorySize, QKV_SMEM);

    wo_convert<<<1024, 256>>>(Wo, pWo);
    conv_w_convert<<<3072, 256>>>(c1W, pC1);
    conv_w_convert<<<3072, 256>>>(c2W, pC2);

    qkv_hmma_kernel<<<dim3(64, 8), 256, QKV_SMEM>>>(x, Wq, Wk, Wv);
    persist_pad_kernel<<<2048, 256>>>(pk, pv);
    vt_convert_kernel<<<dim3(17, 64), 256>>>();

    energy_hmma_kernel<<<dim3(8, 9, 64), 256, EGY_SMEM>>>();
    softmax_kernel<<<8192, 256>>>(pre_th, post_th, seq_mask);
    av_hmma_kernel<<<dim3(8, 64), 256, AV_SMEM>>>();

    gemm_hmma_kernel<<<dim3(64, 4), 256, GEMM_SMEM>>>(
        0, 16, pCtx, pWo, bo, x, seq_mask, pH);
    gemm_hmma_kernel<<<dim3(64, 4), 256, GEMM_SMEM>>>(
        1, 48, pH, pC1, c1b, nullptr, seq_mask, pT1);
    gemm_hmma_kernel<<<dim3(64, 4), 256, GEMM_SMEM>>>(
        2, 48, pT1, pC2, c2b, pH, seq_mask, pT2);

    ln_kernel<<<8192, 256>>>(ln_g, ln_b, out);
}

// round 10
// speedup vs baseline: 4.0801x; 1.0789x over previous
#include <cuda_runtime.h>
#include <cuda_bf16.h>
#include <cuda_fp16.h>
#include <math.h>
#include <stdint.h>

// ---------------------------------------------------------------------------
// TCNAttentionBlock. R10: g_att stored as fp16 RAW QK^T (ALiBi reconstructed
// in softmax via premixed slopes); qkv writes vT fp16 directly (vt kernel
// removed). N=8, T=1024, E=512, H=8, D=64, P=16.
// ---------------------------------------------------------------------------

#define NB   8
#define TT   1024
#define EE   512
#define HH   8
#define DD   64
#define PP   16
#define LP   1040            // TT + PP
#define LPAD 1088            // attn row padded (17 chunks of 64)
#define KPAD 1152            // K rows padded (9 tiles of 128)
#define SOFTMAX_SCALE 0.044194173824159216f   // 1/sqrt(512)

// ------------------------------ scratch -----------------------------------
__device__ float  g_q  [64 * TT * DD];                     // tf32 [ng][q][64]
__device__ float  g_k  [64 * KPAD * DD];                   // tf32 [ng][l][64]
__device__ __half g_vT [64 * DD * LPAD];                   // fp16 [ng][d][1088]
__device__ __half g_att[(size_t)64 * TT * LP];             // fp16 raw QK^T
__device__ __half g_a  [(size_t)64 * TT * LPAD];           // fp16 attn
__device__ float  g_ctx[NB * TT * EE];                     // tf32
__device__ float  g_h  [NB * TT * EE];                     // tf32
__device__ float  g_t1 [NB * TT * EE];                     // tf32
__device__ float  g_t2 [NB * TT * EE];                     // fp32

// preconverted tf32 weights, layout [chunk][co(512)][32]
__device__ float g_Wo[16 * 512 * 32];
__device__ float g_c1[48 * 512 * 32];
__device__ float g_c2[48 * 512 * 32];

// ---------------------------- PTX helpers ----------------------------------
__device__ __forceinline__ uint32_t smem_u32(const void* p) {
    uint32_t a;
    asm("{ .reg .u64 t; cvta.to.shared.u64 t, %1; cvt.u32.u64 %0, t; }"
        : "=r"(a) : "l"(p));
    return a;
}
#define SWZ(o) ((o) ^ (((o) >> 3) & 0x70))

__device__ __forceinline__ uint32_t tf32r_u(float v) {
    uint32_t u;
    asm("cvt.rna.tf32.f32 %0, %1;" : "=r"(u) : "f"(v));
    return u;
}
__device__ __forceinline__ float tf32r(float v) {
    return __uint_as_float(tf32r_u(v));
}
__device__ __forceinline__ void ldsm4(uint32_t* r, uint32_t addr) {
    asm volatile("ldmatrix.sync.aligned.m8n8.x4.shared.b16 {%0,%1,%2,%3}, [%4];"
                 : "=r"(r[0]), "=r"(r[1]), "=r"(r[2]), "=r"(r[3]) : "r"(addr));
}
__device__ __forceinline__ void mma_tf32(float* c, const uint32_t* a, const uint32_t* b) {
    asm volatile(
        "mma.sync.aligned.m16n8k8.row.col.f32.tf32.tf32.f32 "
        "{%0,%1,%2,%3}, {%4,%5,%6,%7}, {%8,%9}, {%0,%1,%2,%3};"
        : "+f"(c[0]), "+f"(c[1]), "+f"(c[2]), "+f"(c[3])
        : "r"(a[0]), "r"(a[1]), "r"(a[2]), "r"(a[3]), "r"(b[0]), "r"(b[1]));
}
__device__ __forceinline__ void mma_f16(float* c, const uint32_t* a, const uint32_t* b) {
    asm volatile(
        "mma.sync.aligned.m16n8k16.row.col.f32.f16.f16.f32 "
        "{%0,%1,%2,%3}, {%4,%5,%6,%7}, {%8,%9}, {%0,%1,%2,%3};"
        : "+f"(c[0]), "+f"(c[1]), "+f"(c[2]), "+f"(c[3])
        : "r"(a[0]), "r"(a[1]), "r"(a[2]), "r"(a[3]), "r"(b[0]), "r"(b[1]));
}
__device__ __forceinline__ void cpasync16(uint32_t saddr, const void* g) {
    asm volatile("cp.async.cg.shared.global [%0], [%1], 16;" :: "r"(saddr), "l"(g));
}
__device__ __forceinline__ void cpasync16z(uint32_t saddr, const void* g, int sz) {
    asm volatile("cp.async.cg.shared.global [%0], [%1], 16, %2;"
                 :: "r"(saddr), "l"(g), "r"(sz));
}
__device__ __forceinline__ void cp_commit() {
    asm volatile("cp.async.commit_group;" ::: "memory");
}
__device__ __forceinline__ void cp_wait0() {
    asm volatile("cp.async.wait_group 0;" ::: "memory");
}
__device__ __forceinline__ void cp_wait1() {
    asm volatile("cp.async.wait_group 1;" ::: "memory");
}

// ---------------------- weight preconversion -------------------------------
__global__ void conv_w_convert(const float* __restrict__ W, float* __restrict__ o) {
    int d = blockIdx.x * 256 + threadIdx.x;          // 48*512*32
    int c  = d >> 14;
    int co = (d >> 5) & 511;
    int ci = d & 31;
    int tap = c >> 4, cib = (c & 15) << 5;
    o[d] = tf32r(W[(size_t)(co * 512 + cib + ci) * 3 + tap]);
}
__global__ void wo_convert(const float* __restrict__ W, float* __restrict__ o) {
    int d = blockIdx.x * 256 + threadIdx.x;          // 16*512*32
    int c  = d >> 14;
    int co = (d >> 5) & 511;
    int ci = d & 31;
    o[d] = tf32r(W[co * 512 + (c << 5) + ci]);
}

// ------------------------ QKV on tf32 HMMA ----------------------------------
// grid (64 t-tiles, 8 heads). writes q/k tf32, v -> g_vT fp16 transposed.
#define QKV_B0 32768
#define QKV_SMEM (32768 + 3 * 16384)
__global__ void __launch_bounds__(256) qkv_hmma_kernel(
    const float* __restrict__ x,
    const float* __restrict__ Wq,
    const float* __restrict__ Wk,
    const float* __restrict__ Wv)
{
    extern __shared__ char smem[];
    const uint32_t sbase = smem_u32(smem);
    const int tid = threadIdx.x;
    const int lane = tid & 31, wid = tid >> 5;
    const int t0 = blockIdx.x * 128;
    const int h  = blockIdx.y;
    const int n  = t0 >> 10;
    const int ng = n * 8 + h;
    const int m0w = (wid & 3) * 32;
    const int n0w = (wid >> 2) * 32;

    #pragma unroll
    for (int it = 0; it < 8; ++it) {
        int lin = it * 1024 + tid * 4;
        int r = lin >> 6, ci = lin & 63;
        float4 v = *(const float4*)(x + (size_t)(t0 + r) * 512 + h * 64 + ci);
        uint32_t off = (ci >> 5) * 16384 + SWZ((uint32_t)(r * 128 + (ci & 31) * 4));
        *(uint4*)(smem + off) = make_uint4(tf32r_u(v.x), tf32r_u(v.y),
                                           tf32r_u(v.z), tf32r_u(v.w));
    }
    #pragma unroll
    for (int m = 0; m < 3; ++m) {
        const float* Wm = (m == 0) ? Wq : (m == 1) ? Wk : Wv;
        #pragma unroll
        for (int it = 0; it < 4; ++it) {
            int lin = it * 1024 + tid * 4;
            int r = lin >> 6, ci = lin & 63;
            float4 v = *(const float4*)(Wm + r * 64 + ci);
            uint32_t off = QKV_B0 + m * 16384 + (ci >> 5) * 8192
                         + SWZ((uint32_t)(r * 128 + (ci & 31) * 4));
            *(uint4*)(smem + off) = make_uint4(tf32r_u(v.x), tf32r_u(v.y),
                                               tf32r_u(v.z), tf32r_u(v.w));
        }
    }
    __syncthreads();

    for (int m = 0; m < 3; ++m) {
        float C[2][4][4];
        #pragma unroll
        for (int mt = 0; mt < 2; ++mt)
            #pragma unroll
            for (int nt = 0; nt < 4; ++nt)
                #pragma unroll
                for (int i = 0; i < 4; ++i) C[mt][nt][i] = 0.f;

        const uint32_t bbase = sbase + QKV_B0 + m * 16384;
        #pragma unroll
        for (int panel = 0; panel < 2; ++panel) {
            #pragma unroll
            for (int ks = 0; ks < 4; ++ks) {
                uint32_t a[2][4];
                #pragma unroll
                for (int mt = 0; mt < 2; ++mt) {
                    uint32_t off = panel * 16384
                        + SWZ((uint32_t)((m0w + mt * 16 + (lane & 15)) * 128
                                         + ks * 32 + (lane >> 4) * 16));
                    ldsm4(a[mt], sbase + off);
                }
                uint32_t b[8];
                #pragma unroll
                for (int p = 0; p < 2; ++p) {
                    uint32_t off = panel * 8192
                        + SWZ((uint32_t)((n0w + p * 16 + (lane & 7) + ((lane >> 4) & 1) * 8) * 128
                                         + ks * 32 + ((lane >> 3) & 1) * 16));
                    ldsm4(&b[p * 4], bbase + off);
                }
                #pragma unroll
                for (int mt = 0; mt < 2; ++mt)
                    #pragma unroll
                    for (int nt = 0; nt < 4; ++nt)
                        mma_tf32(C[mt][nt], a[mt], &b[(nt >> 1) * 4 + (nt & 1) * 2]);
            }
        }

        #pragma unroll
        for (int mt = 0; mt < 2; ++mt) {
            int tb = t0 + m0w + mt * 16 + (lane >> 2);
            #pragma unroll
            for (int nt = 0; nt < 4; ++nt) {
                int col = n0w + nt * 8 + (lane & 3) * 2;
                #pragma unroll
                for (int hf = 0; hf < 2; ++hf) {
                    int ts = (tb + hf * 8) & 1023;
                    float y0 = C[mt][nt][hf * 2 + 0];
                    float y1 = C[mt][nt][hf * 2 + 1];
                    if (m == 0) {
                        size_t o = ((size_t)ng * TT + ts) * 64 + col;
                        *(float2*)(g_q + o) = make_float2(tf32r(y0), tf32r(y1));
                    } else if (m == 1) {
                        size_t o = ((size_t)ng * KPAD + ts) * 64 + col;
                        *(float2*)(g_k + o) = make_float2(tf32r(y0), tf32r(y1));
                    } else {
                        // v transposed: vT[ng][d][l]
                        g_vT[((size_t)ng * 64 + col)     * LPAD + ts] = __float2half(y0);
                        g_vT[((size_t)ng * 64 + col + 1) * LPAD + ts] = __float2half(y1);
                    }
                }
            }
        }
    }
}

// ---------------------- tf32 HMMA GEMM (outproj / conv) ---------------------
#define G_A 0
#define G_B 16384
#define G_BUF 32768
#define GEMM_SMEM (2 * G_BUF)

__global__ void __launch_bounds__(256, 2) gemm_hmma_kernel(
    int mode, int nchunk,
    const float* __restrict__ IN,
    const float* __restrict__ Bg,
    const float* __restrict__ bias,
    const float* __restrict__ resid,
    const int* __restrict__ seq_mask,
    float* __restrict__ OUT)
{
    extern __shared__ char smem[];
    const uint32_t sbase = smem_u32(smem);
    const int tid = threadIdx.x;
    const int lane = tid & 31, wid = tid >> 5;
    const int t0 = blockIdx.x * 128;
    const int co0 = blockIdx.y * 128;
    const int nBseq = t0 & ~1023;
    const int m0w = (wid & 1) * 64;
    const int n0w = (wid >> 1) * 32;

    float C[4][4][4];
    #pragma unroll
    for (int mt = 0; mt < 4; ++mt)
        #pragma unroll
        for (int nt = 0; nt < 4; ++nt)
            #pragma unroll
            for (int i = 0; i < 4; ++i) C[mt][nt][i] = 0.f;

    auto load_chunk = [&](int c, uint32_t bb) {
        int shift, cib;
        if (mode == 0) { shift = 0; cib = c << 5; }
        else           { shift = (c >> 4) - 2; cib = (c & 15) << 5; }
        #pragma unroll
        for (int it = 0; it < 4; ++it) {
            int s = it * 256 + tid;
            int r = s >> 3, cb = s & 7;
            int grow = t0 + r + shift;
            int ok = (grow >= nBseq);
            int ga = ok ? grow : nBseq;
            cpasync16z(bb + G_A + SWZ((uint32_t)(r * 128 + cb * 16)),
                       IN + (size_t)ga * 512 + cib + cb * 4, ok ? 16 : 0);
        }
        #pragma unroll
        for (int it = 0; it < 4; ++it) {
            int s = it * 256 + tid;
            int r = s >> 3, cb = s & 7;
            size_t gb = ((size_t)(c * 512 + co0 + r) << 5) + cb * 4;
            cpasync16(bb + G_B + SWZ((uint32_t)(r * 128 + cb * 16)), Bg + gb);
        }
        cp_commit();
    };

    load_chunk(0, sbase);

    for (int c = 0; c < nchunk; ++c) {
        const bool hn = (c + 1 < nchunk);
        if (hn) load_chunk(c + 1, sbase + ((c + 1) & 1) * G_BUF);
        if (hn) cp_wait1(); else cp_wait0();
        __syncthreads();

        const uint32_t Ab = sbase + (c & 1) * G_BUF;
        #pragma unroll
        for (int ks = 0; ks < 4; ++ks) {
            uint32_t a[4][4];
            #pragma unroll
            for (int mt = 0; mt < 4; ++mt) {
                uint32_t off = SWZ((uint32_t)((m0w + mt * 16 + (lane & 15)) * 128
                                              + ks * 32 + (lane >> 4) * 16));
                ldsm4(a[mt], Ab + G_A + off);
            }
            uint32_t b[8];
            #pragma unroll
            for (int p = 0; p < 2; ++p) {
                uint32_t off = SWZ((uint32_t)((n0w + p * 16 + (lane & 7) + ((lane >> 4) & 1) * 8) * 128
                                              + ks * 32 + ((lane >> 3) & 1) * 16));
                ldsm4(&b[p * 4], Ab + G_B + off);
            }
            #pragma unroll
            for (int mt = 0; mt < 4; ++mt)
                #pragma unroll
                for (int nt = 0; nt < 4; ++nt)
                    mma_tf32(C[mt][nt], a[mt], &b[(nt >> 1) * 4 + (nt & 1) * 2]);
        }
        __syncthreads();
    }

    #pragma unroll
    for (int mt = 0; mt < 4; ++mt) {
        int rb = t0 + m0w + mt * 16 + (lane >> 2);
        #pragma unroll
        for (int nt = 0; nt < 4; ++nt) {
            int col = co0 + n0w + nt * 8 + (lane & 3) * 2;
            float b0 = bias[col], b1 = bias[col + 1];
            #pragma unroll
            for (int hf = 0; hf < 2; ++hf) {
                int r = rb + hf * 8;
                float y0 = C[mt][nt][hf * 2 + 0] + b0;
                float y1 = C[mt][nt][hf * 2 + 1] + b1;
                if (mode == 0) {
                    const float2 rs = *(const float2*)(resid + (size_t)r * 512 + col);
                    y0 = tf32r(y0 + rs.x);
                    y1 = tf32r(y1 + rs.y);
                } else {
                    float valid = (float)seq_mask[r];
                    y0 = fmaxf(y0 * valid, 0.f);
                    y1 = fmaxf(y1 * valid, 0.f);
                    if (mode == 2) {
                        const float2 rs = *(const float2*)(resid + (size_t)r * 512 + col);
                        y0 = fmaxf(y0 + rs.x, 0.f);
                        y1 = fmaxf(y1 + rs.y, 0.f);
                    } else {
                        y0 = tf32r(y0);
                        y1 = tf32r(y1);
                    }
                }
                *(float2*)(OUT + (size_t)r * 512 + col) = make_float2(y0, y1);
            }
        }
    }
}

// ------- persistent kv slots (k + vT) + k padding + vT padding -------------
__global__ void persist_pad_kernel(const float* __restrict__ pk,
                                   const float* __restrict__ pv) {
    int idx = blockIdx.x * 256 + threadIdx.x;
    if (idx < NB * PP * HH * DD) {                      // 65536
        int d = idx & 63, h = (idx >> 6) & 7, p = (idx >> 9) & 15, n = idx >> 13;
        int src = ((p * HH + h) << 6) + d;
        int ng = n * 8 + h;
        g_vT[((size_t)ng * 64 + d) * LPAD + TT + p] = __float2half(pv[src]);
        g_k[((size_t)ng * KPAD + TT + p) * 64 + d] = tf32r(pk[src]);
        return;
    }
    int j = idx - NB * PP * HH * DD;
    if (j < 64 * 112 * 64) {                            // k pad rows [LP,KPAD)
        int d = j & 63;
        int l = LP + ((j >> 6) % 112);
        int ng = j / (112 * 64);
        g_k[((size_t)ng * KPAD + l) * 64 + d] = 0.f;
        return;
    }
    j -= 64 * 112 * 64;
    if (j < 64 * 64 * 48) {                             // vT pad cols [LP,LPAD)
        int c = j % 48;
        int d = (j / 48) & 63;
        int ng = j / (48 * 64);
        g_vT[((size_t)ng * 64 + d) * LPAD + LP + c] = __float2half(0.f);
    }
}

// -------------------- energy: raw Q@K^T -> fp16 (tf32 HMMA) ----------------
#define E_A0 0
#define E_B0 32768
#define EGY_SMEM 65536
__global__ void __launch_bounds__(256) energy_hmma_kernel() {
    extern __shared__ char smem[];
    const uint32_t sbase = smem_u32(smem);
    const int tid = threadIdx.x;
    const int lane = tid & 31, wid = tid >> 5;
    const int qt = blockIdx.x;          // 8
    const int kt = blockIdx.y;          // 9
    const int ng = blockIdx.z;          // 64
    const int m0w = (wid & 1) * 64;
    const int n0w = (wid >> 1) * 32;

    #pragma unroll
    for (int panel = 0; panel < 2; ++panel) {
        #pragma unroll
        for (int it = 0; it < 4; ++it) {
            int s = it * 256 + tid;
            int r = s >> 3, cb = s & 7;
            uint32_t off = SWZ((uint32_t)(r * 128 + cb * 16)) + panel * 16384;
            size_t qa = ((size_t)ng * TT + qt * 128 + r) * 64 + panel * 32 + cb * 4;
            size_t ka = ((size_t)ng * KPAD + kt * 128 + r) * 64 + panel * 32 + cb * 4;
            cpasync16(sbase + E_A0 + off, g_q + qa);
            cpasync16(sbase + E_B0 + off, g_k + ka);
        }
    }
    cp_commit();

    float C[4][4][4];
    #pragma unroll
    for (int mt = 0; mt < 4; ++mt)
        #pragma unroll
        for (int nt = 0; nt < 4; ++nt)
            #pragma unroll
            for (int i = 0; i < 4; ++i) C[mt][nt][i] = 0.f;

    cp_wait0();
    __syncthreads();

    #pragma unroll
    for (int panel = 0; panel < 2; ++panel) {
        #pragma unroll
        for (int ks = 0; ks < 4; ++ks) {
            uint32_t a[4][4];
            #pragma unroll
            for (int mt = 0; mt < 4; ++mt) {
                uint32_t off = SWZ((uint32_t)((m0w + mt * 16 + (lane & 15)) * 128
                                              + ks * 32 + (lane >> 4) * 16)) + panel * 16384;
                ldsm4(a[mt], sbase + E_A0 + off);
            }
            uint32_t b[8];
            #pragma unroll
            for (int p = 0; p < 2; ++p) {
                uint32_t off = SWZ((uint32_t)((n0w + p * 16 + (lane & 7) + ((lane >> 4) & 1) * 8) * 128
                                              + ks * 32 + ((lane >> 3) & 1) * 16)) + panel * 16384;
                ldsm4(&b[p * 4], sbase + E_B0 + off);
            }
            #pragma unroll
            for (int mt = 0; mt < 4; ++mt)
                #pragma unroll
                for (int nt = 0; nt < 4; ++nt)
                    mma_tf32(C[mt][nt], a[mt], &b[(nt >> 1) * 4 + (nt & 1) * 2]);
        }
    }

    #pragma unroll
    for (int mt = 0; mt < 4; ++mt) {
        int qb = qt * 128 + m0w + mt * 16 + (lane >> 2);
        #pragma unroll
        for (int nt = 0; nt < 4; ++nt) {
            int k0 = kt * 128 + n0w + nt * 8 + (lane & 3) * 2;
            if (k0 >= LP) continue;
            #pragma unroll
            for (int hf = 0; hf < 2; ++hf) {
                int q = qb + hf * 8;
                __half2 e = __floats2half2_rn(C[mt][nt][hf * 2 + 0],
                                              C[mt][nt][hf * 2 + 1]);
                *(__half2*)(g_att + ((size_t)(ng * TT + q)) * LP + k0) = e;
            }
        }
    }
}

// ------- pre-mix(+recomputed ALiBi) -> mask -> softmax -> post-mix ---------
__global__ void __launch_bounds__(256, 4) softmax_kernel(
                               const float* __restrict__ pre,
                               const float* __restrict__ post,
                               const int* __restrict__ seq_mask) {
    __shared__ float sm[8][LP];
    __shared__ float ps_pre[64];
    __shared__ float ps_post[64];
    __shared__ float inv_s[8];
    const int nq = blockIdx.x;
    const int n = nq >> 10, q = nq & 1023;
    const int tid = threadIdx.x;

    if (tid < 64) { ps_pre[tid] = pre[tid]; ps_post[tid] = post[tid]; }

    // load raw fp16 energies: 8 rows x 1040 halves (130 uint4 per row)
    for (int i8 = tid; i8 < 8 * (LP / 8); i8 += 256) {
        int h = i8 / (LP / 8), kk8 = (i8 - h * (LP / 8)) * 8;
        const __half2* src = (const __half2*)(g_att + ((size_t)((n * 8 + h) * TT + q)) * LP + kk8);
        #pragma unroll
        for (int u = 0; u < 4; ++u) {
            float2 f = __half22float2(src[u]);
            sm[h][kk8 + u * 2 + 0] = f.x;
            sm[h][kk8 + u * 2 + 1] = f.y;
        }
    }
    __syncthreads();

    // premixed ALiBi slopes: s'_g = sum_h pre[g,h] * 2^-(h+1)
    float spre[8];
    #pragma unroll
    for (int g = 0; g < 8; g++) {
        float s = 0.f;
        #pragma unroll
        for (int h = 0; h < 8; h++) s += ps_pre[g * 8 + h] * exp2f(-(float)(h + 1));
        spre[g] = s;
    }

    // pre-mix + ALiBi + mask + scale (vectorized, in place)
    const float fq = (float)q;
    for (int kk0 = tid * 4; kk0 < LP; kk0 += 1024) {
        float4 a[8];
        #pragma unroll
        for (int h = 0; h < 8; h++) a[h] = *(const float4*)&sm[h][kk0];
        int4 msk = make_int4(1, 1, 1, 1);
        float4 dist = make_float4(0.f, 0.f, 0.f, 0.f);
        if (kk0 < TT) {
            msk = *(const int4*)(seq_mask + n * TT + kk0);
            dist.x = fabsf(fq - (float)(kk0 + 0));
            dist.y = fabsf(fq - (float)(kk0 + 1));
            dist.z = fabsf(fq - (float)(kk0 + 2));
            dist.w = fabsf(fq - (float)(kk0 + 3));
        }
        #pragma unroll
        for (int g = 0; g < 8; g++) {
            float4 o = make_float4(0.f, 0.f, 0.f, 0.f);
            #pragma unroll
            for (int h = 0; h < 8; h++) {
                float w = ps_pre[g * 8 + h];
                o.x += w * a[h].x; o.y += w * a[h].y;
                o.z += w * a[h].z; o.w += w * a[h].w;
            }
            float sg = spre[g];
            o.x = msk.x ? (o.x - dist.x * sg) * SOFTMAX_SCALE : -442.f;
            o.y = msk.y ? (o.y - dist.y * sg) * SOFTMAX_SCALE : -442.f;
            o.z = msk.z ? (o.z - dist.z * sg) * SOFTMAX_SCALE : -442.f;
            o.w = msk.w ? (o.w - dist.w * sg) * SOFTMAX_SCALE : -442.f;
            *(float4*)&sm[g][kk0] = o;
        }
    }
    __syncthreads();

    const int w = tid >> 5, lane = tid & 31;
    float mx = -1e30f;
    for (int kk = lane; kk < LP; kk += 32) mx = fmaxf(mx, sm[w][kk]);
    #pragma unroll
    for (int o = 16; o; o >>= 1) mx = fmaxf(mx, __shfl_xor_sync(0xffffffffu, mx, o));
    float s = 0.f;
    for (int kk = lane; kk < LP; kk += 32) {
        float p = __expf(sm[w][kk] - mx);
        sm[w][kk] = p;
        s += p;
    }
    #pragma unroll
    for (int o = 16; o; o >>= 1) s += __shfl_xor_sync(0xffffffffu, s, o);
    if (lane == 0) inv_s[w] = 1.f / s;
    __syncthreads();

    float inv[8];
    #pragma unroll
    for (int h = 0; h < 8; h++) inv[h] = inv_s[h];
    for (int kk0 = tid * 4; kk0 < LPAD; kk0 += 1024) {
        float4 a[8];
        if (kk0 < LP) {
            #pragma unroll
            for (int h = 0; h < 8; h++) {
                a[h] = *(const float4*)&sm[h][kk0];
                a[h].x *= inv[h]; a[h].y *= inv[h];
                a[h].z *= inv[h]; a[h].w *= inv[h];
            }
        } else {
            #pragma unroll
            for (int h = 0; h < 8; h++) a[h] = make_float4(0.f, 0.f, 0.f, 0.f);
        }
        #pragma unroll
        for (int g = 0; g < 8; g++) {
            float4 o = make_float4(0.f, 0.f, 0.f, 0.f);
            #pragma unroll
            for (int h = 0; h < 8; h++) {
                float wgt = ps_post[g * 8 + h];
                o.x += wgt * a[h].x; o.y += wgt * a[h].y;
                o.z += wgt * a[h].z; o.w += wgt * a[h].w;
            }
            __half2 h01 = __floats2half2_rn(o.x, o.y);
            __half2 h23 = __floats2half2_rn(o.z, o.w);
            __half2* dst = (__half2*)(g_a + ((size_t)((n * 8 + g) * TT + q)) * LPAD + kk0);
            dst[0] = h01;
            dst[1] = h23;
        }
    }
}

// ------------------------- attn @ V (fp16 HMMA) -----------------------------
#define V_A 0
#define V_B 16384
#define V_BUF 24576
#define AV_SMEM (2 * V_BUF)

__global__ void __launch_bounds__(256, 2) av_hmma_kernel() {
    extern __shared__ char smem[];
    const uint32_t sbase = smem_u32(smem);
    const int tid = threadIdx.x;
    const int lane = tid & 31, wid = tid >> 5;
    const int qt = blockIdx.x;          // 8
    const int ng = blockIdx.y;          // 64
    const int m0w = (wid & 3) * 32;
    const int n0w = (wid >> 2) * 32;

    float C[2][4][4];
    #pragma unroll
    for (int mt = 0; mt < 2; ++mt)
        #pragma unroll
        for (int nt = 0; nt < 4; ++nt)
            #pragma unroll
            for (int i = 0; i < 4; ++i) C[mt][nt][i] = 0.f;

    auto load_chunk = [&](int c, uint32_t bb) {
        #pragma unroll
        for (int it = 0; it < 4; ++it) {
            int s = it * 256 + tid;
            int r = s >> 3, cb = s & 7;
            size_t ga = ((size_t)ng * TT + qt * 128 + r) * LPAD + c * 64 + cb * 8;
            cpasync16(bb + V_A + SWZ((uint32_t)(r * 128 + cb * 16)), g_a + ga);
        }
        #pragma unroll
        for (int it = 0; it < 2; ++it) {
            int s = it * 256 + tid;
            int r = s >> 3, cb = s & 7;
            size_t gb = ((size_t)ng * 64 + r) * LPAD + c * 64 + cb * 8;
            cpasync16(bb + V_B + SWZ((uint32_t)(r * 128 + cb * 16)), g_vT + gb);
        }
        cp_commit();
    };

    load_chunk(0, sbase);

    for (int c = 0; c < 17; ++c) {
        const bool hn = (c + 1 < 17);
        if (hn) load_chunk(c + 1, sbase + ((c + 1) & 1) * V_BUF);
        if (hn) cp_wait1(); else cp_wait0();
        __syncthreads();

        const uint32_t Ab = sbase + (c & 1) * V_BUF;
        #pragma unroll
        for (int ks = 0; ks < 4; ++ks) {
            uint32_t a[2][4];
            #pragma unroll
            for (int mt = 0; mt < 2; ++mt) {
                uint32_t off = SWZ((uint32_t)((m0w + mt * 16 + (lane & 15)) * 128
                                              + ks * 32 + (lane >> 4) * 16));
                ldsm4(a[mt], Ab + V_A + off);
            }
            uint32_t b[8];
            #pragma unroll
            for (int p = 0; p < 2; ++p) {
                uint32_t off = SWZ((uint32_t)((n0w + p * 16 + (lane & 7) + ((lane >> 4) & 1) * 8) * 128
                                              + ks * 32 + ((lane >> 3) & 1) * 16));
                ldsm4(&b[p * 4], Ab + V_B + off);
            }
            #pragma unroll
            for (int mt = 0; mt < 2; ++mt)
                #pragma unroll
                for (int nt = 0; nt < 4; ++nt)
                    mma_f16(C[mt][nt], a[mt], &b[(nt >> 1) * 4 + (nt & 1) * 2]);
        }
        __syncthreads();
    }

    const int n = ng >> 3, h = ng & 7;
    #pragma unroll
    for (int mt = 0; mt < 2; ++mt) {
        int qb = qt * 128 + m0w + mt * 16 + (lane >> 2);
        #pragma unroll
        for (int nt = 0; nt < 4; ++nt) {
            int dcol = n0w + nt * 8 + (lane & 3) * 2;
            #pragma unroll
            for (int hf = 0; hf < 2; ++hf) {
                int q = qb + hf * 8;
                size_t o = ((size_t)(n * TT + q)) * 512 + h * 64 + dcol;
                *(float2*)(g_ctx + o) = make_float2(tf32r(C[mt][nt][hf * 2 + 0]),
                                                    tf32r(C[mt][nt][hf * 2 + 1]));
            }
        }
    }
}

// ------------------------------ LayerNorm ----------------------------------
__global__ void ln_kernel(const float* __restrict__ gamma,
                          const float* __restrict__ beta,
                          float* __restrict__ out) {
    const int r = blockIdx.x;
    const int tid = threadIdx.x;
    const float* in = g_t2 + (size_t)r * EE;
    __shared__ float red[8];

    float v0 = in[tid], v1 = in[tid + 256];
    float s = v0 + v1;
    #pragma unroll
    for (int o = 16; o; o >>= 1) s += __shfl_xor_sync(0xffffffffu, s, o);
    if ((tid & 31) == 0) red[tid >> 5] = s;
    __syncthreads();
    float tot = 0.f;
    #pragma unroll
    for (int i = 0; i < 8; i++) tot += red[i];
    float mu = tot * (1.f / EE);
    __syncthreads();

    float d0 = v0 - mu, d1 = v1 - mu;
    float vs = d0 * d0 + d1 * d1;
    #pragma unroll
    for (int o = 16; o; o >>= 1) vs += __shfl_xor_sync(0xffffffffu, vs, o);
    if ((tid & 31) == 0) red[tid >> 5] = vs;
    __syncthreads();
    float vtot = 0.f;
    #pragma unroll
    for (int i = 0; i < 8; i++) vtot += red[i];
    float inv = rsqrtf(vtot * (1.f / EE) + 1e-5f);

    out[(size_t)r * EE + tid]       = d0 * inv * gamma[tid]       + beta[tid];
    out[(size_t)r * EE + tid + 256] = d1 * inv * gamma[tid + 256] + beta[tid + 256];
}

// ------------------------------ launcher -----------------------------------
extern "C" void kernel_launch(void* const* d_in, const int* in_sizes, int n_in,
                              void* d_out, int out_size) {
    const float* x        = (const float*)d_in[0];
    const int*   seq_mask = (const int*)  d_in[1];
    const float* Wq       = (const float*)d_in[2];
    const float* Wk       = (const float*)d_in[3];
    const float* Wv       = (const float*)d_in[4];
    const float* Wo       = (const float*)d_in[5];
    const float* bo       = (const float*)d_in[6];
    const float* pre_th   = (const float*)d_in[7];
    const float* post_th  = (const float*)d_in[8];
    const float* pk       = (const float*)d_in[9];
    const float* pv       = (const float*)d_in[10];
    const float* c1W      = (const float*)d_in[11];
    const float* c1b      = (const float*)d_in[12];
    const float* c2W      = (const float*)d_in[13];
    const float* c2b      = (const float*)d_in[14];
    const float* ln_g     = (const float*)d_in[15];
    const float* ln_b     = (const float*)d_in[16];
    float* out = (float*)d_out;

    float *pWo, *pC1, *pC2, *pCtx, *pH, *pT1, *pT2;
    cudaGetSymbolAddress((void**)&pWo,  g_Wo);
    cudaGetSymbolAddress((void**)&pC1,  g_c1);
    cudaGetSymbolAddress((void**)&pC2,  g_c2);
    cudaGetSymbolAddress((void**)&pCtx, g_ctx);
    cudaGetSymbolAddress((void**)&pH,   g_h);
    cudaGetSymbolAddress((void**)&pT1,  g_t1);
    cudaGetSymbolAddress((void**)&pT2,  g_t2);

    cudaFuncSetAttribute(gemm_hmma_kernel,
                         cudaFuncAttributeMaxDynamicSharedMemorySize, GEMM_SMEM);
    cudaFuncSetAttribute(energy_hmma_kernel,
                         cudaFuncAttributeMaxDynamicSharedMemorySize, EGY_SMEM);
    cudaFuncSetAttribute(av_hmma_kernel,
                         cudaFuncAttributeMaxDynamicSharedMemorySize, AV_SMEM);
    cudaFuncSetAttribute(qkv_hmma_kernel,
                         cudaFuncAttributeMaxDynamicSharedMemorySize, QKV_SMEM);

    wo_convert<<<1024, 256>>>(Wo, pWo);
    conv_w_convert<<<3072, 256>>>(c1W, pC1);
    conv_w_convert<<<3072, 256>>>(c2W, pC2);

    qkv_hmma_kernel<<<dim3(64, 8), 256, QKV_SMEM>>>(x, Wq, Wk, Wv);
    persist_pad_kernel<<<2816, 256>>>(pk, pv);

    energy_hmma_kernel<<<dim3(8, 9, 64), 256, EGY_SMEM>>>();
    softmax_kernel<<<8192, 256>>>(pre_th, post_th, seq_mask);
    av_hmma_kernel<<<dim3(8, 64), 256, AV_SMEM>>>();

    gemm_hmma_kernel<<<dim3(64, 4), 256, GEMM_SMEM>>>(
        0, 16, pCtx, pWo, bo, x, seq_mask, pH);
    gemm_hmma_kernel<<<dim3(64, 4), 256, GEMM_SMEM>>>(
        1, 48, pH, pC1, c1b, nullptr, seq_mask, pT1);
    gemm_hmma_kernel<<<dim3(64, 4), 256, GEMM_SMEM>>>(
        2, 48, pT1, pC2, c2b, pH, seq_mask, pT2);

    ln_kernel<<<8192, 256>>>(ln_g, ln_b, out);
}

// round 11
// speedup vs baseline: 4.9990x; 1.2252x over previous
#include <cuda_runtime.h>
#include <cuda_bf16.h>
#include <cuda_fp16.h>
#include <math.h>
#include <stdint.h>

// ---------------------------------------------------------------------------
// TCNAttentionBlock. R11: ENTIRE pipeline on fp16 HMMA (fp16 eps == tf32 eps;
// all values in range). g_q/g_k/g_ctx/g_h/g_t1 stored fp16.
// N=8, T=1024, E=512, H=8, D=64, P=16.
// ---------------------------------------------------------------------------

#define NB   8
#define TT   1024
#define EE   512
#define HH   8
#define DD   64
#define PP   16
#define LP   1040            // TT + PP
#define LPAD 1088            // attn row padded (17 chunks of 64)
#define KPAD 1152            // K rows padded (9 tiles of 128)
#define SOFTMAX_SCALE 0.044194173824159216f   // 1/sqrt(512)

// ------------------------------ scratch -----------------------------------
__device__ __half g_q  [64 * TT * DD];                     // fp16 [ng][q][64]
__device__ __half g_k  [64 * KPAD * DD];                   // fp16 [ng][l][64]
__device__ __half g_vT [64 * DD * LPAD];                   // fp16 [ng][d][1088]
__device__ __half g_att[(size_t)64 * TT * LP];             // fp16 raw QK^T
__device__ __half g_a  [(size_t)64 * TT * LPAD];           // fp16 attn
__device__ __half g_ctx[NB * TT * EE];                     // fp16
__device__ __half g_h  [NB * TT * EE];                     // fp16 (x + att)
__device__ __half g_t1 [NB * TT * EE];                     // fp16
__device__ float  g_t2 [NB * TT * EE];                     // fp32

// preconverted fp16 weights, layout [chunk][co(512)][64]
__device__ __half g_Wo[8  * 512 * 64];
__device__ __half g_c1[24 * 512 * 64];
__device__ __half g_c2[24 * 512 * 64];

// ---------------------------- PTX helpers ----------------------------------
__device__ __forceinline__ uint32_t smem_u32(const void* p) {
    uint32_t a;
    asm("{ .reg .u64 t; cvta.to.shared.u64 t, %1; cvt.u32.u64 %0, t; }"
        : "=r"(a) : "l"(p));
    return a;
}
#define SWZ(o) ((o) ^ (((o) >> 3) & 0x70))

__device__ __forceinline__ void ldsm4(uint32_t* r, uint32_t addr) {
    asm volatile("ldmatrix.sync.aligned.m8n8.x4.shared.b16 {%0,%1,%2,%3}, [%4];"
                 : "=r"(r[0]), "=r"(r[1]), "=r"(r[2]), "=r"(r[3]) : "r"(addr));
}
__device__ __forceinline__ void mma_f16(float* c, const uint32_t* a, const uint32_t* b) {
    asm volatile(
        "mma.sync.aligned.m16n8k16.row.col.f32.f16.f16.f32 "
        "{%0,%1,%2,%3}, {%4,%5,%6,%7}, {%8,%9}, {%0,%1,%2,%3};"
        : "+f"(c[0]), "+f"(c[1]), "+f"(c[2]), "+f"(c[3])
        : "r"(a[0]), "r"(a[1]), "r"(a[2]), "r"(a[3]), "r"(b[0]), "r"(b[1]));
}
__device__ __forceinline__ void cpasync16(uint32_t saddr, const void* g) {
    asm volatile("cp.async.cg.shared.global [%0], [%1], 16;" :: "r"(saddr), "l"(g));
}
__device__ __forceinline__ void cpasync16z(uint32_t saddr, const void* g, int sz) {
    asm volatile("cp.async.cg.shared.global [%0], [%1], 16, %2;"
                 :: "r"(saddr), "l"(g), "r"(sz));
}
__device__ __forceinline__ void cp_commit() {
    asm volatile("cp.async.commit_group;" ::: "memory");
}
__device__ __forceinline__ void cp_wait0() {
    asm volatile("cp.async.wait_group 0;" ::: "memory");
}
__device__ __forceinline__ void cp_wait1() {
    asm volatile("cp.async.wait_group 1;" ::: "memory");
}
__device__ __forceinline__ uint32_t tf32r_u(float v) {   // kept for A staging in qkv
    uint32_t u;
    asm("cvt.rna.tf32.f32 %0, %1;" : "=r"(u) : "f"(v));
    return u;
}
__device__ __forceinline__ void mma_tf32(float* c, const uint32_t* a, const uint32_t* b) {
    asm volatile(
        "mma.sync.aligned.m16n8k8.row.col.f32.tf32.tf32.f32 "
        "{%0,%1,%2,%3}, {%4,%5,%6,%7}, {%8,%9}, {%0,%1,%2,%3};"
        : "+f"(c[0]), "+f"(c[1]), "+f"(c[2]), "+f"(c[3])
        : "r"(a[0]), "r"(a[1]), "r"(a[2]), "r"(a[3]), "r"(b[0]), "r"(b[1]));
}

// ---------------------- weight preconversion (fp16) -------------------------
__global__ void conv_w_convert(const float* __restrict__ W, __half* __restrict__ o) {
    int d = blockIdx.x * 256 + threadIdx.x;          // 24*512*64 = 786432
    int c  = d >> 15;
    int co = (d >> 6) & 511;
    int ci = d & 63;
    int tap = c >> 3, cib = (c & 7) << 6;
    o[d] = __float2half(W[(size_t)(co * 512 + cib + ci) * 3 + tap]);
}
__global__ void wo_convert(const float* __restrict__ W, __half* __restrict__ o) {
    int d = blockIdx.x * 256 + threadIdx.x;          // 8*512*64 = 262144
    int c  = d >> 15;
    int co = (d >> 6) & 511;
    int ci = d & 63;
    o[d] = __float2half(W[co * 512 + (c << 6) + ci]);
}

// ------------------------ QKV on tf32 HMMA ----------------------------------
// (x, W are fp32 inputs; staging cost trivial.) writes q/k fp16, vT fp16.
#define QKV_B0 32768
#define QKV_SMEM (32768 + 3 * 16384)
__global__ void __launch_bounds__(256) qkv_hmma_kernel(
    const float* __restrict__ x,
    const float* __restrict__ Wq,
    const float* __restrict__ Wk,
    const float* __restrict__ Wv)
{
    extern __shared__ char smem[];
    const uint32_t sbase = smem_u32(smem);
    const int tid = threadIdx.x;
    const int lane = tid & 31, wid = tid >> 5;
    const int t0 = blockIdx.x * 128;
    const int h  = blockIdx.y;
    const int n  = t0 >> 10;
    const int ng = n * 8 + h;
    const int m0w = (wid & 3) * 32;
    const int n0w = (wid >> 2) * 32;

    #pragma unroll
    for (int it = 0; it < 8; ++it) {
        int lin = it * 1024 + tid * 4;
        int r = lin >> 6, ci = lin & 63;
        float4 v = *(const float4*)(x + (size_t)(t0 + r) * 512 + h * 64 + ci);
        uint32_t off = (ci >> 5) * 16384 + SWZ((uint32_t)(r * 128 + (ci & 31) * 4));
        *(uint4*)(smem + off) = make_uint4(tf32r_u(v.x), tf32r_u(v.y),
                                           tf32r_u(v.z), tf32r_u(v.w));
    }
    #pragma unroll
    for (int m = 0; m < 3; ++m) {
        const float* Wm = (m == 0) ? Wq : (m == 1) ? Wk : Wv;
        #pragma unroll
        for (int it = 0; it < 4; ++it) {
            int lin = it * 1024 + tid * 4;
            int r = lin >> 6, ci = lin & 63;
            float4 v = *(const float4*)(Wm + r * 64 + ci);
            uint32_t off = QKV_B0 + m * 16384 + (ci >> 5) * 8192
                         + SWZ((uint32_t)(r * 128 + (ci & 31) * 4));
            *(uint4*)(smem + off) = make_uint4(tf32r_u(v.x), tf32r_u(v.y),
                                               tf32r_u(v.z), tf32r_u(v.w));
        }
    }
    __syncthreads();

    for (int m = 0; m < 3; ++m) {
        float C[2][4][4];
        #pragma unroll
        for (int mt = 0; mt < 2; ++mt)
            #pragma unroll
            for (int nt = 0; nt < 4; ++nt)
                #pragma unroll
                for (int i = 0; i < 4; ++i) C[mt][nt][i] = 0.f;

        const uint32_t bbase = sbase + QKV_B0 + m * 16384;
        #pragma unroll
        for (int panel = 0; panel < 2; ++panel) {
            #pragma unroll
            for (int ks = 0; ks < 4; ++ks) {
                uint32_t a[2][4];
                #pragma unroll
                for (int mt = 0; mt < 2; ++mt) {
                    uint32_t off = panel * 16384
                        + SWZ((uint32_t)((m0w + mt * 16 + (lane & 15)) * 128
                                         + ks * 32 + (lane >> 4) * 16));
                    ldsm4(a[mt], sbase + off);
                }
                uint32_t b[8];
                #pragma unroll
                for (int p = 0; p < 2; ++p) {
                    uint32_t off = panel * 8192
                        + SWZ((uint32_t)((n0w + p * 16 + (lane & 7) + ((lane >> 4) & 1) * 8) * 128
                                         + ks * 32 + ((lane >> 3) & 1) * 16));
                    ldsm4(&b[p * 4], bbase + off);
                }
                #pragma unroll
                for (int mt = 0; mt < 2; ++mt)
                    #pragma unroll
                    for (int nt = 0; nt < 4; ++nt)
                        mma_tf32(C[mt][nt], a[mt], &b[(nt >> 1) * 4 + (nt & 1) * 2]);
            }
        }

        #pragma unroll
        for (int mt = 0; mt < 2; ++mt) {
            int tb = t0 + m0w + mt * 16 + (lane >> 2);
            #pragma unroll
            for (int nt = 0; nt < 4; ++nt) {
                int col = n0w + nt * 8 + (lane & 3) * 2;
                #pragma unroll
                for (int hf = 0; hf < 2; ++hf) {
                    int ts = (tb + hf * 8) & 1023;
                    float y0 = C[mt][nt][hf * 2 + 0];
                    float y1 = C[mt][nt][hf * 2 + 1];
                    if (m == 0) {
                        size_t o = ((size_t)ng * TT + ts) * 64 + col;
                        *(__half2*)(g_q + o) = __floats2half2_rn(y0, y1);
                    } else if (m == 1) {
                        size_t o = ((size_t)ng * KPAD + ts) * 64 + col;
                        *(__half2*)(g_k + o) = __floats2half2_rn(y0, y1);
                    } else {
                        g_vT[((size_t)ng * 64 + col)     * LPAD + ts] = __float2half(y0);
                        g_vT[((size_t)ng * 64 + col + 1) * LPAD + ts] = __float2half(y1);
                    }
                }
            }
        }
    }
}

// ---------------------- fp16 HMMA GEMM (outproj / conv) ---------------------
// A (fp16 in memory) and B (fp16 weights) both cp.async. K-chunk = 64.
// mode 0: outproj (8 chunks):  OUT(h fp16) = acc + bias + resid_f32(x)
// mode 1: conv1   (24 chunks): OUT(t1 fp16) = relu((acc+bias)*valid)
// mode 2: conv2   (24 chunks): OUT(t2 fp32) = relu(relu((acc+bias)*valid)+resid_h16)
#define G_A 0
#define G_B 16384
#define G_BUF 32768
#define GEMM_SMEM (2 * G_BUF)

__global__ void __launch_bounds__(256, 2) gemm_hmma_kernel(
    int mode, int nchunk,
    const __half* __restrict__ IN,
    const __half* __restrict__ Bg,
    const float* __restrict__ bias,
    const float* __restrict__ residf,
    const __half* __restrict__ residh,
    const int* __restrict__ seq_mask,
    void* __restrict__ OUTv)
{
    extern __shared__ char smem[];
    const uint32_t sbase = smem_u32(smem);
    const int tid = threadIdx.x;
    const int lane = tid & 31, wid = tid >> 5;
    const int t0 = blockIdx.x * 128;
    const int co0 = blockIdx.y * 128;
    const int nBseq = t0 & ~1023;
    const int m0w = (wid & 1) * 64;
    const int n0w = (wid >> 1) * 32;

    float C[4][4][4];
    #pragma unroll
    for (int mt = 0; mt < 4; ++mt)
        #pragma unroll
        for (int nt = 0; nt < 4; ++nt)
            #pragma unroll
            for (int i = 0; i < 4; ++i) C[mt][nt][i] = 0.f;

    auto load_chunk = [&](int c, uint32_t bb) {
        int shift, cib;
        if (mode == 0) { shift = 0; cib = c << 6; }
        else           { shift = (c >> 3) - 2; cib = (c & 7) << 6; }
        #pragma unroll
        for (int it = 0; it < 4; ++it) {
            int s = it * 256 + tid;
            int r = s >> 3, cb = s & 7;
            int grow = t0 + r + shift;
            int ok = (grow >= nBseq);
            int ga = ok ? grow : nBseq;
            cpasync16z(bb + G_A + SWZ((uint32_t)(r * 128 + cb * 16)),
                       IN + (size_t)ga * 512 + cib + cb * 8, ok ? 16 : 0);
        }
        #pragma unroll
        for (int it = 0; it < 4; ++it) {
            int s = it * 256 + tid;
            int r = s >> 3, cb = s & 7;
            size_t gb = ((size_t)(c * 512 + co0 + r) << 6) + cb * 8;
            cpasync16(bb + G_B + SWZ((uint32_t)(r * 128 + cb * 16)), Bg + gb);
        }
        cp_commit();
    };

    load_chunk(0, sbase);

    for (int c = 0; c < nchunk; ++c) {
        const bool hn = (c + 1 < nchunk);
        if (hn) load_chunk(c + 1, sbase + ((c + 1) & 1) * G_BUF);
        if (hn) cp_wait1(); else cp_wait0();
        __syncthreads();

        const uint32_t Ab = sbase + (c & 1) * G_BUF;
        #pragma unroll
        for (int ks = 0; ks < 4; ++ks) {
            uint32_t a[4][4];
            #pragma unroll
            for (int mt = 0; mt < 4; ++mt) {
                uint32_t off = SWZ((uint32_t)((m0w + mt * 16 + (lane & 15)) * 128
                                              + ks * 32 + (lane >> 4) * 16));
                ldsm4(a[mt], Ab + G_A + off);
            }
            uint32_t b[8];
            #pragma unroll
            for (int p = 0; p < 2; ++p) {
                uint32_t off = SWZ((uint32_t)((n0w + p * 16 + (lane & 7) + ((lane >> 4) & 1) * 8) * 128
                                              + ks * 32 + ((lane >> 3) & 1) * 16));
                ldsm4(&b[p * 4], Ab + G_B + off);
            }
            #pragma unroll
            for (int mt = 0; mt < 4; ++mt)
                #pragma unroll
                for (int nt = 0; nt < 4; ++nt)
                    mma_f16(C[mt][nt], a[mt], &b[(nt >> 1) * 4 + (nt & 1) * 2]);
        }
        __syncthreads();
    }

    #pragma unroll
    for (int mt = 0; mt < 4; ++mt) {
        int rb = t0 + m0w + mt * 16 + (lane >> 2);
        #pragma unroll
        for (int nt = 0; nt < 4; ++nt) {
            int col = co0 + n0w + nt * 8 + (lane & 3) * 2;
            float b0 = bias[col], b1 = bias[col + 1];
            #pragma unroll
            for (int hf = 0; hf < 2; ++hf) {
                int r = rb + hf * 8;
                float y0 = C[mt][nt][hf * 2 + 0] + b0;
                float y1 = C[mt][nt][hf * 2 + 1] + b1;
                if (mode == 0) {
                    const float2 rs = *(const float2*)(residf + (size_t)r * 512 + col);
                    *(__half2*)((__half*)OUTv + (size_t)r * 512 + col) =
                        __floats2half2_rn(y0 + rs.x, y1 + rs.y);
                } else {
                    float valid = (float)seq_mask[r];
                    y0 = fmaxf(y0 * valid, 0.f);
                    y1 = fmaxf(y1 * valid, 0.f);
                    if (mode == 2) {
                        float2 rs = __half22float2(
                            *(const __half2*)(residh + (size_t)r * 512 + col));
                        y0 = fmaxf(y0 + rs.x, 0.f);
                        y1 = fmaxf(y1 + rs.y, 0.f);
                        *(float2*)((float*)OUTv + (size_t)r * 512 + col) =
                            make_float2(y0, y1);
                    } else {
                        *(__half2*)((__half*)OUTv + (size_t)r * 512 + col) =
                            __floats2half2_rn(y0, y1);
                    }
                }
            }
        }
    }
}

// ------- persistent kv slots (k + vT) + k padding + vT padding -------------
__global__ void persist_pad_kernel(const float* __restrict__ pk,
                                   const float* __restrict__ pv) {
    int idx = blockIdx.x * 256 + threadIdx.x;
    if (idx < NB * PP * HH * DD) {                      // 65536
        int d = idx & 63, h = (idx >> 6) & 7, p = (idx >> 9) & 15, n = idx >> 13;
        int src = ((p * HH + h) << 6) + d;
        int ng = n * 8 + h;
        g_vT[((size_t)ng * 64 + d) * LPAD + TT + p] = __float2half(pv[src]);
        g_k[((size_t)ng * KPAD + TT + p) * 64 + d] = __float2half(pk[src]);
        return;
    }
    int j = idx - NB * PP * HH * DD;
    if (j < 64 * 112 * 64) {                            // k pad rows [LP,KPAD)
        int d = j & 63;
        int l = LP + ((j >> 6) % 112);
        int ng = j / (112 * 64);
        g_k[((size_t)ng * KPAD + l) * 64 + d] = __float2half(0.f);
        return;
    }
    j -= 64 * 112 * 64;
    if (j < 64 * 64 * 48) {                             // vT pad cols [LP,LPAD)
        int c = j % 48;
        int d = (j / 48) & 63;
        int ng = j / (48 * 64);
        g_vT[((size_t)ng * 64 + d) * LPAD + LP + c] = __float2half(0.f);
    }
}

// -------------------- energy: raw Q@K^T -> fp16 (fp16 HMMA) ----------------
#define E_A0 0
#define E_B0 16384
#define EGY_SMEM 32768
__global__ void __launch_bounds__(256) energy_hmma_kernel() {
    extern __shared__ char smem[];
    const uint32_t sbase = smem_u32(smem);
    const int tid = threadIdx.x;
    const int lane = tid & 31, wid = tid >> 5;
    const int qt = blockIdx.x;          // 8
    const int kt = blockIdx.y;          // 9
    const int ng = blockIdx.z;          // 64
    const int m0w = (wid & 1) * 64;
    const int n0w = (wid >> 1) * 32;

    // A = Q[128][64] fp16, B = K[128][64] fp16 (one 128B row each)
    #pragma unroll
    for (int it = 0; it < 4; ++it) {
        int s = it * 256 + tid;
        int r = s >> 3, cb = s & 7;
        uint32_t off = SWZ((uint32_t)(r * 128 + cb * 16));
        size_t qa = ((size_t)ng * TT + qt * 128 + r) * 64 + cb * 8;
        size_t ka = ((size_t)ng * KPAD + kt * 128 + r) * 64 + cb * 8;
        cpasync16(sbase + E_A0 + off, g_q + qa);
        cpasync16(sbase + E_B0 + off, g_k + ka);
    }
    cp_commit();

    float C[4][4][4];
    #pragma unroll
    for (int mt = 0; mt < 4; ++mt)
        #pragma unroll
        for (int nt = 0; nt < 4; ++nt)
            #pragma unroll
            for (int i = 0; i < 4; ++i) C[mt][nt][i] = 0.f;

    cp_wait0();
    __syncthreads();

    #pragma unroll
    for (int ks = 0; ks < 4; ++ks) {
        uint32_t a[4][4];
        #pragma unroll
        for (int mt = 0; mt < 4; ++mt) {
            uint32_t off = SWZ((uint32_t)((m0w + mt * 16 + (lane & 15)) * 128
                                          + ks * 32 + (lane >> 4) * 16));
            ldsm4(a[mt], sbase + E_A0 + off);
        }
        uint32_t b[8];
        #pragma unroll
        for (int p = 0; p < 2; ++p) {
            uint32_t off = SWZ((uint32_t)((n0w + p * 16 + (lane & 7) + ((lane >> 4) & 1) * 8) * 128
                                          + ks * 32 + ((lane >> 3) & 1) * 16));
            ldsm4(&b[p * 4], sbase + E_B0 + off);
        }
        #pragma unroll
        for (int mt = 0; mt < 4; ++mt)
            #pragma unroll
            for (int nt = 0; nt < 4; ++nt)
                mma_f16(C[mt][nt], a[mt], &b[(nt >> 1) * 4 + (nt & 1) * 2]);
    }

    #pragma unroll
    for (int mt = 0; mt < 4; ++mt) {
        int qb = qt * 128 + m0w + mt * 16 + (lane >> 2);
        #pragma unroll
        for (int nt = 0; nt < 4; ++nt) {
            int k0 = kt * 128 + n0w + nt * 8 + (lane & 3) * 2;
            if (k0 >= LP) continue;
            #pragma unroll
            for (int hf = 0; hf < 2; ++hf) {
                int q = qb + hf * 8;
                __half2 e = __floats2half2_rn(C[mt][nt][hf * 2 + 0],
                                              C[mt][nt][hf * 2 + 1]);
                *(__half2*)(g_att + ((size_t)(ng * TT + q)) * LP + k0) = e;
            }
        }
    }
}

// ------- pre-mix(+recomputed ALiBi) -> mask -> softmax -> post-mix ---------
__global__ void __launch_bounds__(256, 4) softmax_kernel(
                               const float* __restrict__ pre,
                               const float* __restrict__ post,
                               const int* __restrict__ seq_mask) {
    __shared__ float sm[8][LP];
    __shared__ float ps_pre[64];
    __shared__ float ps_post[64];
    __shared__ float inv_s[8];
    const int nq = blockIdx.x;
    const int n = nq >> 10, q = nq & 1023;
    const int tid = threadIdx.x;

    if (tid < 64) { ps_pre[tid] = pre[tid]; ps_post[tid] = post[tid]; }

    for (int i8 = tid; i8 < 8 * (LP / 8); i8 += 256) {
        int h = i8 / (LP / 8), kk8 = (i8 - h * (LP / 8)) * 8;
        const __half2* src = (const __half2*)(g_att + ((size_t)((n * 8 + h) * TT + q)) * LP + kk8);
        #pragma unroll
        for (int u = 0; u < 4; ++u) {
            float2 f = __half22float2(src[u]);
            sm[h][kk8 + u * 2 + 0] = f.x;
            sm[h][kk8 + u * 2 + 1] = f.y;
        }
    }
    __syncthreads();

    float spre[8];
    #pragma unroll
    for (int g = 0; g < 8; g++) {
        float s = 0.f;
        #pragma unroll
        for (int h = 0; h < 8; h++) s += ps_pre[g * 8 + h] * exp2f(-(float)(h + 1));
        spre[g] = s;
    }

    const float fq = (float)q;
    for (int kk0 = tid * 4; kk0 < LP; kk0 += 1024) {
        float4 a[8];
        #pragma unroll
        for (int h = 0; h < 8; h++) a[h] = *(const float4*)&sm[h][kk0];
        int4 msk = make_int4(1, 1, 1, 1);
        float4 dist = make_float4(0.f, 0.f, 0.f, 0.f);
        if (kk0 < TT) {
            msk = *(const int4*)(seq_mask + n * TT + kk0);
            dist.x = fabsf(fq - (float)(kk0 + 0));
            dist.y = fabsf(fq - (float)(kk0 + 1));
            dist.z = fabsf(fq - (float)(kk0 + 2));
            dist.w = fabsf(fq - (float)(kk0 + 3));
        }
        #pragma unroll
        for (int g = 0; g < 8; g++) {
            float4 o = make_float4(0.f, 0.f, 0.f, 0.f);
            #pragma unroll
            for (int h = 0; h < 8; h++) {
                float w = ps_pre[g * 8 + h];
                o.x += w * a[h].x; o.y += w * a[h].y;
                o.z += w * a[h].z; o.w += w * a[h].w;
            }
            float sg = spre[g];
            o.x = msk.x ? (o.x - dist.x * sg) * SOFTMAX_SCALE : -442.f;
            o.y = msk.y ? (o.y - dist.y * sg) * SOFTMAX_SCALE : -442.f;
            o.z = msk.z ? (o.z - dist.z * sg) * SOFTMAX_SCALE : -442.f;
            o.w = msk.w ? (o.w - dist.w * sg) * SOFTMAX_SCALE : -442.f;
            *(float4*)&sm[g][kk0] = o;
        }
    }
    __syncthreads();

    const int w = tid >> 5, lane = tid & 31;
    float mx = -1e30f;
    for (int kk = lane; kk < LP; kk += 32) mx = fmaxf(mx, sm[w][kk]);
    #pragma unroll
    for (int o = 16; o; o >>= 1) mx = fmaxf(mx, __shfl_xor_sync(0xffffffffu, mx, o));
    float s = 0.f;
    for (int kk = lane; kk < LP; kk += 32) {
        float p = __expf(sm[w][kk] - mx);
        sm[w][kk] = p;
        s += p;
    }
    #pragma unroll
    for (int o = 16; o; o >>= 1) s += __shfl_xor_sync(0xffffffffu, s, o);
    if (lane == 0) inv_s[w] = 1.f / s;
    __syncthreads();

    float inv[8];
    #pragma unroll
    for (int h = 0; h < 8; h++) inv[h] = inv_s[h];
    for (int kk0 = tid * 4; kk0 < LPAD; kk0 += 1024) {
        float4 a[8];
        if (kk0 < LP) {
            #pragma unroll
            for (int h = 0; h < 8; h++) {
                a[h] = *(const float4*)&sm[h][kk0];
                a[h].x *= inv[h]; a[h].y *= inv[h];
                a[h].z *= inv[h]; a[h].w *= inv[h];
            }
        } else {
            #pragma unroll
            for (int h = 0; h < 8; h++) a[h] = make_float4(0.f, 0.f, 0.f, 0.f);
        }
        #pragma unroll
        for (int g = 0; g < 8; g++) {
            float4 o = make_float4(0.f, 0.f, 0.f, 0.f);
            #pragma unroll
            for (int h = 0; h < 8; h++) {
                float wgt = ps_post[g * 8 + h];
                o.x += wgt * a[h].x; o.y += wgt * a[h].y;
                o.z += wgt * a[h].z; o.w += wgt * a[h].w;
            }
            __half2 h01 = __floats2half2_rn(o.x, o.y);
            __half2 h23 = __floats2half2_rn(o.z, o.w);
            __half2* dst = (__half2*)(g_a + ((size_t)((n * 8 + g) * TT + q)) * LPAD + kk0);
            dst[0] = h01;
            dst[1] = h23;
        }
    }
}

// ------------------------- attn @ V (fp16 HMMA) -----------------------------
#define V_A 0
#define V_B 16384
#define V_BUF 24576
#define AV_SMEM (2 * V_BUF)

__global__ void __launch_bounds__(256, 2) av_hmma_kernel() {
    extern __shared__ char smem[];
    const uint32_t sbase = smem_u32(smem);
    const int tid = threadIdx.x;
    const int lane = tid & 31, wid = tid >> 5;
    const int qt = blockIdx.x;          // 8
    const int ng = blockIdx.y;          // 64
    const int m0w = (wid & 3) * 32;
    const int n0w = (wid >> 2) * 32;

    float C[2][4][4];
    #pragma unroll
    for (int mt = 0; mt < 2; ++mt)
        #pragma unroll
        for (int nt = 0; nt < 4; ++nt)
            #pragma unroll
            for (int i = 0; i < 4; ++i) C[mt][nt][i] = 0.f;

    auto load_chunk = [&](int c, uint32_t bb) {
        #pragma unroll
        for (int it = 0; it < 4; ++it) {
            int s = it * 256 + tid;
            int r = s >> 3, cb = s & 7;
            size_t ga = ((size_t)ng * TT + qt * 128 + r) * LPAD + c * 64 + cb * 8;
            cpasync16(bb + V_A + SWZ((uint32_t)(r * 128 + cb * 16)), g_a + ga);
        }
        #pragma unroll
        for (int it = 0; it < 2; ++it) {
            int s = it * 256 + tid;
            int r = s >> 3, cb = s & 7;
            size_t gb = ((size_t)ng * 64 + r) * LPAD + c * 64 + cb * 8;
            cpasync16(bb + V_B + SWZ((uint32_t)(r * 128 + cb * 16)), g_vT + gb);
        }
        cp_commit();
    };

    load_chunk(0, sbase);

    for (int c = 0; c < 17; ++c) {
        const bool hn = (c + 1 < 17);
        if (hn) load_chunk(c + 1, sbase + ((c + 1) & 1) * V_BUF);
        if (hn) cp_wait1(); else cp_wait0();
        __syncthreads();

        const uint32_t Ab = sbase + (c & 1) * V_BUF;
        #pragma unroll
        for (int ks = 0; ks < 4; ++ks) {
            uint32_t a[2][4];
            #pragma unroll
            for (int mt = 0; mt < 2; ++mt) {
                uint32_t off = SWZ((uint32_t)((m0w + mt * 16 + (lane & 15)) * 128
                                              + ks * 32 + (lane >> 4) * 16));
                ldsm4(a[mt], Ab + V_A + off);
            }
            uint32_t b[8];
            #pragma unroll
            for (int p = 0; p < 2; ++p) {
                uint32_t off = SWZ((uint32_t)((n0w + p * 16 + (lane & 7) + ((lane >> 4) & 1) * 8) * 128
                                              + ks * 32 + ((lane >> 3) & 1) * 16));
                ldsm4(&b[p * 4], Ab + V_B + off);
            }
            #pragma unroll
            for (int mt = 0; mt < 2; ++mt)
                #pragma unroll
                for (int nt = 0; nt < 4; ++nt)
                    mma_f16(C[mt][nt], a[mt], &b[(nt >> 1) * 4 + (nt & 1) * 2]);
        }
        __syncthreads();
    }

    const int n = ng >> 3, h = ng & 7;
    #pragma unroll
    for (int mt = 0; mt < 2; ++mt) {
        int qb = qt * 128 + m0w + mt * 16 + (lane >> 2);
        #pragma unroll
        for (int nt = 0; nt < 4; ++nt) {
            int dcol = n0w + nt * 8 + (lane & 3) * 2;
            #pragma unroll
            for (int hf = 0; hf < 2; ++hf) {
                int q = qb + hf * 8;
                size_t o = ((size_t)(n * TT + q)) * 512 + h * 64 + dcol;
                *(__half2*)(g_ctx + o) =
                    __floats2half2_rn(C[mt][nt][hf * 2 + 0], C[mt][nt][hf * 2 + 1]);
            }
        }
    }
}

// ------------------------------ LayerNorm ----------------------------------
__global__ void ln_kernel(const float* __restrict__ gamma,
                          const float* __restrict__ beta,
                          float* __restrict__ out) {
    const int r = blockIdx.x;
    const int tid = threadIdx.x;
    const float* in = g_t2 + (size_t)r * EE;
    __shared__ float red[8];

    float v0 = in[tid], v1 = in[tid + 256];
    float s = v0 + v1;
    #pragma unroll
    for (int o = 16; o; o >>= 1) s += __shfl_xor_sync(0xffffffffu, s, o);
    if ((tid & 31) == 0) red[tid >> 5] = s;
    __syncthreads();
    float tot = 0.f;
    #pragma unroll
    for (int i = 0; i < 8; i++) tot += red[i];
    float mu = tot * (1.f / EE);
    __syncthreads();

    float d0 = v0 - mu, d1 = v1 - mu;
    float vs = d0 * d0 + d1 * d1;
    #pragma unroll
    for (int o = 16; o; o >>= 1) vs += __shfl_xor_sync(0xffffffffu, vs, o);
    if ((tid & 31) == 0) red[tid >> 5] = vs;
    __syncthreads();
    float vtot = 0.f;
    #pragma unroll
    for (int i = 0; i < 8; i++) vtot += red[i];
    float inv = rsqrtf(vtot * (1.f / EE) + 1e-5f);

    out[(size_t)r * EE + tid]       = d0 * inv * gamma[tid]       + beta[tid];
    out[(size_t)r * EE + tid + 256] = d1 * inv * gamma[tid + 256] + beta[tid + 256];
}

// ------------------------------ launcher -----------------------------------
extern "C" void kernel_launch(void* const* d_in, const int* in_sizes, int n_in,
                              void* d_out, int out_size) {
    const float* x        = (const float*)d_in[0];
    const int*   seq_mask = (const int*)  d_in[1];
    const float* Wq       = (const float*)d_in[2];
    const float* Wk       = (const float*)d_in[3];
    const float* Wv       = (const float*)d_in[4];
    const float* Wo       = (const float*)d_in[5];
    const float* bo       = (const float*)d_in[6];
    const float* pre_th   = (const float*)d_in[7];
    const float* post_th  = (const float*)d_in[8];
    const float* pk       = (const float*)d_in[9];
    const float* pv       = (const float*)d_in[10];
    const float* c1W      = (const float*)d_in[11];
    const float* c1b      = (const float*)d_in[12];
    const float* c2W      = (const float*)d_in[13];
    const float* c2b      = (const float*)d_in[14];
    const float* ln_g     = (const float*)d_in[15];
    const float* ln_b     = (const float*)d_in[16];
    float* out = (float*)d_out;

    __half *pWo, *pC1, *pC2, *pCtx, *pH, *pT1;
    float *pT2;
    cudaGetSymbolAddress((void**)&pWo,  g_Wo);
    cudaGetSymbolAddress((void**)&pC1,  g_c1);
    cudaGetSymbolAddress((void**)&pC2,  g_c2);
    cudaGetSymbolAddress((void**)&pCtx, g_ctx);
    cudaGetSymbolAddress((void**)&pH,   g_h);
    cudaGetSymbolAddress((void**)&pT1,  g_t1);
    cudaGetSymbolAddress((void**)&pT2,  g_t2);

    cudaFuncSetAttribute(gemm_hmma_kernel,
                         cudaFuncAttributeMaxDynamicSharedMemorySize, GEMM_SMEM);
    cudaFuncSetAttribute(energy_hmma_kernel,
                         cudaFuncAttributeMaxDynamicSharedMemorySize, EGY_SMEM);
    cudaFuncSetAttribute(av_hmma_kernel,
                         cudaFuncAttributeMaxDynamicSharedMemorySize, AV_SMEM);
    cudaFuncSetAttribute(qkv_hmma_kernel,
                         cudaFuncAttributeMaxDynamicSharedMemorySize, QKV_SMEM);

    wo_convert<<<1024, 256>>>(Wo, pWo);
    conv_w_convert<<<3072, 256>>>(c1W, pC1);
    conv_w_convert<<<3072, 256>>>(c2W, pC2);

    qkv_hmma_kernel<<<dim3(64, 8), 256, QKV_SMEM>>>(x, Wq, Wk, Wv);
    persist_pad_kernel<<<2816, 256>>>(pk, pv);

    energy_hmma_kernel<<<dim3(8, 9, 64), 256, EGY_SMEM>>>();
    softmax_kernel<<<8192, 256>>>(pre_th, post_th, seq_mask);
    av_hmma_kernel<<<dim3(8, 64), 256, AV_SMEM>>>();

    // outproj: g_h(fp16) = ctx @ Wo^T + bo + x
    gemm_hmma_kernel<<<dim3(64, 4), 256, GEMM_SMEM>>>(
        0, 8, pCtx, pWo, bo, x, nullptr, seq_mask, pH);
    // conv1: g_t1(fp16) = relu((conv(g_h)+b1)*valid)
    gemm_hmma_kernel<<<dim3(64, 4), 256, GEMM_SMEM>>>(
        1, 24, pH, pC1, c1b, nullptr, nullptr, seq_mask, pT1);
    // conv2: g_t2(fp32) = relu(relu((conv(g_t1)+b2)*valid) + g_h)
    gemm_hmma_kernel<<<dim3(64, 4), 256, GEMM_SMEM>>>(
        2, 24, pT1, pC2, c2b, nullptr, pH, seq_mask, pT2);

    ln_kernel<<<8192, 256>>>(ln_g, ln_b, out);
}